// round 9
// baseline (speedup 1.0000x reference)
#include <cuda_runtime.h>

// Problem constants
#define BB 32
#define TT 24
#define NN 325
#define DD 64
#define NHEAD 8
#define DHEAD 8

#define NB 4                  // nodes per CTA
#define MROWS (NB * TT)       // 96 rows
#define NTILES ((NN + NB - 1) / NB)   // 82
#define NTHREADS 384

// smem float offsets (114688 B -> 2 CTAs/SM)
#define XB_OFF 0                      // 96*64 (X -> attention O)
#define QB_OFF 6144                   // Q -> FC1 hidden H
#define KB_OFF 12288
#define VB_OFF 18432
#define WP_OFF 24576                  // split-pair weight slot (4096 floats)
#define SMEM_FLOATS 28672
#define SMEM_BYTES (SMEM_FLOATS * 4)

typedef unsigned long long ull;

__device__ __forceinline__ ull ffma2(ull a, ull b, ull c) {
    ull d;
    asm("fma.rn.f32x2 %0, %1, %2, %3;" : "=l"(d) : "l"(a), "l"(b), "l"(c));
    return d;
}
__device__ __forceinline__ float2 unpack2(ull v) {
    float2 r;
    asm("mov.b64 {%0, %1}, %2;" : "=f"(r.x), "=f"(r.y) : "l"(v));
    return r;
}

// Rotation layout: logical chunk k4 (0..15) of row r lives at memory chunk
// (k4 + rot(r)) & 15, rot(r) = (r>>2) & 1 (4-row granularity = thread tile).
__device__ __forceinline__ int rot_of_row(int r) { return (r >> 2) & 1; }

// ---------------------------------------------------------------------------
// Stage a 64x64 weight matrix into split-pair form. For k-group k4 (0..15):
//   block = Wp + k4*256
//   block[cg*4 + {0..3}]       = {W[4k4][c0],  W[4k4+1][c0],  W[4k4][c1],  W[4k4+1][c1]}
//   block[64 + cg*4 + {0..3}]  = cols 4cg+2,4cg+3 of k-pair (4k4, 4k4+1)
//   block[128.. / 192..]       = same for k-pair (4k4+2, 4k4+3)
// ---------------------------------------------------------------------------
__device__ __forceinline__ void load_weight_pairs(float* __restrict__ Wp,
                                                  const float* __restrict__ Wg,
                                                  int tid) {
#pragma unroll
    for (int it = 0; it < 2; ++it) {
        int idx = tid + it * NTHREADS;        // 512 tasks: p(32) x cg(16)
        if (idx < 512) {
            int p = idx >> 4;                 // k-pair index 0..31
            int cg = idx & 15;
            float4 g0 = *(const float4*)(Wg + (2 * p) * DD + cg * 4);
            float4 g1 = *(const float4*)(Wg + (2 * p + 1) * DD + cg * 4);
            int k4 = p >> 1;
            int sub = (p & 1) ? 128 : 0;
            float* dst = Wp + (k4 << 8) + sub + cg * 4;
            *(float4*)(dst)      = make_float4(g0.x, g1.x, g0.y, g1.y);
            *(float4*)(dst + 64) = make_float4(g0.z, g1.z, g0.w, g1.w);
        }
    }
}

// ---------------------------------------------------------------------------
// GEMM core: C[96x64] = A[96x64] @ W[64x64].
// Thread tile 4 rows x 4 cols; 24 row-groups x 16 col-groups = 384 threads.
// A chunk address = ((k + rot) & 15) * 4; W block offset k*256 compile-time,
// identical across the warp (broadcast). acc[i][j] packs {even,odd} k sums.
// ---------------------------------------------------------------------------
__device__ __forceinline__ void gemm_core(const float* __restrict__ As,
                                          const float* __restrict__ Wp,
                                          ull acc[4][4], int r0, int cg, int rot) {
#pragma unroll
    for (int i = 0; i < 4; ++i)
#pragma unroll
        for (int j = 0; j < 4; ++j) acc[i][j] = 0ull;

    const float* a0 = As + r0 * DD;
    const float* wcg = Wp + cg * 4;

#pragma unroll 4
    for (int k = 0; k < 16; ++k) {
        const float* wb = wcg + (k << 8);
        ulonglong2 w0lo = *(const ulonglong2*)(wb);         // pair p0, cols 0,1
        ulonglong2 w0hi = *(const ulonglong2*)(wb + 64);    // pair p0, cols 2,3
        ulonglong2 w1lo = *(const ulonglong2*)(wb + 128);   // pair p1, cols 0,1
        ulonglong2 w1hi = *(const ulonglong2*)(wb + 192);   // pair p1, cols 2,3
        const int ao = ((k + rot) & 15) << 2;
#pragma unroll
        for (int i = 0; i < 4; ++i) {
            ulonglong2 a = *(const ulonglong2*)(a0 + i * DD + ao);
            // a.x = {x[4k], x[4k+1]}, a.y = {x[4k+2], x[4k+3]}
            acc[i][0] = ffma2(a.x, w0lo.x, acc[i][0]);
            acc[i][1] = ffma2(a.x, w0lo.y, acc[i][1]);
            acc[i][2] = ffma2(a.x, w0hi.x, acc[i][2]);
            acc[i][3] = ffma2(a.x, w0hi.y, acc[i][3]);
            acc[i][0] = ffma2(a.y, w1lo.x, acc[i][0]);
            acc[i][1] = ffma2(a.y, w1lo.y, acc[i][1]);
            acc[i][2] = ffma2(a.y, w1hi.x, acc[i][2]);
            acc[i][3] = ffma2(a.y, w1hi.y, acc[i][3]);
        }
    }
}

// Epilogue -> rotated smem buffer, bias + ReLU.
__device__ __forceinline__ void gemm_to_smem(const float* __restrict__ As,
                                             const float* __restrict__ Wp,
                                             const float* __restrict__ bias,
                                             float* __restrict__ outs, int tid) {
    const int rg = tid >> 4;
    const int cg = tid & 15;
    const int r0 = rg * 4;
    const int rot = rg & 1;
    ull acc[4][4];
    gemm_core(As, Wp, acc, r0, cg, rot);
    float4 bb = *(const float4*)(bias + cg * 4);
    const int sc = ((cg + rot) & 15) << 2;   // rotated store chunk offset
#pragma unroll
    for (int i = 0; i < 4; ++i) {
        float2 s0 = unpack2(acc[i][0]);
        float2 s1 = unpack2(acc[i][1]);
        float2 s2 = unpack2(acc[i][2]);
        float2 s3 = unpack2(acc[i][3]);
        float4 r;
        r.x = fmaxf(s0.x + s0.y + bb.x, 0.f);
        r.y = fmaxf(s1.x + s1.y + bb.y, 0.f);
        r.z = fmaxf(s2.x + s2.y + bb.z, 0.f);
        r.w = fmaxf(s3.x + s3.y + bb.w, 0.f);
        *(float4*)(outs + (r0 + i) * DD + sc) = r;
    }
}

// Epilogue -> global Y (final layer), bias, no ReLU, node guard.
__device__ __forceinline__ void gemm_to_global(const float* __restrict__ As,
                                               const float* __restrict__ Wp,
                                               const float* __restrict__ bias,
                                               float* __restrict__ Y,
                                               int b, int n0, int tid) {
    const int rg = tid >> 4;
    const int cg = tid & 15;
    const int r0 = rg * 4;
    const int rot = rg & 1;
    ull acc[4][4];
    gemm_core(As, Wp, acc, r0, cg, rot);
    float4 bb = *(const float4*)(bias + cg * 4);
#pragma unroll
    for (int i = 0; i < 4; ++i) {
        int row = r0 + i;
        int node = row / TT;
        int t = row - node * TT;
        int n = n0 + node;
        if (n < NN) {
            float2 s0 = unpack2(acc[i][0]);
            float2 s1 = unpack2(acc[i][1]);
            float2 s2 = unpack2(acc[i][2]);
            float2 s3 = unpack2(acc[i][3]);
            float4 r = make_float4(s0.x + s0.y + bb.x, s1.x + s1.y + bb.y,
                                   s2.x + s2.y + bb.z, s3.x + s3.y + bb.w);
            *(float4*)(Y + ((size_t)(b * TT + t) * NN + n) * DD + cg * 4) = r;
        }
    }
}

// ---------------------------------------------------------------------------
// Attention: one thread per (node, head, t-pair): 4*8*12 = 384 tasks.
// K/V rows loaded once per 2 queries. s-loop split 6x4 so rot = j&1 is
// compile-time. No max-subtraction (shift-invariant; masked terms exactly 0).
// ---------------------------------------------------------------------------
__device__ __forceinline__ void attention(const float* __restrict__ Qs,
                                          const float* __restrict__ Ks,
                                          const float* __restrict__ Vs,
                                          float* __restrict__ Os,
                                          int tid) {
    const float scale = 0.3535533905932738f;  // 1/sqrt(8)
    const int node = tid / 96;
    const int rem = tid - node * 96;
    const int h = rem / 12;
    const int tg = rem - h * 12;
    const int tbase = tg * 2;
    const int rbase = node * TT;
    const int ch = 2 * h;

    // Q/O rows rbase + 2tg + {0,1}: rot = ((2tg)>>2)&1 = (tg>>1)&1 (24|rbase)
    const int rotq = (tg >> 1) & 1;
    const int qc1 = ((ch + rotq) & 15) << 2;
    const int qc2 = ((ch + 1 + rotq) & 15) << 2;

    float q[2][8];
    float o[2][8];
    float sum[2];
#pragma unroll
    for (int i = 0; i < 2; ++i) {
        const float* qr = Qs + (rbase + tbase + i) * DD;
        float4 a = *(const float4*)(qr + qc1);
        float4 c = *(const float4*)(qr + qc2);
        q[i][0] = a.x * scale; q[i][1] = a.y * scale;
        q[i][2] = a.z * scale; q[i][3] = a.w * scale;
        q[i][4] = c.x * scale; q[i][5] = c.y * scale;
        q[i][6] = c.z * scale; q[i][7] = c.w * scale;
        sum[i] = 0.0f;
#pragma unroll
        for (int j = 0; j < 8; ++j) o[i][j] = 0.0f;
    }

#pragma unroll
    for (int j = 0; j < 6; ++j) {                 // s = 4j + u; rot = j&1
        const int rots = j & 1;
        const int c1 = ((ch + rots) & 15) << 2;
        const int c2 = ((ch + 1 + rots) & 15) << 2;
#pragma unroll
        for (int u = 0; u < 4; ++u) {
            int s = 4 * j + u;
            const float* kr = Ks + (rbase + s) * DD;
            const float* vr = Vs + (rbase + s) * DD;
            float4 k0 = *(const float4*)(kr + c1);
            float4 k1 = *(const float4*)(kr + c2);
            float4 v0 = *(const float4*)(vr + c1);
            float4 v1 = *(const float4*)(vr + c2);
#pragma unroll
            for (int i = 0; i < 2; ++i) {
                float dot = q[i][0] * k0.x;
                dot = fmaf(q[i][1], k0.y, dot);
                dot = fmaf(q[i][2], k0.z, dot);
                dot = fmaf(q[i][3], k0.w, dot);
                dot = fmaf(q[i][4], k1.x, dot);
                dot = fmaf(q[i][5], k1.y, dot);
                dot = fmaf(q[i][6], k1.z, dot);
                dot = fmaf(q[i][7], k1.w, dot);
                float e = (s >= tbase + i) ? __expf(dot) : 0.0f;
                sum[i] += e;
                o[i][0] = fmaf(e, v0.x, o[i][0]);
                o[i][1] = fmaf(e, v0.y, o[i][1]);
                o[i][2] = fmaf(e, v0.z, o[i][2]);
                o[i][3] = fmaf(e, v0.w, o[i][3]);
                o[i][4] = fmaf(e, v1.x, o[i][4]);
                o[i][5] = fmaf(e, v1.y, o[i][5]);
                o[i][6] = fmaf(e, v1.z, o[i][6]);
                o[i][7] = fmaf(e, v1.w, o[i][7]);
            }
        }
    }

#pragma unroll
    for (int i = 0; i < 2; ++i) {
        float inv = 1.0f / sum[i];
        float* orow = Os + (rbase + tbase + i) * DD;
        *(float4*)(orow + qc1) =
            make_float4(o[i][0] * inv, o[i][1] * inv, o[i][2] * inv, o[i][3] * inv);
        *(float4*)(orow + qc2) =
            make_float4(o[i][4] * inv, o[i][5] * inv, o[i][6] * inv, o[i][7] * inv);
    }
}

// ---------------------------------------------------------------------------
// Fused kernel: one CTA per (batch, 4-node tile); 2 CTAs/SM, 24 warps/SM.
// ---------------------------------------------------------------------------
__global__ void __launch_bounds__(NTHREADS, 2)
temporal_attention_fused(const float* __restrict__ X,
                         const float* __restrict__ Wq, const float* __restrict__ bq,
                         const float* __restrict__ Wk, const float* __restrict__ bk,
                         const float* __restrict__ Wv, const float* __restrict__ bv,
                         const float* __restrict__ Wf1, const float* __restrict__ bf1,
                         const float* __restrict__ Wf2, const float* __restrict__ bf2,
                         float* __restrict__ Y) {
    extern __shared__ float smem[];
    float* Xb = smem + XB_OFF;   // X, later attention output O
    float* Qb = smem + QB_OFF;   // Q, later FC1 hidden H
    float* Kb = smem + KB_OFF;
    float* Vb = smem + VB_OFF;
    float* Wp = smem + WP_OFF;

    const int tid = threadIdx.x;
    const int n0 = blockIdx.x * NB;
    const int b = blockIdx.y;

    // Load X tile into rotated layout; zero-fill out-of-range nodes.
#pragma unroll 2
    for (int i = tid; i < MROWS * 16; i += NTHREADS) {
        int row = i >> 4;
        int f4 = i & 15;
        int node = row / TT;
        int t = row - node * TT;
        int n = n0 + node;
        float4 v = make_float4(0.f, 0.f, 0.f, 0.f);
        if (n < NN)
            v = *(const float4*)(X + ((size_t)(b * TT + t) * NN + n) * DD + f4 * 4);
        int sc = ((f4 + rot_of_row(row)) & 15) << 2;
        *(float4*)(Xb + row * DD + sc) = v;
    }
    load_weight_pairs(Wp, Wq, tid);
    __syncthreads();

    gemm_to_smem(Xb, Wp, bq, Qb, tid);        // q = relu(X@Wq + bq)
    __syncthreads();
    load_weight_pairs(Wp, Wk, tid);
    __syncthreads();
    gemm_to_smem(Xb, Wp, bk, Kb, tid);        // k
    __syncthreads();
    load_weight_pairs(Wp, Wv, tid);
    __syncthreads();
    gemm_to_smem(Xb, Wp, bv, Vb, tid);        // v
    __syncthreads();

    load_weight_pairs(Wp, Wf1, tid);          // stage Wf1 while attention runs
    attention(Qb, Kb, Vb, Xb, tid);           // O overwrites X buffer
    __syncthreads();

    gemm_to_smem(Xb, Wp, bf1, Qb, tid);       // h = relu(O@Wf1 + bf1) -> Q buffer
    __syncthreads();
    load_weight_pairs(Wp, Wf2, tid);
    __syncthreads();
    gemm_to_global(Qb, Wp, bf2, Y, b, n0, tid);  // y = h@Wf2 + bf2
}

// ---------------------------------------------------------------------------
// kernel_launch: inputs per metadata order:
// 0=X 1=STE(unused) 2=Wq 3=bq 4=Wk 5=bk 6=Wv 7=bv 8=Wf1 9=bf1 10=Wf2 11=bf2
// ---------------------------------------------------------------------------
extern "C" void kernel_launch(void* const* d_in, const int* in_sizes, int n_in,
                              void* d_out, int out_size) {
    const float* X   = (const float*)d_in[0];
    const float* Wq  = (const float*)d_in[2];
    const float* bq  = (const float*)d_in[3];
    const float* Wk  = (const float*)d_in[4];
    const float* bk  = (const float*)d_in[5];
    const float* Wv  = (const float*)d_in[6];
    const float* bv  = (const float*)d_in[7];
    const float* Wf1 = (const float*)d_in[8];
    const float* bf1 = (const float*)d_in[9];
    const float* Wf2 = (const float*)d_in[10];
    const float* bf2 = (const float*)d_in[11];
    float* Y = (float*)d_out;

    cudaFuncSetAttribute(temporal_attention_fused,
                         cudaFuncAttributeMaxDynamicSharedMemorySize, SMEM_BYTES);

    dim3 grid(NTILES, BB);
    temporal_attention_fused<<<grid, NTHREADS, SMEM_BYTES>>>(
        X, Wq, bq, Wk, bk, Wv, bv, Wf1, bf1, Wf2, bf2, Y);
}

// round 10
// speedup vs baseline: 1.7363x; 1.7363x over previous
#include <cuda_runtime.h>
#include <cuda_bf16.h>
#include <cstdint>

// Problem constants
#define BB 32
#define TT 24
#define NN 325
#define DD 64

#define NB 4                  // nodes per CTA
#define MROWS 96              // NB * TT
#define NTILES 82
#define NTHREADS 384          // 12 warps: 6 m-tiles x 2 n-halves

// smem byte offsets (total 114688 -> 2 CTAs/SM)
#define XHI_OFF 0             // X hi bf16 [96][64] (later O hi)
#define XLO_OFF 12288         // X lo (later O lo)
#define QF_OFF  24576         // Q fp32 [96][64]  (later H hi/lo)
#define HHI_OFF 24576
#define HLO_OFF 36864
#define KF_OFF  49152         // K fp32
#define VF_OFF  73728         // V fp32
#define WHI_OFF 98304         // W hi bf16 [64][64] k-major
#define WLO_OFF 106496
#define SMEM_BYTES 114688

// ---------------------------------------------------------------------------
// PTX helpers
// ---------------------------------------------------------------------------
__device__ __forceinline__ uint32_t smem_u32(const void* p) {
    return (uint32_t)__cvta_generic_to_shared(p);
}
__device__ __forceinline__ void ldsm4(uint32_t addr, uint32_t& r0, uint32_t& r1,
                                      uint32_t& r2, uint32_t& r3) {
    asm volatile("ldmatrix.sync.aligned.m8n8.x4.shared.b16 {%0,%1,%2,%3}, [%4];"
                 : "=r"(r0), "=r"(r1), "=r"(r2), "=r"(r3) : "r"(addr));
}
__device__ __forceinline__ void ldsm4t(uint32_t addr, uint32_t& r0, uint32_t& r1,
                                       uint32_t& r2, uint32_t& r3) {
    asm volatile("ldmatrix.sync.aligned.m8n8.x4.trans.shared.b16 {%0,%1,%2,%3}, [%4];"
                 : "=r"(r0), "=r"(r1), "=r"(r2), "=r"(r3) : "r"(addr));
}
#define MMA(ac, A0, A1, A2, A3, B0, B1)                                        \
    asm volatile(                                                              \
        "mma.sync.aligned.m16n8k16.row.col.f32.bf16.bf16.f32 "                 \
        "{%0,%1,%2,%3}, {%4,%5,%6,%7}, {%8,%9}, {%0,%1,%2,%3};"                \
        : "+f"((ac)[0]), "+f"((ac)[1]), "+f"((ac)[2]), "+f"((ac)[3])           \
        : "r"(A0), "r"(A1), "r"(A2), "r"(A3), "r"(B0), "r"(B1))

// Split fp32 pair into bf16 hi pair + bf16 residual pair (packed b32 each).
// Low 16 bits = first (lower-k) element, matching row-major bf16 order.
__device__ __forceinline__ void split_pair(float a, float b,
                                           uint32_t& hi, uint32_t& lo) {
    __nv_bfloat16 ah = __float2bfloat16_rn(a);
    __nv_bfloat16 bh = __float2bfloat16_rn(b);
    __nv_bfloat16 al = __float2bfloat16_rn(a - __bfloat162float(ah));
    __nv_bfloat16 bl = __float2bfloat16_rn(b - __bfloat162float(bh));
    __nv_bfloat162 H = __halves2bfloat162(ah, bh);
    __nv_bfloat162 L = __halves2bfloat162(al, bl);
    hi = *reinterpret_cast<uint32_t*>(&H);
    lo = *reinterpret_cast<uint32_t*>(&L);
}

// ---------------------------------------------------------------------------
// Stage a 64x64 fp32 weight (k-major) into bf16 hi/lo k-major smem with
// chunk-XOR swizzle: 16B chunk g of row k stored at chunk g ^ (k & 7).
// ---------------------------------------------------------------------------
__device__ __forceinline__ void stage_W(char* __restrict__ Whi,
                                        char* __restrict__ Wlo,
                                        const float* __restrict__ Wg, int tid) {
#pragma unroll
    for (int p = 0; p < 2; ++p) {
        int idx = tid + p * NTHREADS;      // 512 tasks: k(64) x group(8)
        if (idx < 512) {
            int k = idx >> 3, g = idx & 7;
            const float* src = Wg + k * 64 + g * 8;
            float4 f0 = *(const float4*)(src);
            float4 f1 = *(const float4*)(src + 4);
            uint32_t h0, l0, h1, l1, h2, l2, h3, l3;
            split_pair(f0.x, f0.y, h0, l0);
            split_pair(f0.z, f0.w, h1, l1);
            split_pair(f1.x, f1.y, h2, l2);
            split_pair(f1.z, f1.w, h3, l3);
            int off = k * 128 + ((g ^ (k & 7)) << 4);
            *(uint4*)(Whi + off) = make_uint4(h0, h1, h2, h3);
            *(uint4*)(Wlo + off) = make_uint4(l0, l1, l2, l3);
        }
    }
}

// ---------------------------------------------------------------------------
// Tensor-core GEMM: C[96x64] = A[96x64] @ W[64x64] with 3-term bf16 split.
// A: bf16 hi/lo [m][k] (128B rows, chunk^=(m&7)); W: bf16 hi/lo [k][n].
// 12 warps: warp w -> m-tile (w%6)*16, n-half (w/6)*32. 4 n8-tiles/warp.
// MODE 0: fp32 smem out (+bias,+relu)  MODE 1: bf16 hi/lo out (+bias,+relu)
// MODE 2: global fp32 out (+bias)
// ---------------------------------------------------------------------------
template <int MODE>
__device__ __forceinline__ void gemm_mma(
    uint32_t aHi, uint32_t aLo, uint32_t wHi, uint32_t wLo,
    const float* __restrict__ bias,
    char* __restrict__ outF,
    char* __restrict__ outHi, char* __restrict__ outLo,
    float* __restrict__ Y, int b, int n0blk, int tid) {
    const int wid = tid >> 5, lane = tid & 31;
    const int m0 = (wid % 6) * 16;
    const int n0 = (wid / 6) * 32;
    const int i7 = lane & 7;
    const int h8 = (lane >> 3) & 1;
    const int kh = (lane >> 4) & 1;

    // A lane address: tiles [m0,k0],[m0+8,k0],[m0,k0+8],[m0+8,k0+8]
    const int rowA = m0 + i7 + h8 * 8;
    const uint32_t aHiB = aHi + rowA * 128;
    const uint32_t aLoB = aLo + rowA * 128;
    // B lane address (trans): tiles [k0,n0],[k0+8,n0],[k0,n0+8],[k0+8,n0+8]
    const int rowB = i7 + h8 * 8;
    const uint32_t cB0 = (uint32_t)((((n0) >> 3) + kh) ^ i7) << 4;
    const uint32_t cB1 = (uint32_t)((((n0 + 16) >> 3) + kh) ^ i7) << 4;
    const uint32_t wHiB = wHi + rowB * 128;
    const uint32_t wLoB = wLo + rowB * 128;

    float acc[4][4];
#pragma unroll
    for (int j = 0; j < 4; ++j)
#pragma unroll
        for (int x = 0; x < 4; ++x) acc[j][x] = 0.0f;

#pragma unroll
    for (int ks = 0; ks < 4; ++ks) {
        const uint32_t cA = (uint32_t)(((2 * ks) + kh) ^ i7) << 4;
        uint32_t ah0, ah1, ah2, ah3, al0, al1, al2, al3;
        ldsm4(aHiB + cA, ah0, ah1, ah2, ah3);
        ldsm4(aLoB + cA, al0, al1, al2, al3);
        const uint32_t wk = (uint32_t)(ks * 2048);
        {   // n-half 0: tiles n0, n0+8
            uint32_t bh0, bh1, bh2, bh3, bl0, bl1, bl2, bl3;
            ldsm4t(wHiB + wk + cB0, bh0, bh1, bh2, bh3);
            ldsm4t(wLoB + wk + cB0, bl0, bl1, bl2, bl3);
            MMA(acc[0], ah0, ah1, ah2, ah3, bh0, bh1);
            MMA(acc[0], ah0, ah1, ah2, ah3, bl0, bl1);
            MMA(acc[0], al0, al1, al2, al3, bh0, bh1);
            MMA(acc[1], ah0, ah1, ah2, ah3, bh2, bh3);
            MMA(acc[1], ah0, ah1, ah2, ah3, bl2, bl3);
            MMA(acc[1], al0, al1, al2, al3, bh2, bh3);
        }
        {   // n-half 1: tiles n0+16, n0+24
            uint32_t bh0, bh1, bh2, bh3, bl0, bl1, bl2, bl3;
            ldsm4t(wHiB + wk + cB1, bh0, bh1, bh2, bh3);
            ldsm4t(wLoB + wk + cB1, bl0, bl1, bl2, bl3);
            MMA(acc[2], ah0, ah1, ah2, ah3, bh0, bh1);
            MMA(acc[2], ah0, ah1, ah2, ah3, bl0, bl1);
            MMA(acc[2], al0, al1, al2, al3, bh0, bh1);
            MMA(acc[3], ah0, ah1, ah2, ah3, bh2, bh3);
            MMA(acc[3], ah0, ah1, ah2, ah3, bl2, bl3);
            MMA(acc[3], al0, al1, al2, al3, bh2, bh3);
        }
    }

    // Epilogue. D frag: d0,d1 -> row m0+g cols cc,cc+1; d2,d3 -> row m0+g+8.
    const int g = lane >> 2;
    const int c2 = (lane & 3) * 2;
#pragma unroll
    for (int j = 0; j < 4; ++j) {
        const int cc = n0 + 8 * j + c2;
        float2 bv = *(const float2*)(bias + cc);
        float v00 = acc[j][0] + bv.x, v01 = acc[j][1] + bv.y;
        float v10 = acc[j][2] + bv.x, v11 = acc[j][3] + bv.y;
        const int r1 = m0 + g, r2 = r1 + 8;
        if (MODE == 0) {
            v00 = fmaxf(v00, 0.f); v01 = fmaxf(v01, 0.f);
            v10 = fmaxf(v10, 0.f); v11 = fmaxf(v11, 0.f);
            const int coff = (((cc >> 2) ^ g) << 4) + (cc & 3) * 4;
            *(float2*)(outF + r1 * 256 + coff) = make_float2(v00, v01);
            *(float2*)(outF + r2 * 256 + coff) = make_float2(v10, v11);
        } else if (MODE == 1) {
            v00 = fmaxf(v00, 0.f); v01 = fmaxf(v01, 0.f);
            v10 = fmaxf(v10, 0.f); v11 = fmaxf(v11, 0.f);
            uint32_t hi1, lo1, hi2, lo2;
            split_pair(v00, v01, hi1, lo1);
            split_pair(v10, v11, hi2, lo2);
            const int coff = (((cc >> 3) ^ g) << 4) + (cc & 7) * 2;
            *(uint32_t*)(outHi + r1 * 128 + coff) = hi1;
            *(uint32_t*)(outLo + r1 * 128 + coff) = lo1;
            *(uint32_t*)(outHi + r2 * 128 + coff) = hi2;
            *(uint32_t*)(outLo + r2 * 128 + coff) = lo2;
        } else {
            int node1 = r1 / TT, t1 = r1 - node1 * TT, n1 = n0blk + node1;
            if (n1 < NN)
                *(float2*)(Y + ((size_t)(b * TT + t1) * NN + n1) * DD + cc) =
                    make_float2(v00, v01);
            int node2 = r2 / TT, t2 = r2 - node2 * TT, n2 = n0blk + node2;
            if (n2 < NN)
                *(float2*)(Y + ((size_t)(b * TT + t2) * NN + n2) * DD + cc) =
                    make_float2(v10, v11);
        }
    }
}

// ---------------------------------------------------------------------------
// Attention: one thread per (node, head, t-pair): 4*8*12 = 384 tasks.
// Q/K/V fp32 buffers (256B rows, 16B chunk c stored at c^(row&7)).
// Writes O as bf16 hi/lo (A operand of FC1). No max-subtraction.
// ---------------------------------------------------------------------------
__device__ __forceinline__ void attention(const char* __restrict__ Qf,
                                          const char* __restrict__ Kf,
                                          const char* __restrict__ Vf,
                                          char* __restrict__ Ohi,
                                          char* __restrict__ Olo, int tid) {
    const float scale = 0.3535533905932738f;  // 1/sqrt(8)
    const int node = tid / 96;
    const int rem = tid - node * 96;
    const int h = rem / 12;
    const int tg = rem - h * 12;
    const int tbase = tg * 2;
    const int rbase = node * TT;      // multiple of 24 -> (rbase & 7) == 0
    const int ch = 2 * h;

    float q[2][8], o[2][8], sum[2];
#pragma unroll
    for (int i = 0; i < 2; ++i) {
        int r7 = (tbase + i) & 7;
        const char* qr = Qf + (rbase + tbase + i) * 256;
        float4 a = *(const float4*)(qr + ((ch ^ r7) << 4));
        float4 c = *(const float4*)(qr + (((ch + 1) ^ r7) << 4));
        q[i][0] = a.x * scale; q[i][1] = a.y * scale;
        q[i][2] = a.z * scale; q[i][3] = a.w * scale;
        q[i][4] = c.x * scale; q[i][5] = c.y * scale;
        q[i][6] = c.z * scale; q[i][7] = c.w * scale;
        sum[i] = 0.0f;
#pragma unroll
        for (int j = 0; j < 8; ++j) o[i][j] = 0.0f;
    }

#pragma unroll
    for (int a8 = 0; a8 < 3; ++a8) {
#pragma unroll
        for (int e = 0; e < 8; ++e) {      // s & 7 == e (compile-time)
            int s = 8 * a8 + e;
            const char* kr = Kf + (rbase + s) * 256;
            const char* vr = Vf + (rbase + s) * 256;
            const int c1 = ((ch ^ e) << 4), c2v = (((ch + 1) ^ e) << 4);
            float4 k0 = *(const float4*)(kr + c1);
            float4 k1 = *(const float4*)(kr + c2v);
            float4 v0 = *(const float4*)(vr + c1);
            float4 v1 = *(const float4*)(vr + c2v);
#pragma unroll
            for (int i = 0; i < 2; ++i) {
                float dot = q[i][0] * k0.x;
                dot = fmaf(q[i][1], k0.y, dot);
                dot = fmaf(q[i][2], k0.z, dot);
                dot = fmaf(q[i][3], k0.w, dot);
                dot = fmaf(q[i][4], k1.x, dot);
                dot = fmaf(q[i][5], k1.y, dot);
                dot = fmaf(q[i][6], k1.z, dot);
                dot = fmaf(q[i][7], k1.w, dot);
                float e2 = (s >= tbase + i) ? __expf(dot) : 0.0f;
                sum[i] += e2;
                o[i][0] = fmaf(e2, v0.x, o[i][0]);
                o[i][1] = fmaf(e2, v0.y, o[i][1]);
                o[i][2] = fmaf(e2, v0.z, o[i][2]);
                o[i][3] = fmaf(e2, v0.w, o[i][3]);
                o[i][4] = fmaf(e2, v1.x, o[i][4]);
                o[i][5] = fmaf(e2, v1.y, o[i][5]);
                o[i][6] = fmaf(e2, v1.z, o[i][6]);
                o[i][7] = fmaf(e2, v1.w, o[i][7]);
            }
        }
    }

#pragma unroll
    for (int i = 0; i < 2; ++i) {
        float inv = 1.0f / sum[i];
        int row = rbase + tbase + i;
        int r7 = (tbase + i) & 7;
        uint32_t hi[4], lo[4];
        split_pair(o[i][0] * inv, o[i][1] * inv, hi[0], lo[0]);
        split_pair(o[i][2] * inv, o[i][3] * inv, hi[1], lo[1]);
        split_pair(o[i][4] * inv, o[i][5] * inv, hi[2], lo[2]);
        split_pair(o[i][6] * inv, o[i][7] * inv, hi[3], lo[3]);
        int off = row * 128 + ((h ^ r7) << 4);   // bf16 chunk h of row
        *(uint4*)(Ohi + off) = make_uint4(hi[0], hi[1], hi[2], hi[3]);
        *(uint4*)(Olo + off) = make_uint4(lo[0], lo[1], lo[2], lo[3]);
    }
}

// ---------------------------------------------------------------------------
// Fused kernel: one CTA per (batch, 4-node tile); 2 CTAs/SM, 24 warps/SM.
// ---------------------------------------------------------------------------
__global__ void __launch_bounds__(NTHREADS, 2)
temporal_attention_mma(const float* __restrict__ X,
                       const float* __restrict__ Wq, const float* __restrict__ bq,
                       const float* __restrict__ Wk, const float* __restrict__ bk,
                       const float* __restrict__ Wv, const float* __restrict__ bv,
                       const float* __restrict__ Wf1, const float* __restrict__ bf1,
                       const float* __restrict__ Wf2, const float* __restrict__ bf2,
                       float* __restrict__ Y) {
    extern __shared__ char smem[];
    char* Xhi = smem + XHI_OFF;
    char* Xlo = smem + XLO_OFF;
    char* Whi = smem + WHI_OFF;
    char* Wlo = smem + WLO_OFF;

    const int tid = threadIdx.x;
    const int n0blk = blockIdx.x * NB;
    const int b = blockIdx.y;

    const uint32_t xhiU = smem_u32(Xhi);
    const uint32_t xloU = smem_u32(Xlo);
    const uint32_t whiU = smem_u32(Whi);
    const uint32_t wloU = smem_u32(Wlo);
    const uint32_t hhiU = smem_u32(smem + HHI_OFF);
    const uint32_t hloU = smem_u32(smem + HLO_OFF);

    // Stage X as bf16 hi/lo (zero-fill out-of-range nodes).
#pragma unroll
    for (int p = 0; p < 2; ++p) {
        int idx = tid + p * NTHREADS;      // 768 tasks: row(96) x group(8)
        int row = idx >> 3, g = idx & 7;
        int node = row / TT, t = row - node * TT;
        int n = n0blk + node;
        float4 f0 = make_float4(0.f, 0.f, 0.f, 0.f);
        float4 f1 = make_float4(0.f, 0.f, 0.f, 0.f);
        if (n < NN) {
            const float* src = X + ((size_t)(b * TT + t) * NN + n) * DD + g * 8;
            f0 = *(const float4*)(src);
            f1 = *(const float4*)(src + 4);
        }
        uint32_t h0, l0, h1, l1, h2, l2, h3, l3;
        split_pair(f0.x, f0.y, h0, l0);
        split_pair(f0.z, f0.w, h1, l1);
        split_pair(f1.x, f1.y, h2, l2);
        split_pair(f1.z, f1.w, h3, l3);
        int off = row * 128 + ((g ^ (row & 7)) << 4);
        *(uint4*)(Xhi + off) = make_uint4(h0, h1, h2, h3);
        *(uint4*)(Xlo + off) = make_uint4(l0, l1, l2, l3);
    }
    stage_W(Whi, Wlo, Wq, tid);
    __syncthreads();

    gemm_mma<0>(xhiU, xloU, whiU, wloU, bq, smem + QF_OFF,
                nullptr, nullptr, nullptr, 0, 0, tid);   // Q
    __syncthreads();
    stage_W(Whi, Wlo, Wk, tid);
    __syncthreads();
    gemm_mma<0>(xhiU, xloU, whiU, wloU, bk, smem + KF_OFF,
                nullptr, nullptr, nullptr, 0, 0, tid);   // K
    __syncthreads();
    stage_W(Whi, Wlo, Wv, tid);
    __syncthreads();
    gemm_mma<0>(xhiU, xloU, whiU, wloU, bv, smem + VF_OFF,
                nullptr, nullptr, nullptr, 0, 0, tid);   // V
    __syncthreads();

    stage_W(Whi, Wlo, Wf1, tid);                          // overlap with attn
    attention(smem + QF_OFF, smem + KF_OFF, smem + VF_OFF, Xhi, Xlo, tid);
    __syncthreads();

    gemm_mma<1>(xhiU, xloU, whiU, wloU, bf1, nullptr,
                smem + HHI_OFF, smem + HLO_OFF, nullptr, 0, 0, tid);  // FC1
    __syncthreads();
    stage_W(Whi, Wlo, Wf2, tid);
    __syncthreads();
    gemm_mma<2>(hhiU, hloU, whiU, wloU, bf2, nullptr,
                nullptr, nullptr, Y, b, n0blk, tid);      // FC2 -> global
}

// ---------------------------------------------------------------------------
// kernel_launch: inputs per metadata order:
// 0=X 1=STE(unused) 2=Wq 3=bq 4=Wk 5=bk 6=Wv 7=bv 8=Wf1 9=bf1 10=Wf2 11=bf2
// ---------------------------------------------------------------------------
extern "C" void kernel_launch(void* const* d_in, const int* in_sizes, int n_in,
                              void* d_out, int out_size) {
    const float* X   = (const float*)d_in[0];
    const float* Wq  = (const float*)d_in[2];
    const float* bq  = (const float*)d_in[3];
    const float* Wk  = (const float*)d_in[4];
    const float* bk  = (const float*)d_in[5];
    const float* Wv  = (const float*)d_in[6];
    const float* bv  = (const float*)d_in[7];
    const float* Wf1 = (const float*)d_in[8];
    const float* bf1 = (const float*)d_in[9];
    const float* Wf2 = (const float*)d_in[10];
    const float* bf2 = (const float*)d_in[11];
    float* Y = (float*)d_out;

    cudaFuncSetAttribute(temporal_attention_mma,
                         cudaFuncAttributeMaxDynamicSharedMemorySize, SMEM_BYTES);

    dim3 grid(NTILES, BB);
    temporal_attention_mma<<<grid, NTHREADS, SMEM_BYTES>>>(
        X, Wq, bq, Wk, bk, Wv, bv, Wf1, bf1, Wf2, bf2, Y);
}

// round 11
// speedup vs baseline: 1.7703x; 1.0196x over previous
#include <cuda_runtime.h>
#include <cuda_bf16.h>
#include <cstdint>

// Problem constants
#define BB 32
#define TT 24
#define NN 325
#define DD 64

#define NB 4                  // nodes per CTA
#define MROWS 96              // NB * TT
#define NTILES 82
#define NTHREADS 384          // 12 warps: 6 m-tiles x 2 n-halves

// smem byte offsets (total 114688 -> 2 CTAs/SM)
#define XHI_OFF 0             // X hi bf16 [96][64] (later O hi)
#define XLO_OFF 12288         // X lo (later O lo)
#define QF_OFF  24576         // Q fp32 [96][64]  (later H hi/lo)
#define HHI_OFF 24576
#define HLO_OFF 36864
#define KF_OFF  49152         // K fp32 (head 16K doubles as W bounce)
#define VF_OFF  73728         // V fp32 (head 16K doubles as W bounce)
#define WHI_OFF 98304         // W hi bf16 [64][64] k-major (pre-split)
#define WLO_OFF 106496
#define SMEM_BYTES 114688

// Pre-split weights: [w][0..8192) = hi plane, [8192..16384) = lo plane,
// already in the swizzled smem layout (row k: 128B; chunk g at g^(k&7)).
__device__ __align__(16) unsigned char g_wsplit[5][16384];

// ---------------------------------------------------------------------------
// PTX helpers
// ---------------------------------------------------------------------------
__device__ __forceinline__ uint32_t smem_u32(const void* p) {
    return (uint32_t)__cvta_generic_to_shared(p);
}
__device__ __forceinline__ void ldsm4(uint32_t addr, uint32_t& r0, uint32_t& r1,
                                      uint32_t& r2, uint32_t& r3) {
    asm volatile("ldmatrix.sync.aligned.m8n8.x4.shared.b16 {%0,%1,%2,%3}, [%4];"
                 : "=r"(r0), "=r"(r1), "=r"(r2), "=r"(r3) : "r"(addr));
}
__device__ __forceinline__ void ldsm4t(uint32_t addr, uint32_t& r0, uint32_t& r1,
                                       uint32_t& r2, uint32_t& r3) {
    asm volatile("ldmatrix.sync.aligned.m8n8.x4.trans.shared.b16 {%0,%1,%2,%3}, [%4];"
                 : "=r"(r0), "=r"(r1), "=r"(r2), "=r"(r3) : "r"(addr));
}
#define MMA(ac, A0, A1, A2, A3, B0, B1)                                        \
    asm volatile(                                                              \
        "mma.sync.aligned.m16n8k16.row.col.f32.bf16.bf16.f32 "                 \
        "{%0,%1,%2,%3}, {%4,%5,%6,%7}, {%8,%9}, {%0,%1,%2,%3};"                \
        : "+f"((ac)[0]), "+f"((ac)[1]), "+f"((ac)[2]), "+f"((ac)[3])           \
        : "r"(A0), "r"(A1), "r"(A2), "r"(A3), "r"(B0), "r"(B1))

__device__ __forceinline__ float ex2f(float x) {
    float y;
    asm("ex2.approx.f32 %0, %1;" : "=f"(y) : "f"(x));
    return y;
}

// Split fp32 pair into bf16 hi pair + bf16 residual pair (packed b32 each).
__device__ __forceinline__ void split_pair(float a, float b,
                                           uint32_t& hi, uint32_t& lo) {
    __nv_bfloat16 ah = __float2bfloat16_rn(a);
    __nv_bfloat16 bh = __float2bfloat16_rn(b);
    __nv_bfloat16 al = __float2bfloat16_rn(a - __bfloat162float(ah));
    __nv_bfloat16 bl = __float2bfloat16_rn(b - __bfloat162float(bh));
    __nv_bfloat162 H = __halves2bfloat162(ah, bh);
    __nv_bfloat162 L = __halves2bfloat162(al, bl);
    hi = *reinterpret_cast<uint32_t*>(&H);
    lo = *reinterpret_cast<uint32_t*>(&L);
}

// ---------------------------------------------------------------------------
// Prep kernel: split each 64x64 fp32 weight into bf16 hi/lo planes in the
// final swizzled layout, once for all main-kernel CTAs.
// ---------------------------------------------------------------------------
__global__ void prep_weights(const float* __restrict__ Wq,
                             const float* __restrict__ Wk,
                             const float* __restrict__ Wv,
                             const float* __restrict__ Wf1,
                             const float* __restrict__ Wf2) {
    const float* Ws[5] = {Wq, Wk, Wv, Wf1, Wf2};
    const float* W = Ws[blockIdx.x];
    unsigned char* hi = g_wsplit[blockIdx.x];
    unsigned char* lo = g_wsplit[blockIdx.x] + 8192;
    int tid = threadIdx.x;                 // 512 threads: k(64) x g(8)
    int k = tid >> 3, g = tid & 7;
    const float* src = W + k * 64 + g * 8;
    float4 f0 = *(const float4*)(src);
    float4 f1 = *(const float4*)(src + 4);
    uint32_t h0, l0, h1, l1, h2, l2, h3, l3;
    split_pair(f0.x, f0.y, h0, l0);
    split_pair(f0.z, f0.w, h1, l1);
    split_pair(f1.x, f1.y, h2, l2);
    split_pair(f1.z, f1.w, h3, l3);
    int off = k * 128 + ((g ^ (k & 7)) << 4);
    *(uint4*)(hi + off) = make_uint4(h0, h1, h2, h3);
    *(uint4*)(lo + off) = make_uint4(l0, l1, l2, l3);
}

// ---------------------------------------------------------------------------
// cp.async fetch of one pre-split W (16KB) into an smem region + bounce copy.
// ---------------------------------------------------------------------------
__device__ __forceinline__ void fetch_W(uint32_t dstU, int widx, int tid) {
#pragma unroll
    for (int i = 0; i < 3; ++i) {
        int idx = tid + i * NTHREADS;
        if (idx < 1024)
            asm volatile("cp.async.ca.shared.global [%0], [%1], 16;"
                         :: "r"(dstU + idx * 16),
                            "l"(g_wsplit[widx] + idx * 16));
    }
    asm volatile("cp.async.commit_group;" ::: "memory");
}
__device__ __forceinline__ void wait_cp() {
    asm volatile("cp.async.wait_group 0;" ::: "memory");
}
__device__ __forceinline__ void copy_16k(char* __restrict__ dst,
                                         const char* __restrict__ src, int tid) {
#pragma unroll
    for (int i = 0; i < 3; ++i) {
        int idx = tid + i * NTHREADS;
        if (idx < 1024)
            *(uint4*)(dst + idx * 16) = *(const uint4*)(src + idx * 16);
    }
}

// ---------------------------------------------------------------------------
// Tensor-core GEMM: C[96x64] = A[96x64] @ W[64x64] with 3-term bf16 split.
// A: bf16 hi/lo [m][k] (128B rows, chunk^=(m&7)); W: bf16 hi/lo [k][n].
// 12 warps: warp w -> m-tile (w%6)*16, n-half (w/6)*32.
// MODE 0: fp32 smem out (+bias,+relu)  MODE 1: bf16 hi/lo out (+bias,+relu)
// MODE 2: global fp32 out (+bias)
// ---------------------------------------------------------------------------
template <int MODE>
__device__ __forceinline__ void gemm_mma(
    uint32_t aHi, uint32_t aLo, uint32_t wHi, uint32_t wLo,
    const float* __restrict__ bias,
    char* __restrict__ outF,
    char* __restrict__ outHi, char* __restrict__ outLo,
    float* __restrict__ Y, int b, int n0blk, int tid) {
    const int wid = tid >> 5, lane = tid & 31;
    const int m0 = (wid % 6) * 16;
    const int n0 = (wid / 6) * 32;
    const int i7 = lane & 7;
    const int h8 = (lane >> 3) & 1;
    const int kh = (lane >> 4) & 1;

    const int rowA = m0 + i7 + h8 * 8;
    const uint32_t aHiB = aHi + rowA * 128;
    const uint32_t aLoB = aLo + rowA * 128;
    const int rowB = i7 + h8 * 8;
    const uint32_t cB0 = (uint32_t)((((n0) >> 3) + kh) ^ i7) << 4;
    const uint32_t cB1 = (uint32_t)((((n0 + 16) >> 3) + kh) ^ i7) << 4;
    const uint32_t wHiB = wHi + rowB * 128;
    const uint32_t wLoB = wLo + rowB * 128;

    float acc[4][4];
#pragma unroll
    for (int j = 0; j < 4; ++j)
#pragma unroll
        for (int x = 0; x < 4; ++x) acc[j][x] = 0.0f;

#pragma unroll
    for (int ks = 0; ks < 4; ++ks) {
        const uint32_t cA = (uint32_t)(((2 * ks) + kh) ^ i7) << 4;
        uint32_t ah0, ah1, ah2, ah3, al0, al1, al2, al3;
        ldsm4(aHiB + cA, ah0, ah1, ah2, ah3);
        ldsm4(aLoB + cA, al0, al1, al2, al3);
        const uint32_t wk = (uint32_t)(ks * 2048);
        {
            uint32_t bh0, bh1, bh2, bh3, bl0, bl1, bl2, bl3;
            ldsm4t(wHiB + wk + cB0, bh0, bh1, bh2, bh3);
            ldsm4t(wLoB + wk + cB0, bl0, bl1, bl2, bl3);
            MMA(acc[0], ah0, ah1, ah2, ah3, bh0, bh1);
            MMA(acc[0], ah0, ah1, ah2, ah3, bl0, bl1);
            MMA(acc[0], al0, al1, al2, al3, bh0, bh1);
            MMA(acc[1], ah0, ah1, ah2, ah3, bh2, bh3);
            MMA(acc[1], ah0, ah1, ah2, ah3, bl2, bl3);
            MMA(acc[1], al0, al1, al2, al3, bh2, bh3);
        }
        {
            uint32_t bh0, bh1, bh2, bh3, bl0, bl1, bl2, bl3;
            ldsm4t(wHiB + wk + cB1, bh0, bh1, bh2, bh3);
            ldsm4t(wLoB + wk + cB1, bl0, bl1, bl2, bl3);
            MMA(acc[2], ah0, ah1, ah2, ah3, bh0, bh1);
            MMA(acc[2], ah0, ah1, ah2, ah3, bl0, bl1);
            MMA(acc[2], al0, al1, al2, al3, bh0, bh1);
            MMA(acc[3], ah0, ah1, ah2, ah3, bh2, bh3);
            MMA(acc[3], ah0, ah1, ah2, ah3, bl2, bl3);
            MMA(acc[3], al0, al1, al2, al3, bh2, bh3);
        }
    }

    const int g = lane >> 2;
    const int c2 = (lane & 3) * 2;
#pragma unroll
    for (int j = 0; j < 4; ++j) {
        const int cc = n0 + 8 * j + c2;
        float2 bv = *(const float2*)(bias + cc);
        float v00 = acc[j][0] + bv.x, v01 = acc[j][1] + bv.y;
        float v10 = acc[j][2] + bv.x, v11 = acc[j][3] + bv.y;
        const int r1 = m0 + g, r2 = r1 + 8;
        if (MODE == 0) {
            v00 = fmaxf(v00, 0.f); v01 = fmaxf(v01, 0.f);
            v10 = fmaxf(v10, 0.f); v11 = fmaxf(v11, 0.f);
            const int coff = (((cc >> 2) ^ g) << 4) + (cc & 3) * 4;
            *(float2*)(outF + r1 * 256 + coff) = make_float2(v00, v01);
            *(float2*)(outF + r2 * 256 + coff) = make_float2(v10, v11);
        } else if (MODE == 1) {
            v00 = fmaxf(v00, 0.f); v01 = fmaxf(v01, 0.f);
            v10 = fmaxf(v10, 0.f); v11 = fmaxf(v11, 0.f);
            uint32_t hi1, lo1, hi2, lo2;
            split_pair(v00, v01, hi1, lo1);
            split_pair(v10, v11, hi2, lo2);
            const int coff = (((cc >> 3) ^ g) << 4) + (cc & 7) * 2;
            *(uint32_t*)(outHi + r1 * 128 + coff) = hi1;
            *(uint32_t*)(outLo + r1 * 128 + coff) = lo1;
            *(uint32_t*)(outHi + r2 * 128 + coff) = hi2;
            *(uint32_t*)(outLo + r2 * 128 + coff) = lo2;
        } else {
            int node1 = r1 / TT, t1 = r1 - node1 * TT, n1 = n0blk + node1;
            if (n1 < NN)
                *(float2*)(Y + ((size_t)(b * TT + t1) * NN + n1) * DD + cc) =
                    make_float2(v00, v01);
            int node2 = r2 / TT, t2 = r2 - node2 * TT, n2 = n0blk + node2;
            if (n2 < NN)
                *(float2*)(Y + ((size_t)(b * TT + t2) * NN + n2) * DD + cc) =
                    make_float2(v10, v11);
        }
    }
}

// ---------------------------------------------------------------------------
// Attention: one thread per (node, head, t-pair): 4*8*12 = 384 tasks.
// Q/K/V fp32 buffers (256B rows, 16B chunk c at c^(row&7)).
// Scale folds 1/sqrt(d) * log2(e); exp via raw ex2.approx.
// Writes O as bf16 hi/lo (A operand of FC1). No max-subtraction.
// ---------------------------------------------------------------------------
__device__ __forceinline__ void attention(const char* __restrict__ Qf,
                                          const char* __restrict__ Kf,
                                          const char* __restrict__ Vf,
                                          char* __restrict__ Ohi,
                                          char* __restrict__ Olo, int tid) {
    const float scale = 0.5100697176f;   // (1/sqrt(8)) * log2(e)
    const int node = tid / 96;
    const int rem = tid - node * 96;
    const int h = rem / 12;
    const int tg = rem - h * 12;
    const int tbase = tg * 2;
    const int rbase = node * TT;         // multiple of 24 -> (rbase & 7) == 0
    const int ch = 2 * h;

    float q[2][8], o[2][8], sum[2];
#pragma unroll
    for (int i = 0; i < 2; ++i) {
        int r7 = (tbase + i) & 7;
        const char* qr = Qf + (rbase + tbase + i) * 256;
        float4 a = *(const float4*)(qr + ((ch ^ r7) << 4));
        float4 c = *(const float4*)(qr + (((ch + 1) ^ r7) << 4));
        q[i][0] = a.x * scale; q[i][1] = a.y * scale;
        q[i][2] = a.z * scale; q[i][3] = a.w * scale;
        q[i][4] = c.x * scale; q[i][5] = c.y * scale;
        q[i][6] = c.z * scale; q[i][7] = c.w * scale;
        sum[i] = 0.0f;
#pragma unroll
        for (int j = 0; j < 8; ++j) o[i][j] = 0.0f;
    }

#pragma unroll
    for (int a8 = 0; a8 < 3; ++a8) {
#pragma unroll
        for (int e = 0; e < 8; ++e) {      // s & 7 == e (compile-time)
            int s = 8 * a8 + e;
            const char* kr = Kf + (rbase + s) * 256;
            const char* vr = Vf + (rbase + s) * 256;
            const int c1 = ((ch ^ e) << 4), c2v = (((ch + 1) ^ e) << 4);
            float4 k0 = *(const float4*)(kr + c1);
            float4 k1 = *(const float4*)(kr + c2v);
            float4 v0 = *(const float4*)(vr + c1);
            float4 v1 = *(const float4*)(vr + c2v);
#pragma unroll
            for (int i = 0; i < 2; ++i) {
                float dot = q[i][0] * k0.x;
                dot = fmaf(q[i][1], k0.y, dot);
                dot = fmaf(q[i][2], k0.z, dot);
                dot = fmaf(q[i][3], k0.w, dot);
                dot = fmaf(q[i][4], k1.x, dot);
                dot = fmaf(q[i][5], k1.y, dot);
                dot = fmaf(q[i][6], k1.z, dot);
                dot = fmaf(q[i][7], k1.w, dot);
                float e2 = (s >= tbase + i) ? ex2f(dot) : 0.0f;
                sum[i] += e2;
                o[i][0] = fmaf(e2, v0.x, o[i][0]);
                o[i][1] = fmaf(e2, v0.y, o[i][1]);
                o[i][2] = fmaf(e2, v0.z, o[i][2]);
                o[i][3] = fmaf(e2, v0.w, o[i][3]);
                o[i][4] = fmaf(e2, v1.x, o[i][4]);
                o[i][5] = fmaf(e2, v1.y, o[i][5]);
                o[i][6] = fmaf(e2, v1.z, o[i][6]);
                o[i][7] = fmaf(e2, v1.w, o[i][7]);
            }
        }
    }

#pragma unroll
    for (int i = 0; i < 2; ++i) {
        float inv = 1.0f / sum[i];
        int row = rbase + tbase + i;
        int r7 = (tbase + i) & 7;
        uint32_t hi[4], lo[4];
        split_pair(o[i][0] * inv, o[i][1] * inv, hi[0], lo[0]);
        split_pair(o[i][2] * inv, o[i][3] * inv, hi[1], lo[1]);
        split_pair(o[i][4] * inv, o[i][5] * inv, hi[2], lo[2]);
        split_pair(o[i][6] * inv, o[i][7] * inv, hi[3], lo[3]);
        int off = row * 128 + ((h ^ r7) << 4);
        *(uint4*)(Ohi + off) = make_uint4(hi[0], hi[1], hi[2], hi[3]);
        *(uint4*)(Olo + off) = make_uint4(lo[0], lo[1], lo[2], lo[3]);
    }
}

// ---------------------------------------------------------------------------
// Fused kernel: one CTA per (batch, 4-node tile); 2 CTAs/SM, 24 warps/SM.
// W fetches are cp.async, overlapped with the previous stage via dead-region
// bounce buffers (KF/VF heads) or directly into the W slot when it is dead.
// ---------------------------------------------------------------------------
__global__ void __launch_bounds__(NTHREADS, 2)
temporal_attention_mma(const float* __restrict__ X,
                       const float* __restrict__ bq, const float* __restrict__ bk,
                       const float* __restrict__ bv, const float* __restrict__ bf1,
                       const float* __restrict__ bf2,
                       float* __restrict__ Y) {
    extern __shared__ char smem[];
    char* Xhi = smem + XHI_OFF;
    char* Xlo = smem + XLO_OFF;

    const int tid = threadIdx.x;
    const int n0blk = blockIdx.x * NB;
    const int b = blockIdx.y;

    const uint32_t xhiU = smem_u32(Xhi);
    const uint32_t xloU = smem_u32(Xlo);
    const uint32_t whiU = smem_u32(smem + WHI_OFF);
    const uint32_t wloU = smem_u32(smem + WLO_OFF);
    const uint32_t hhiU = smem_u32(smem + HHI_OFF);
    const uint32_t hloU = smem_u32(smem + HLO_OFF);
    const uint32_t kfU  = smem_u32(smem + KF_OFF);
    const uint32_t vfU  = smem_u32(smem + VF_OFF);

    // Wq -> W slot directly (nothing reads it yet); overlaps X staging.
    fetch_W(whiU, 0, tid);

    // Stage X as bf16 hi/lo (zero-fill out-of-range nodes).
#pragma unroll
    for (int p = 0; p < 2; ++p) {
        int idx = tid + p * NTHREADS;      // 768 tasks: row(96) x group(8)
        int row = idx >> 3, g = idx & 7;
        int node = row / TT, t = row - node * TT;
        int n = n0blk + node;
        float4 f0 = make_float4(0.f, 0.f, 0.f, 0.f);
        float4 f1 = make_float4(0.f, 0.f, 0.f, 0.f);
        if (n < NN) {
            const float* src = X + ((size_t)(b * TT + t) * NN + n) * DD + g * 8;
            f0 = *(const float4*)(src);
            f1 = *(const float4*)(src + 4);
        }
        uint32_t h0, l0, h1, l1, h2, l2, h3, l3;
        split_pair(f0.x, f0.y, h0, l0);
        split_pair(f0.z, f0.w, h1, l1);
        split_pair(f1.x, f1.y, h2, l2);
        split_pair(f1.z, f1.w, h3, l3);
        int off = row * 128 + ((g ^ (row & 7)) << 4);
        *(uint4*)(Xhi + off) = make_uint4(h0, h1, h2, h3);
        *(uint4*)(Xlo + off) = make_uint4(l0, l1, l2, l3);
    }
    wait_cp();
    __syncthreads();

    // Q GEMM; Wk streams into KF bounce meanwhile.
    fetch_W(kfU, 1, tid);
    gemm_mma<0>(xhiU, xloU, whiU, wloU, bq, smem + QF_OFF,
                nullptr, nullptr, nullptr, 0, 0, tid);
    wait_cp();
    __syncthreads();
    copy_16k(smem + WHI_OFF, smem + KF_OFF, tid);
    __syncthreads();

    // K GEMM; Wv streams into VF bounce meanwhile.
    fetch_W(vfU, 2, tid);
    gemm_mma<0>(xhiU, xloU, whiU, wloU, bk, smem + KF_OFF,
                nullptr, nullptr, nullptr, 0, 0, tid);
    wait_cp();
    __syncthreads();
    copy_16k(smem + WHI_OFF, smem + VF_OFF, tid);
    __syncthreads();

    // V GEMM.
    gemm_mma<0>(xhiU, xloU, whiU, wloU, bv, smem + VF_OFF,
                nullptr, nullptr, nullptr, 0, 0, tid);
    __syncthreads();

    // Attention; Wf1 streams directly into the (dead) W slot meanwhile.
    fetch_W(whiU, 3, tid);
    attention(smem + QF_OFF, smem + KF_OFF, smem + VF_OFF, Xhi, Xlo, tid);
    wait_cp();
    __syncthreads();

    // FC1 GEMM; Wf2 streams into VF bounce (V is dead) meanwhile.
    fetch_W(vfU, 4, tid);
    gemm_mma<1>(xhiU, xloU, whiU, wloU, bf1, nullptr,
                smem + HHI_OFF, smem + HLO_OFF, nullptr, 0, 0, tid);
    wait_cp();
    __syncthreads();
    copy_16k(smem + WHI_OFF, smem + VF_OFF, tid);
    __syncthreads();

    // FC2 GEMM -> global.
    gemm_mma<2>(hhiU, hloU, whiU, wloU, bf2, nullptr,
                nullptr, nullptr, Y, b, n0blk, tid);
}

// ---------------------------------------------------------------------------
// kernel_launch: inputs per metadata order:
// 0=X 1=STE(unused) 2=Wq 3=bq 4=Wk 5=bk 6=Wv 7=bv 8=Wf1 9=bf1 10=Wf2 11=bf2
// ---------------------------------------------------------------------------
extern "C" void kernel_launch(void* const* d_in, const int* in_sizes, int n_in,
                              void* d_out, int out_size) {
    const float* X   = (const float*)d_in[0];
    const float* Wq  = (const float*)d_in[2];
    const float* bq  = (const float*)d_in[3];
    const float* Wk  = (const float*)d_in[4];
    const float* bk  = (const float*)d_in[5];
    const float* Wv  = (const float*)d_in[6];
    const float* bv  = (const float*)d_in[7];
    const float* Wf1 = (const float*)d_in[8];
    const float* bf1 = (const float*)d_in[9];
    const float* Wf2 = (const float*)d_in[10];
    const float* bf2 = (const float*)d_in[11];
    float* Y = (float*)d_out;

    prep_weights<<<5, 512>>>(Wq, Wk, Wv, Wf1, Wf2);

    cudaFuncSetAttribute(temporal_attention_mma,
                         cudaFuncAttributeMaxDynamicSharedMemorySize, SMEM_BYTES);
    dim3 grid(NTILES, BB);
    temporal_attention_mma<<<grid, NTHREADS, SMEM_BYTES>>>(
        X, bq, bk, bv, bf1, bf2, Y);
}

// round 12
// speedup vs baseline: 1.8439x; 1.0416x over previous
#include <cuda_runtime.h>
#include <cuda_bf16.h>
#include <cstdint>

// Problem constants
#define BB 32
#define TT 24
#define NN 325
#define DD 64

#define NB 4                  // nodes per CTA
#define MROWS 96              // NB * TT
#define NTILES 82
#define NTHREADS 256          // 8 warps: 2 m-groups (48 rows) x 4 n-groups (16)

// smem byte offsets (total 114688 -> 2 CTAs/SM)
#define XHI_OFF 0             // X hi bf16 [96][64] (later O hi)
#define XLO_OFF 12288         // X lo (later O lo)
#define QF_OFF  24576         // Q fp32 [96][64]  (later H hi/lo)
#define HHI_OFF 24576
#define HLO_OFF 36864
#define KF_OFF  49152         // K fp32 (head 16K doubles as W bounce)
#define VF_OFF  73728         // V fp32 (head 16K doubles as W bounce)
#define WHI_OFF 98304         // W hi bf16 [64][64] k-major (pre-split)
#define WLO_OFF 106496
#define SMEM_BYTES 114688

// Pre-split weights: [w][0..8192) = hi plane, [8192..16384) = lo plane,
// already in the swizzled smem layout (row k: 128B; chunk g at g^(k&7)).
__device__ __align__(16) unsigned char g_wsplit[5][16384];

// ---------------------------------------------------------------------------
// PTX helpers
// ---------------------------------------------------------------------------
__device__ __forceinline__ uint32_t smem_u32(const void* p) {
    return (uint32_t)__cvta_generic_to_shared(p);
}
__device__ __forceinline__ void ldsm4(uint32_t addr, uint32_t& r0, uint32_t& r1,
                                      uint32_t& r2, uint32_t& r3) {
    asm volatile("ldmatrix.sync.aligned.m8n8.x4.shared.b16 {%0,%1,%2,%3}, [%4];"
                 : "=r"(r0), "=r"(r1), "=r"(r2), "=r"(r3) : "r"(addr));
}
__device__ __forceinline__ void ldsm4t(uint32_t addr, uint32_t& r0, uint32_t& r1,
                                       uint32_t& r2, uint32_t& r3) {
    asm volatile("ldmatrix.sync.aligned.m8n8.x4.trans.shared.b16 {%0,%1,%2,%3}, [%4];"
                 : "=r"(r0), "=r"(r1), "=r"(r2), "=r"(r3) : "r"(addr));
}
#define MMA(ac, A0, A1, A2, A3, B0, B1)                                        \
    asm volatile(                                                              \
        "mma.sync.aligned.m16n8k16.row.col.f32.bf16.bf16.f32 "                 \
        "{%0,%1,%2,%3}, {%4,%5,%6,%7}, {%8,%9}, {%0,%1,%2,%3};"                \
        : "+f"((ac)[0]), "+f"((ac)[1]), "+f"((ac)[2]), "+f"((ac)[3])           \
        : "r"(A0), "r"(A1), "r"(A2), "r"(A3), "r"(B0), "r"(B1))

__device__ __forceinline__ float ex2f(float x) {
    float y;
    asm("ex2.approx.f32 %0, %1;" : "=f"(y) : "f"(x));
    return y;
}

// Split fp32 pair into bf16 hi pair + bf16 residual pair (packed b32 each).
__device__ __forceinline__ void split_pair(float a, float b,
                                           uint32_t& hi, uint32_t& lo) {
    __nv_bfloat16 ah = __float2bfloat16_rn(a);
    __nv_bfloat16 bh = __float2bfloat16_rn(b);
    __nv_bfloat16 al = __float2bfloat16_rn(a - __bfloat162float(ah));
    __nv_bfloat16 bl = __float2bfloat16_rn(b - __bfloat162float(bh));
    __nv_bfloat162 H = __halves2bfloat162(ah, bh);
    __nv_bfloat162 L = __halves2bfloat162(al, bl);
    hi = *reinterpret_cast<uint32_t*>(&H);
    lo = *reinterpret_cast<uint32_t*>(&L);
}

// ---------------------------------------------------------------------------
// Prep kernel: split each 64x64 fp32 weight into bf16 hi/lo planes in the
// final swizzled layout, once for all main-kernel CTAs.
// ---------------------------------------------------------------------------
__global__ void prep_weights(const float* __restrict__ Wq,
                             const float* __restrict__ Wk,
                             const float* __restrict__ Wv,
                             const float* __restrict__ Wf1,
                             const float* __restrict__ Wf2) {
    const float* Ws[5] = {Wq, Wk, Wv, Wf1, Wf2};
    const float* W = Ws[blockIdx.x];
    unsigned char* hi = g_wsplit[blockIdx.x];
    unsigned char* lo = g_wsplit[blockIdx.x] + 8192;
    int tid = threadIdx.x;                 // 512 threads: k(64) x g(8)
    int k = tid >> 3, g = tid & 7;
    const float* src = W + k * 64 + g * 8;
    float4 f0 = *(const float4*)(src);
    float4 f1 = *(const float4*)(src + 4);
    uint32_t h0, l0, h1, l1, h2, l2, h3, l3;
    split_pair(f0.x, f0.y, h0, l0);
    split_pair(f0.z, f0.w, h1, l1);
    split_pair(f1.x, f1.y, h2, l2);
    split_pair(f1.z, f1.w, h3, l3);
    int off = k * 128 + ((g ^ (k & 7)) << 4);
    *(uint4*)(hi + off) = make_uint4(h0, h1, h2, h3);
    *(uint4*)(lo + off) = make_uint4(l0, l1, l2, l3);
}

// ---------------------------------------------------------------------------
// cp.async fetch of one pre-split W (16KB) into an smem region + bounce copy.
// ---------------------------------------------------------------------------
__device__ __forceinline__ void fetch_W(uint32_t dstU, int widx, int tid) {
#pragma unroll
    for (int i = 0; i < 4; ++i) {
        int idx = tid + i * NTHREADS;      // 1024 x 16B
        asm volatile("cp.async.ca.shared.global [%0], [%1], 16;"
                     :: "r"(dstU + idx * 16),
                        "l"(g_wsplit[widx] + idx * 16));
    }
    asm volatile("cp.async.commit_group;" ::: "memory");
}
__device__ __forceinline__ void wait_cp() {
    asm volatile("cp.async.wait_group 0;" ::: "memory");
}
__device__ __forceinline__ void copy_16k(char* __restrict__ dst,
                                         const char* __restrict__ src, int tid) {
#pragma unroll
    for (int i = 0; i < 4; ++i) {
        int idx = tid + i * NTHREADS;
        *(uint4*)(dst + idx * 16) = *(const uint4*)(src + idx * 16);
    }
}

// ---------------------------------------------------------------------------
// Tensor-core GEMM: C[96x64] = A[96x64] @ W[64x64], 3-term bf16 split.
// A: bf16 hi/lo [m][k] (128B rows, chunk^=(m&7)); W: bf16 hi/lo [k][n].
// 8 warps: warp w -> m-group (w&1)*48 (3 m16 tiles), n-group (w>>1)*16.
// Per k-step: 6 A ldsm4 + 2 W ldsm4t, then 18 MMAs issued term-major so
// same-accumulator reuse distance is 6 (deep ILP for the tensor pipe).
// MODE 0: fp32 smem out (+bias,+relu)  MODE 1: bf16 hi/lo out (+bias,+relu)
// MODE 2: global fp32 out (+bias)
// ---------------------------------------------------------------------------
template <int MODE>
__device__ __forceinline__ void gemm_mma(
    uint32_t aHi, uint32_t aLo, uint32_t wHi, uint32_t wLo,
    const float* __restrict__ bias,
    char* __restrict__ outF,
    char* __restrict__ outHi, char* __restrict__ outLo,
    float* __restrict__ Y, int b, int n0blk, int tid) {
    const int wid = tid >> 5, lane = tid & 31;
    const int m0 = (wid & 1) * 48;
    const int n0 = (wid >> 1) * 16;
    const int i7 = lane & 7;
    const int h8 = (lane >> 3) & 1;
    const int kh = (lane >> 4) & 1;

    const int rowA = m0 + i7 + h8 * 8;      // m0, m0+16, m0+32 all 8-aligned
    const uint32_t aHiB = aHi + rowA * 128;
    const uint32_t aLoB = aLo + rowA * 128;
    const int rowB = i7 + h8 * 8;
    const uint32_t cB = (uint32_t)(((n0 >> 3) + kh) ^ i7) << 4;
    const uint32_t wHiB = wHi + rowB * 128 + cB;
    const uint32_t wLoB = wLo + rowB * 128 + cB;

    float acc[3][2][4];
#pragma unroll
    for (int mi = 0; mi < 3; ++mi)
#pragma unroll
        for (int nj = 0; nj < 2; ++nj)
#pragma unroll
            for (int x = 0; x < 4; ++x) acc[mi][nj][x] = 0.0f;

#pragma unroll
    for (int ks = 0; ks < 4; ++ks) {
        const uint32_t cA = (uint32_t)(((2 * ks) + kh) ^ i7) << 4;
        const uint32_t wk = (uint32_t)(ks * 2048);
        uint32_t ah[3][4], al[3][4], bh[4], bl[4];
        ldsm4t(wHiB + wk, bh[0], bh[1], bh[2], bh[3]);
        ldsm4t(wLoB + wk, bl[0], bl[1], bl[2], bl[3]);
#pragma unroll
        for (int mi = 0; mi < 3; ++mi) {
            ldsm4(aHiB + mi * 2048 + cA, ah[mi][0], ah[mi][1], ah[mi][2], ah[mi][3]);
            ldsm4(aLoB + mi * 2048 + cA, al[mi][0], al[mi][1], al[mi][2], al[mi][3]);
        }
        // term 1: Ah @ Wh
#pragma unroll
        for (int mi = 0; mi < 3; ++mi) {
            MMA(acc[mi][0], ah[mi][0], ah[mi][1], ah[mi][2], ah[mi][3], bh[0], bh[1]);
            MMA(acc[mi][1], ah[mi][0], ah[mi][1], ah[mi][2], ah[mi][3], bh[2], bh[3]);
        }
        // term 2: Ah @ Wl
#pragma unroll
        for (int mi = 0; mi < 3; ++mi) {
            MMA(acc[mi][0], ah[mi][0], ah[mi][1], ah[mi][2], ah[mi][3], bl[0], bl[1]);
            MMA(acc[mi][1], ah[mi][0], ah[mi][1], ah[mi][2], ah[mi][3], bl[2], bl[3]);
        }
        // term 3: Al @ Wh
#pragma unroll
        for (int mi = 0; mi < 3; ++mi) {
            MMA(acc[mi][0], al[mi][0], al[mi][1], al[mi][2], al[mi][3], bh[0], bh[1]);
            MMA(acc[mi][1], al[mi][0], al[mi][1], al[mi][2], al[mi][3], bh[2], bh[3]);
        }
    }

    const int g = lane >> 2;
    const int c2 = (lane & 3) * 2;
#pragma unroll
    for (int mi = 0; mi < 3; ++mi) {
#pragma unroll
        for (int nj = 0; nj < 2; ++nj) {
            const int cc = n0 + 8 * nj + c2;
            float2 bv = *(const float2*)(bias + cc);
            float v00 = acc[mi][nj][0] + bv.x, v01 = acc[mi][nj][1] + bv.y;
            float v10 = acc[mi][nj][2] + bv.x, v11 = acc[mi][nj][3] + bv.y;
            const int r1 = m0 + mi * 16 + g, r2 = r1 + 8;
            if (MODE == 0) {
                v00 = fmaxf(v00, 0.f); v01 = fmaxf(v01, 0.f);
                v10 = fmaxf(v10, 0.f); v11 = fmaxf(v11, 0.f);
                const int coff = (((cc >> 2) ^ g) << 4) + (cc & 3) * 4;
                *(float2*)(outF + r1 * 256 + coff) = make_float2(v00, v01);
                *(float2*)(outF + r2 * 256 + coff) = make_float2(v10, v11);
            } else if (MODE == 1) {
                v00 = fmaxf(v00, 0.f); v01 = fmaxf(v01, 0.f);
                v10 = fmaxf(v10, 0.f); v11 = fmaxf(v11, 0.f);
                uint32_t hi1, lo1, hi2, lo2;
                split_pair(v00, v01, hi1, lo1);
                split_pair(v10, v11, hi2, lo2);
                const int coff = (((cc >> 3) ^ g) << 4) + (cc & 7) * 2;
                *(uint32_t*)(outHi + r1 * 128 + coff) = hi1;
                *(uint32_t*)(outLo + r1 * 128 + coff) = lo1;
                *(uint32_t*)(outHi + r2 * 128 + coff) = hi2;
                *(uint32_t*)(outLo + r2 * 128 + coff) = lo2;
            } else {
                int node1 = r1 / TT, t1 = r1 - node1 * TT, n1 = n0blk + node1;
                if (n1 < NN)
                    *(float2*)(Y + ((size_t)(b * TT + t1) * NN + n1) * DD + cc) =
                        make_float2(v00, v01);
                int node2 = r2 / TT, t2 = r2 - node2 * TT, n2 = n0blk + node2;
                if (n2 < NN)
                    *(float2*)(Y + ((size_t)(b * TT + t2) * NN + n2) * DD + cc) =
                        make_float2(v10, v11);
            }
        }
    }
}

// ---------------------------------------------------------------------------
// Attention: one thread per (node, head, t-triple): 4*8*8 = 256 tasks.
// Q/K/V fp32 buffers (256B rows, 16B chunk c at c^(row&7)).
// Scale folds 1/sqrt(d)*log2(e); exp via raw ex2.approx; no max-subtraction.
// Writes O as bf16 hi/lo (A operand of FC1).
// ---------------------------------------------------------------------------
__device__ __forceinline__ void attention(const char* __restrict__ Qf,
                                          const char* __restrict__ Kf,
                                          const char* __restrict__ Vf,
                                          char* __restrict__ Ohi,
                                          char* __restrict__ Olo, int tid) {
    const float scale = 0.5100697176f;   // (1/sqrt(8)) * log2(e)
    const int node = tid >> 6;
    const int h = (tid >> 3) & 7;
    const int tg = tid & 7;
    const int tbase = tg * 3;
    const int rbase = node * TT;         // multiple of 24 -> (rbase & 7) == 0
    const int ch = 2 * h;

    float q[3][8], o[3][8], sum[3];
#pragma unroll
    for (int i = 0; i < 3; ++i) {
        int r7 = (tbase + i) & 7;
        const char* qr = Qf + (rbase + tbase + i) * 256;
        float4 a = *(const float4*)(qr + ((ch ^ r7) << 4));
        float4 c = *(const float4*)(qr + (((ch + 1) ^ r7) << 4));
        q[i][0] = a.x * scale; q[i][1] = a.y * scale;
        q[i][2] = a.z * scale; q[i][3] = a.w * scale;
        q[i][4] = c.x * scale; q[i][5] = c.y * scale;
        q[i][6] = c.z * scale; q[i][7] = c.w * scale;
        sum[i] = 0.0f;
#pragma unroll
        for (int j = 0; j < 8; ++j) o[i][j] = 0.0f;
    }

#pragma unroll
    for (int a8 = 0; a8 < 3; ++a8) {
#pragma unroll
        for (int e = 0; e < 8; ++e) {      // s & 7 == e (compile-time)
            int s = 8 * a8 + e;
            const char* kr = Kf + (rbase + s) * 256;
            const char* vr = Vf + (rbase + s) * 256;
            const int c1 = ((ch ^ e) << 4), c2v = (((ch + 1) ^ e) << 4);
            float4 k0 = *(const float4*)(kr + c1);
            float4 k1 = *(const float4*)(kr + c2v);
            float4 v0 = *(const float4*)(vr + c1);
            float4 v1 = *(const float4*)(vr + c2v);
#pragma unroll
            for (int i = 0; i < 3; ++i) {
                float dot = q[i][0] * k0.x;
                dot = fmaf(q[i][1], k0.y, dot);
                dot = fmaf(q[i][2], k0.z, dot);
                dot = fmaf(q[i][3], k0.w, dot);
                dot = fmaf(q[i][4], k1.x, dot);
                dot = fmaf(q[i][5], k1.y, dot);
                dot = fmaf(q[i][6], k1.z, dot);
                dot = fmaf(q[i][7], k1.w, dot);
                float e2 = (s >= tbase + i) ? ex2f(dot) : 0.0f;
                sum[i] += e2;
                o[i][0] = fmaf(e2, v0.x, o[i][0]);
                o[i][1] = fmaf(e2, v0.y, o[i][1]);
                o[i][2] = fmaf(e2, v0.z, o[i][2]);
                o[i][3] = fmaf(e2, v0.w, o[i][3]);
                o[i][4] = fmaf(e2, v1.x, o[i][4]);
                o[i][5] = fmaf(e2, v1.y, o[i][5]);
                o[i][6] = fmaf(e2, v1.z, o[i][6]);
                o[i][7] = fmaf(e2, v1.w, o[i][7]);
            }
        }
    }

#pragma unroll
    for (int i = 0; i < 3; ++i) {
        float inv = 1.0f / sum[i];
        int row = rbase + tbase + i;
        int r7 = (tbase + i) & 7;
        uint32_t hi[4], lo[4];
        split_pair(o[i][0] * inv, o[i][1] * inv, hi[0], lo[0]);
        split_pair(o[i][2] * inv, o[i][3] * inv, hi[1], lo[1]);
        split_pair(o[i][4] * inv, o[i][5] * inv, hi[2], lo[2]);
        split_pair(o[i][6] * inv, o[i][7] * inv, hi[3], lo[3]);
        int off = row * 128 + ((h ^ r7) << 4);
        *(uint4*)(Ohi + off) = make_uint4(hi[0], hi[1], hi[2], hi[3]);
        *(uint4*)(Olo + off) = make_uint4(lo[0], lo[1], lo[2], lo[3]);
    }
}

// ---------------------------------------------------------------------------
// Fused kernel: one CTA per (batch, 4-node tile); 2 CTAs/SM, 16 warps/SM,
// 128-reg budget so ptxas can pipeline ldsm/mma.
// ---------------------------------------------------------------------------
__global__ void __launch_bounds__(NTHREADS, 2)
temporal_attention_mma(const float* __restrict__ X,
                       const float* __restrict__ bq, const float* __restrict__ bk,
                       const float* __restrict__ bv, const float* __restrict__ bf1,
                       const float* __restrict__ bf2,
                       float* __restrict__ Y) {
    extern __shared__ char smem[];
    char* Xhi = smem + XHI_OFF;
    char* Xlo = smem + XLO_OFF;

    const int tid = threadIdx.x;
    const int n0blk = blockIdx.x * NB;
    const int b = blockIdx.y;

    const uint32_t xhiU = smem_u32(Xhi);
    const uint32_t xloU = smem_u32(Xlo);
    const uint32_t whiU = smem_u32(smem + WHI_OFF);
    const uint32_t wloU = smem_u32(smem + WLO_OFF);
    const uint32_t hhiU = smem_u32(smem + HHI_OFF);
    const uint32_t hloU = smem_u32(smem + HLO_OFF);
    const uint32_t kfU  = smem_u32(smem + KF_OFF);
    const uint32_t vfU  = smem_u32(smem + VF_OFF);

    // Wq -> W slot directly (nothing reads it yet); overlaps X staging.
    fetch_W(whiU, 0, tid);

    // Stage X as bf16 hi/lo (zero-fill out-of-range nodes).
#pragma unroll
    for (int p = 0; p < 3; ++p) {
        int idx = tid + p * NTHREADS;      // 768 tasks: row(96) x group(8)
        int row = idx >> 3, g = idx & 7;
        int node = row / TT, t = row - node * TT;
        int n = n0blk + node;
        float4 f0 = make_float4(0.f, 0.f, 0.f, 0.f);
        float4 f1 = make_float4(0.f, 0.f, 0.f, 0.f);
        if (n < NN) {
            const float* src = X + ((size_t)(b * TT + t) * NN + n) * DD + g * 8;
            f0 = *(const float4*)(src);
            f1 = *(const float4*)(src + 4);
        }
        uint32_t h0, l0, h1, l1, h2, l2, h3, l3;
        split_pair(f0.x, f0.y, h0, l0);
        split_pair(f0.z, f0.w, h1, l1);
        split_pair(f1.x, f1.y, h2, l2);
        split_pair(f1.z, f1.w, h3, l3);
        int off = row * 128 + ((g ^ (row & 7)) << 4);
        *(uint4*)(Xhi + off) = make_uint4(h0, h1, h2, h3);
        *(uint4*)(Xlo + off) = make_uint4(l0, l1, l2, l3);
    }
    wait_cp();
    __syncthreads();

    // Q GEMM; Wk streams into KF bounce meanwhile.
    fetch_W(kfU, 1, tid);
    gemm_mma<0>(xhiU, xloU, whiU, wloU, bq, smem + QF_OFF,
                nullptr, nullptr, nullptr, 0, 0, tid);
    wait_cp();
    __syncthreads();
    copy_16k(smem + WHI_OFF, smem + KF_OFF, tid);
    __syncthreads();

    // K GEMM; Wv streams into VF bounce meanwhile.
    fetch_W(vfU, 2, tid);
    gemm_mma<0>(xhiU, xloU, whiU, wloU, bk, smem + KF_OFF,
                nullptr, nullptr, nullptr, 0, 0, tid);
    wait_cp();
    __syncthreads();
    copy_16k(smem + WHI_OFF, smem + VF_OFF, tid);
    __syncthreads();

    // V GEMM.
    gemm_mma<0>(xhiU, xloU, whiU, wloU, bv, smem + VF_OFF,
                nullptr, nullptr, nullptr, 0, 0, tid);
    __syncthreads();

    // Attention; Wf1 streams directly into the (dead) W slot meanwhile.
    fetch_W(whiU, 3, tid);
    attention(smem + QF_OFF, smem + KF_OFF, smem + VF_OFF, Xhi, Xlo, tid);
    wait_cp();
    __syncthreads();

    // FC1 GEMM; Wf2 streams into VF bounce (V is dead) meanwhile.
    fetch_W(vfU, 4, tid);
    gemm_mma<1>(xhiU, xloU, whiU, wloU, bf1, nullptr,
                smem + HHI_OFF, smem + HLO_OFF, nullptr, 0, 0, tid);
    wait_cp();
    __syncthreads();
    copy_16k(smem + WHI_OFF, smem + VF_OFF, tid);
    __syncthreads();

    // FC2 GEMM -> global.
    gemm_mma<2>(hhiU, hloU, whiU, wloU, bf2, nullptr,
                nullptr, nullptr, Y, b, n0blk, tid);
}

// ---------------------------------------------------------------------------
// kernel_launch: inputs per metadata order:
// 0=X 1=STE(unused) 2=Wq 3=bq 4=Wk 5=bk 6=Wv 7=bv 8=Wf1 9=bf1 10=Wf2 11=bf2
// ---------------------------------------------------------------------------
extern "C" void kernel_launch(void* const* d_in, const int* in_sizes, int n_in,
                              void* d_out, int out_size) {
    const float* X   = (const float*)d_in[0];
    const float* Wq  = (const float*)d_in[2];
    const float* bq  = (const float*)d_in[3];
    const float* Wk  = (const float*)d_in[4];
    const float* bk  = (const float*)d_in[5];
    const float* Wv  = (const float*)d_in[6];
    const float* bv  = (const float*)d_in[7];
    const float* Wf1 = (const float*)d_in[8];
    const float* bf1 = (const float*)d_in[9];
    const float* Wf2 = (const float*)d_in[10];
    const float* bf2 = (const float*)d_in[11];
    float* Y = (float*)d_out;

    prep_weights<<<5, 512>>>(Wq, Wk, Wv, Wf1, Wf2);

    cudaFuncSetAttribute(temporal_attention_mma,
                         cudaFuncAttributeMaxDynamicSharedMemorySize, SMEM_BYTES);
    dim3 grid(NTILES, BB);
    temporal_attention_mma<<<grid, NTHREADS, SMEM_BYTES>>>(
        X, bq, bk, bv, bf1, bf2, Y);
}

// round 13
// speedup vs baseline: 1.9284x; 1.0459x over previous
#include <cuda_runtime.h>
#include <cuda_bf16.h>
#include <cstdint>

// Problem constants
#define BB 32
#define TT 24
#define NN 325
#define DD 64

#define NB 4                  // nodes per CTA
#define MROWS 96              // NB * TT
#define NTILES 82
#define NTHREADS 256          // 8 warps: 2 m-groups (48 rows) x 4 n-groups (16)

// smem regions (total 114688 -> 2 CTAs/SM). W slabs live inside P2/P3/P4
// at different times; see lifetime table in the kernel.
#define P0_OFF 0              // X hi/lo bf16 (12K+12K); later O hi/lo
#define P1_OFF 24576          // Q fp32 24K; later H hi/lo (12K+12K)
#define P2_OFF 49152          // Wk slab (16K), then V fp32 (24K)
#define P3_OFF 73728          // K fp32 (24K); later Wf2 slab (16K)
#define P4_OFF 98304          // Wq -> Wv -> Wf1 slab (16K)
#define SMEM_BYTES 114688

// Pre-split weights: [w][0..8192) = hi plane, [8192..16384) = lo plane,
// already in the swizzled smem layout (row k: 128B; chunk g at g^(k&7)).
__device__ __align__(16) unsigned char g_wsplit[5][16384];

// ---------------------------------------------------------------------------
// PTX helpers
// ---------------------------------------------------------------------------
__device__ __forceinline__ uint32_t smem_u32(const void* p) {
    return (uint32_t)__cvta_generic_to_shared(p);
}
__device__ __forceinline__ void ldsm4(uint32_t addr, uint32_t& r0, uint32_t& r1,
                                      uint32_t& r2, uint32_t& r3) {
    asm volatile("ldmatrix.sync.aligned.m8n8.x4.shared.b16 {%0,%1,%2,%3}, [%4];"
                 : "=r"(r0), "=r"(r1), "=r"(r2), "=r"(r3) : "r"(addr));
}
__device__ __forceinline__ void ldsm4t(uint32_t addr, uint32_t& r0, uint32_t& r1,
                                       uint32_t& r2, uint32_t& r3) {
    asm volatile("ldmatrix.sync.aligned.m8n8.x4.trans.shared.b16 {%0,%1,%2,%3}, [%4];"
                 : "=r"(r0), "=r"(r1), "=r"(r2), "=r"(r3) : "r"(addr));
}
#define MMA(ac, A0, A1, A2, A3, B0, B1)                                        \
    asm volatile(                                                              \
        "mma.sync.aligned.m16n8k16.row.col.f32.bf16.bf16.f32 "                 \
        "{%0,%1,%2,%3}, {%4,%5,%6,%7}, {%8,%9}, {%0,%1,%2,%3};"                \
        : "+f"((ac)[0]), "+f"((ac)[1]), "+f"((ac)[2]), "+f"((ac)[3])           \
        : "r"(A0), "r"(A1), "r"(A2), "r"(A3), "r"(B0), "r"(B1))

__device__ __forceinline__ float ex2f(float x) {
    float y;
    asm("ex2.approx.f32 %0, %1;" : "=f"(y) : "f"(x));
    return y;
}

// Split fp32 pair into bf16 hi pair + bf16 residual pair (packed b32 each).
__device__ __forceinline__ void split_pair(float a, float b,
                                           uint32_t& hi, uint32_t& lo) {
    __nv_bfloat16 ah = __float2bfloat16_rn(a);
    __nv_bfloat16 bh = __float2bfloat16_rn(b);
    __nv_bfloat16 al = __float2bfloat16_rn(a - __bfloat162float(ah));
    __nv_bfloat16 bl = __float2bfloat16_rn(b - __bfloat162float(bh));
    __nv_bfloat162 H = __halves2bfloat162(ah, bh);
    __nv_bfloat162 L = __halves2bfloat162(al, bl);
    hi = *reinterpret_cast<uint32_t*>(&H);
    lo = *reinterpret_cast<uint32_t*>(&L);
}

// ---------------------------------------------------------------------------
// Prep kernel: split each 64x64 fp32 weight into bf16 hi/lo planes in the
// final swizzled layout, once for all main-kernel CTAs.
// ---------------------------------------------------------------------------
__global__ void prep_weights(const float* __restrict__ Wq,
                             const float* __restrict__ Wk,
                             const float* __restrict__ Wv,
                             const float* __restrict__ Wf1,
                             const float* __restrict__ Wf2) {
    const float* Ws[5] = {Wq, Wk, Wv, Wf1, Wf2};
    const float* W = Ws[blockIdx.x];
    unsigned char* hi = g_wsplit[blockIdx.x];
    unsigned char* lo = g_wsplit[blockIdx.x] + 8192;
    int tid = threadIdx.x;                 // 512 threads: k(64) x g(8)
    int k = tid >> 3, g = tid & 7;
    const float* src = W + k * 64 + g * 8;
    float4 f0 = *(const float4*)(src);
    float4 f1 = *(const float4*)(src + 4);
    uint32_t h0, l0, h1, l1, h2, l2, h3, l3;
    split_pair(f0.x, f0.y, h0, l0);
    split_pair(f0.z, f0.w, h1, l1);
    split_pair(f1.x, f1.y, h2, l2);
    split_pair(f1.z, f1.w, h3, l3);
    int off = k * 128 + ((g ^ (k & 7)) << 4);
    *(uint4*)(hi + off) = make_uint4(h0, h1, h2, h3);
    *(uint4*)(lo + off) = make_uint4(l0, l1, l2, l3);
}

// ---------------------------------------------------------------------------
// cp.async fetch of one pre-split W (16KB) into an smem slab.
// ---------------------------------------------------------------------------
__device__ __forceinline__ void fetch_W(uint32_t dstU, int widx, int tid) {
#pragma unroll
    for (int i = 0; i < 4; ++i) {
        int idx = tid + i * NTHREADS;      // 1024 x 16B
        asm volatile("cp.async.ca.shared.global [%0], [%1], 16;"
                     :: "r"(dstU + idx * 16),
                        "l"(g_wsplit[widx] + idx * 16));
    }
    asm volatile("cp.async.commit_group;" ::: "memory");
}
__device__ __forceinline__ void wait_cp() {
    asm volatile("cp.async.wait_group 0;" ::: "memory");
}

// ---------------------------------------------------------------------------
// Tensor-core GEMM: C[96x64] = A[96x64] @ W[64x64], 3-term bf16 split.
// A: bf16 hi/lo [m][k] (128B rows, chunk^=(m&7)); W: bf16 hi/lo [k][n].
// 8 warps: warp w -> m-group (w&1)*48 (3 m16 tiles), n-group (w>>1)*16.
// Per k-step: 6 A ldsm4 + 2 W ldsm4t, then 18 MMAs issued term-major so
// same-accumulator reuse distance is 6 (deep ILP for the tensor pipe).
// MODE 0: fp32 smem out (+bias,+relu)  MODE 1: bf16 hi/lo out (+bias,+relu)
// MODE 2: global fp32 out (+bias)
// ---------------------------------------------------------------------------
template <int MODE>
__device__ __forceinline__ void gemm_mma(
    uint32_t aHi, uint32_t aLo, uint32_t wHi, uint32_t wLo,
    const float* __restrict__ bias,
    char* __restrict__ outF,
    char* __restrict__ outHi, char* __restrict__ outLo,
    float* __restrict__ Y, int b, int n0blk, int tid) {
    const int wid = tid >> 5, lane = tid & 31;
    const int m0 = (wid & 1) * 48;
    const int n0 = (wid >> 1) * 16;
    const int i7 = lane & 7;
    const int h8 = (lane >> 3) & 1;
    const int kh = (lane >> 4) & 1;

    const int rowA = m0 + i7 + h8 * 8;      // m0, m0+16, m0+32 all 8-aligned
    const uint32_t aHiB = aHi + rowA * 128;
    const uint32_t aLoB = aLo + rowA * 128;
    const int rowB = i7 + h8 * 8;
    const uint32_t cB = (uint32_t)(((n0 >> 3) + kh) ^ i7) << 4;
    const uint32_t wHiB = wHi + rowB * 128 + cB;
    const uint32_t wLoB = wLo + rowB * 128 + cB;

    float acc[3][2][4];
#pragma unroll
    for (int mi = 0; mi < 3; ++mi)
#pragma unroll
        for (int nj = 0; nj < 2; ++nj)
#pragma unroll
            for (int x = 0; x < 4; ++x) acc[mi][nj][x] = 0.0f;

#pragma unroll
    for (int ks = 0; ks < 4; ++ks) {
        const uint32_t cA = (uint32_t)(((2 * ks) + kh) ^ i7) << 4;
        const uint32_t wk = (uint32_t)(ks * 2048);
        uint32_t ah[3][4], al[3][4], bh[4], bl[4];
        ldsm4t(wHiB + wk, bh[0], bh[1], bh[2], bh[3]);
        ldsm4t(wLoB + wk, bl[0], bl[1], bl[2], bl[3]);
#pragma unroll
        for (int mi = 0; mi < 3; ++mi) {
            ldsm4(aHiB + mi * 2048 + cA, ah[mi][0], ah[mi][1], ah[mi][2], ah[mi][3]);
            ldsm4(aLoB + mi * 2048 + cA, al[mi][0], al[mi][1], al[mi][2], al[mi][3]);
        }
        // term 1: Ah @ Wh
#pragma unroll
        for (int mi = 0; mi < 3; ++mi) {
            MMA(acc[mi][0], ah[mi][0], ah[mi][1], ah[mi][2], ah[mi][3], bh[0], bh[1]);
            MMA(acc[mi][1], ah[mi][0], ah[mi][1], ah[mi][2], ah[mi][3], bh[2], bh[3]);
        }
        // term 2: Ah @ Wl
#pragma unroll
        for (int mi = 0; mi < 3; ++mi) {
            MMA(acc[mi][0], ah[mi][0], ah[mi][1], ah[mi][2], ah[mi][3], bl[0], bl[1]);
            MMA(acc[mi][1], ah[mi][0], ah[mi][1], ah[mi][2], ah[mi][3], bl[2], bl[3]);
        }
        // term 3: Al @ Wh
#pragma unroll
        for (int mi = 0; mi < 3; ++mi) {
            MMA(acc[mi][0], al[mi][0], al[mi][1], al[mi][2], al[mi][3], bh[0], bh[1]);
            MMA(acc[mi][1], al[mi][0], al[mi][1], al[mi][2], al[mi][3], bh[2], bh[3]);
        }
    }

    const int g = lane >> 2;
    const int c2 = (lane & 3) * 2;
#pragma unroll
    for (int mi = 0; mi < 3; ++mi) {
#pragma unroll
        for (int nj = 0; nj < 2; ++nj) {
            const int cc = n0 + 8 * nj + c2;
            float2 bv = *(const float2*)(bias + cc);
            float v00 = acc[mi][nj][0] + bv.x, v01 = acc[mi][nj][1] + bv.y;
            float v10 = acc[mi][nj][2] + bv.x, v11 = acc[mi][nj][3] + bv.y;
            const int r1 = m0 + mi * 16 + g, r2 = r1 + 8;
            if (MODE == 0) {
                v00 = fmaxf(v00, 0.f); v01 = fmaxf(v01, 0.f);
                v10 = fmaxf(v10, 0.f); v11 = fmaxf(v11, 0.f);
                const int coff = (((cc >> 2) ^ g) << 4) + (cc & 3) * 4;
                *(float2*)(outF + r1 * 256 + coff) = make_float2(v00, v01);
                *(float2*)(outF + r2 * 256 + coff) = make_float2(v10, v11);
            } else if (MODE == 1) {
                v00 = fmaxf(v00, 0.f); v01 = fmaxf(v01, 0.f);
                v10 = fmaxf(v10, 0.f); v11 = fmaxf(v11, 0.f);
                uint32_t hi1, lo1, hi2, lo2;
                split_pair(v00, v01, hi1, lo1);
                split_pair(v10, v11, hi2, lo2);
                const int coff = (((cc >> 3) ^ g) << 4) + (cc & 7) * 2;
                *(uint32_t*)(outHi + r1 * 128 + coff) = hi1;
                *(uint32_t*)(outLo + r1 * 128 + coff) = lo1;
                *(uint32_t*)(outHi + r2 * 128 + coff) = hi2;
                *(uint32_t*)(outLo + r2 * 128 + coff) = lo2;
            } else {
                int node1 = r1 / TT, t1 = r1 - node1 * TT, n1 = n0blk + node1;
                if (n1 < NN)
                    *(float2*)(Y + ((size_t)(b * TT + t1) * NN + n1) * DD + cc) =
                        make_float2(v00, v01);
                int node2 = r2 / TT, t2 = r2 - node2 * TT, n2 = n0blk + node2;
                if (n2 < NN)
                    *(float2*)(Y + ((size_t)(b * TT + t2) * NN + n2) * DD + cc) =
                        make_float2(v10, v11);
            }
        }
    }
}

// ---------------------------------------------------------------------------
// Attention: one thread per (node, head, t-triple): 4*8*8 = 256 tasks.
// Q/K/V fp32 buffers (256B rows, 16B chunk c at c^(row&7)).
// Scale folds 1/sqrt(d)*log2(e); exp via raw ex2.approx; no max-subtraction.
// Writes O as bf16 hi/lo (A operand of FC1).
// ---------------------------------------------------------------------------
__device__ __forceinline__ void attention(const char* __restrict__ Qf,
                                          const char* __restrict__ Kf,
                                          const char* __restrict__ Vf,
                                          char* __restrict__ Ohi,
                                          char* __restrict__ Olo, int tid) {
    const float scale = 0.5100697176f;   // (1/sqrt(8)) * log2(e)
    const int node = tid >> 6;
    const int h = (tid >> 3) & 7;
    const int tg = tid & 7;
    const int tbase = tg * 3;
    const int rbase = node * TT;         // multiple of 24 -> (rbase & 7) == 0
    const int ch = 2 * h;

    float q[3][8], o[3][8], sum[3];
#pragma unroll
    for (int i = 0; i < 3; ++i) {
        int r7 = (tbase + i) & 7;
        const char* qr = Qf + (rbase + tbase + i) * 256;
        float4 a = *(const float4*)(qr + ((ch ^ r7) << 4));
        float4 c = *(const float4*)(qr + (((ch + 1) ^ r7) << 4));
        q[i][0] = a.x * scale; q[i][1] = a.y * scale;
        q[i][2] = a.z * scale; q[i][3] = a.w * scale;
        q[i][4] = c.x * scale; q[i][5] = c.y * scale;
        q[i][6] = c.z * scale; q[i][7] = c.w * scale;
        sum[i] = 0.0f;
#pragma unroll
        for (int j = 0; j < 8; ++j) o[i][j] = 0.0f;
    }

#pragma unroll
    for (int a8 = 0; a8 < 3; ++a8) {
#pragma unroll
        for (int e = 0; e < 8; ++e) {      // s & 7 == e (compile-time)
            int s = 8 * a8 + e;
            const char* kr = Kf + (rbase + s) * 256;
            const char* vr = Vf + (rbase + s) * 256;
            const int c1 = ((ch ^ e) << 4), c2v = (((ch + 1) ^ e) << 4);
            float4 k0 = *(const float4*)(kr + c1);
            float4 k1 = *(const float4*)(kr + c2v);
            float4 v0 = *(const float4*)(vr + c1);
            float4 v1 = *(const float4*)(vr + c2v);
#pragma unroll
            for (int i = 0; i < 3; ++i) {
                float dot = q[i][0] * k0.x;
                dot = fmaf(q[i][1], k0.y, dot);
                dot = fmaf(q[i][2], k0.z, dot);
                dot = fmaf(q[i][3], k0.w, dot);
                dot = fmaf(q[i][4], k1.x, dot);
                dot = fmaf(q[i][5], k1.y, dot);
                dot = fmaf(q[i][6], k1.z, dot);
                dot = fmaf(q[i][7], k1.w, dot);
                float e2 = (s >= tbase + i) ? ex2f(dot) : 0.0f;
                sum[i] += e2;
                o[i][0] = fmaf(e2, v0.x, o[i][0]);
                o[i][1] = fmaf(e2, v0.y, o[i][1]);
                o[i][2] = fmaf(e2, v0.z, o[i][2]);
                o[i][3] = fmaf(e2, v0.w, o[i][3]);
                o[i][4] = fmaf(e2, v1.x, o[i][4]);
                o[i][5] = fmaf(e2, v1.y, o[i][5]);
                o[i][6] = fmaf(e2, v1.z, o[i][6]);
                o[i][7] = fmaf(e2, v1.w, o[i][7]);
            }
        }
    }

#pragma unroll
    for (int i = 0; i < 3; ++i) {
        float inv = 1.0f / sum[i];
        int row = rbase + tbase + i;
        int r7 = (tbase + i) & 7;
        uint32_t hi[4], lo[4];
        split_pair(o[i][0] * inv, o[i][1] * inv, hi[0], lo[0]);
        split_pair(o[i][2] * inv, o[i][3] * inv, hi[1], lo[1]);
        split_pair(o[i][4] * inv, o[i][5] * inv, hi[2], lo[2]);
        split_pair(o[i][6] * inv, o[i][7] * inv, hi[3], lo[3]);
        int off = row * 128 + ((h ^ r7) << 4);
        *(uint4*)(Ohi + off) = make_uint4(hi[0], hi[1], hi[2], hi[3]);
        *(uint4*)(Olo + off) = make_uint4(lo[0], lo[1], lo[2], lo[3]);
    }
}

// ---------------------------------------------------------------------------
// Fused kernel: one CTA per (batch, 4-node tile); 2 CTAs/SM.
// W slabs rotate through dead regions (no smem-to-smem copies, 6 barriers):
//   stage X            | cp Wq -> P4
//   Q = X@Wq   (P4)->P1| cp Wk -> P2
//   K = X@Wk   (P2)->P3| cp Wv -> P4
//   V = X@Wv   (P4)->P2|
//   attention  -> P0   | cp Wf1 -> P4
//   H = O@Wf1  (P4)->P1| cp Wf2 -> P3
//   Y = H@Wf2  (P3)    |
// ---------------------------------------------------------------------------
__global__ void __launch_bounds__(NTHREADS, 2)
temporal_attention_mma(const float* __restrict__ X,
                       const float* __restrict__ bq, const float* __restrict__ bk,
                       const float* __restrict__ bv, const float* __restrict__ bf1,
                       const float* __restrict__ bf2,
                       float* __restrict__ Y) {
    extern __shared__ char smem[];
    char* Xhi = smem + P0_OFF;             // 12K hi + 12K lo
    char* Xlo = smem + P0_OFF + 12288;

    const int tid = threadIdx.x;
    const int n0blk = blockIdx.x * NB;
    const int b = blockIdx.y;

    const uint32_t xhiU = smem_u32(Xhi);
    const uint32_t xloU = smem_u32(Xlo);
    const uint32_t p2U = smem_u32(smem + P2_OFF);
    const uint32_t p3U = smem_u32(smem + P3_OFF);
    const uint32_t p4U = smem_u32(smem + P4_OFF);
    const uint32_t hhiU = smem_u32(smem + P1_OFF);
    const uint32_t hloU = smem_u32(smem + P1_OFF + 12288);

    // Wq -> P4 (nothing reads it yet); overlaps X staging.
    fetch_W(p4U, 0, tid);

    // Stage X as bf16 hi/lo (zero-fill out-of-range nodes).
#pragma unroll
    for (int p = 0; p < 3; ++p) {
        int idx = tid + p * NTHREADS;      // 768 tasks: row(96) x group(8)
        int row = idx >> 3, g = idx & 7;
        int node = row / TT, t = row - node * TT;
        int n = n0blk + node;
        float4 f0 = make_float4(0.f, 0.f, 0.f, 0.f);
        float4 f1 = make_float4(0.f, 0.f, 0.f, 0.f);
        if (n < NN) {
            const float* src = X + ((size_t)(b * TT + t) * NN + n) * DD + g * 8;
            f0 = *(const float4*)(src);
            f1 = *(const float4*)(src + 4);
        }
        uint32_t h0, l0, h1, l1, h2, l2, h3, l3;
        split_pair(f0.x, f0.y, h0, l0);
        split_pair(f0.z, f0.w, h1, l1);
        split_pair(f1.x, f1.y, h2, l2);
        split_pair(f1.z, f1.w, h3, l3);
        int off = row * 128 + ((g ^ (row & 7)) << 4);
        *(uint4*)(Xhi + off) = make_uint4(h0, h1, h2, h3);
        *(uint4*)(Xlo + off) = make_uint4(l0, l1, l2, l3);
    }
    wait_cp();
    __syncthreads();

    // Q GEMM (W in P4 -> Q in P1); Wk streams into P2.
    fetch_W(p2U, 1, tid);
    gemm_mma<0>(xhiU, xloU, p4U, p4U + 8192, bq, smem + P1_OFF,
                nullptr, nullptr, nullptr, 0, 0, tid);
    wait_cp();
    __syncthreads();

    // K GEMM (W in P2 -> K in P3); Wv streams into P4 (Wq dead).
    fetch_W(p4U, 2, tid);
    gemm_mma<0>(xhiU, xloU, p2U, p2U + 8192, bk, smem + P3_OFF,
                nullptr, nullptr, nullptr, 0, 0, tid);
    wait_cp();
    __syncthreads();

    // V GEMM (W in P4 -> V in P2, Wk dead).
    gemm_mma<0>(xhiU, xloU, p4U, p4U + 8192, bv, smem + P2_OFF,
                nullptr, nullptr, nullptr, 0, 0, tid);
    __syncthreads();

    // Attention (Q=P1, K=P3, V=P2 -> O over P0); Wf1 streams into P4 (Wv dead).
    fetch_W(p4U, 3, tid);
    attention(smem + P1_OFF, smem + P3_OFF, smem + P2_OFF, Xhi, Xlo, tid);
    wait_cp();
    __syncthreads();

    // FC1 GEMM (O@Wf1 -> H hi/lo in P1, Q dead); Wf2 streams into P3 (K dead).
    fetch_W(p3U, 4, tid);
    gemm_mma<1>(xhiU, xloU, p4U, p4U + 8192, bf1, nullptr,
                smem + P1_OFF, smem + P1_OFF + 12288, nullptr, 0, 0, tid);
    wait_cp();
    __syncthreads();

    // FC2 GEMM (H@Wf2 -> Y).
    gemm_mma<2>(hhiU, hloU, p3U, p3U + 8192, bf2, nullptr,
                nullptr, nullptr, Y, b, n0blk, tid);
}

// ---------------------------------------------------------------------------
// kernel_launch: inputs per metadata order:
// 0=X 1=STE(unused) 2=Wq 3=bq 4=Wk 5=bk 6=Wv 7=bv 8=Wf1 9=bf1 10=Wf2 11=bf2
// ---------------------------------------------------------------------------
extern "C" void kernel_launch(void* const* d_in, const int* in_sizes, int n_in,
                              void* d_out, int out_size) {
    const float* X   = (const float*)d_in[0];
    const float* Wq  = (const float*)d_in[2];
    const float* bq  = (const float*)d_in[3];
    const float* Wk  = (const float*)d_in[4];
    const float* bk  = (const float*)d_in[5];
    const float* Wv  = (const float*)d_in[6];
    const float* bv  = (const float*)d_in[7];
    const float* Wf1 = (const float*)d_in[8];
    const float* bf1 = (const float*)d_in[9];
    const float* Wf2 = (const float*)d_in[10];
    const float* bf2 = (const float*)d_in[11];
    float* Y = (float*)d_out;

    prep_weights<<<5, 512>>>(Wq, Wk, Wv, Wf1, Wf2);

    cudaFuncSetAttribute(temporal_attention_mma,
                         cudaFuncAttributeMaxDynamicSharedMemorySize, SMEM_BYTES);
    dim3 grid(NTILES, BB);
    temporal_attention_mma<<<grid, NTHREADS, SMEM_BYTES>>>(
        X, bq, bk, bv, bf1, bf2, Y);
}

// round 14
// speedup vs baseline: 2.1162x; 1.0974x over previous
#include <cuda_runtime.h>
#include <cuda_bf16.h>
#include <cstdint>

// Problem constants
#define BB 32
#define TT 24
#define NN 325
#define DD 64

#define NB 4                  // nodes per CTA
#define MROWS 96              // NB * TT
#define NTILES 82
#define NTHREADS 256          // 8 warps: 2 m-groups (48 rows) x 4 n-groups (16)

// smem regions (total 114688 -> 2 CTAs/SM)
//   X_OFF: X hi/lo bf16 (12K+12K); later O hi/lo (attention out)
//   Q_OFF: Q bf16-hi (12K); later H hi (FC1 out)
//   K_OFF: K bf16-hi (12K); later H lo
//   S0..S3: four 16K W slabs; V fp32 (24K) lands over S0+S1 after Wq/Wk die.
#define X_OFF 0
#define Q_OFF 24576
#define K_OFF 36864
#define S0_OFF 49152
#define S1_OFF 65536
#define S2_OFF 81920
#define S3_OFF 98304
#define SMEM_BYTES 114688

// Pre-split weights: [w][0..8192) hi plane, [8192..16384) lo plane,
// in the swizzled smem layout (row k: 128B; chunk g at g^(k&7)).
__device__ __align__(16) unsigned char g_wsplit[5][16384];

typedef unsigned long long ull;

// ---------------------------------------------------------------------------
// PTX helpers
// ---------------------------------------------------------------------------
__device__ __forceinline__ uint32_t smem_u32(const void* p) {
    return (uint32_t)__cvta_generic_to_shared(p);
}
__device__ __forceinline__ void ldsm4(uint32_t addr, uint32_t& r0, uint32_t& r1,
                                      uint32_t& r2, uint32_t& r3) {
    asm volatile("ldmatrix.sync.aligned.m8n8.x4.shared.b16 {%0,%1,%2,%3}, [%4];"
                 : "=r"(r0), "=r"(r1), "=r"(r2), "=r"(r3) : "r"(addr));
}
__device__ __forceinline__ void ldsm4t(uint32_t addr, uint32_t& r0, uint32_t& r1,
                                       uint32_t& r2, uint32_t& r3) {
    asm volatile("ldmatrix.sync.aligned.m8n8.x4.trans.shared.b16 {%0,%1,%2,%3}, [%4];"
                 : "=r"(r0), "=r"(r1), "=r"(r2), "=r"(r3) : "r"(addr));
}
#define MMA(ac, A0, A1, A2, A3, B0, B1)                                        \
    asm volatile(                                                              \
        "mma.sync.aligned.m16n8k16.row.col.f32.bf16.bf16.f32 "                 \
        "{%0,%1,%2,%3}, {%4,%5,%6,%7}, {%8,%9}, {%0,%1,%2,%3};"                \
        : "+f"((ac)[0]), "+f"((ac)[1]), "+f"((ac)[2]), "+f"((ac)[3])           \
        : "r"(A0), "r"(A1), "r"(A2), "r"(A3), "r"(B0), "r"(B1))

__device__ __forceinline__ float ex2f(float x) {
    float y;
    asm("ex2.approx.f32 %0, %1;" : "=f"(y) : "f"(x));
    return y;
}
__device__ __forceinline__ ull ffma2(ull a, ull b, ull c) {
    ull d;
    asm("fma.rn.f32x2 %0, %1, %2, %3;" : "=l"(d) : "l"(a), "l"(b), "l"(c));
    return d;
}
__device__ __forceinline__ ull mul2(ull a, ull b) {
    ull d;
    asm("mul.rn.f32x2 %0, %1, %2;" : "=l"(d) : "l"(a), "l"(b));
    return d;
}
__device__ __forceinline__ float2 unpack2(ull v) {
    float2 r;
    asm("mov.b64 {%0, %1}, %2;" : "=f"(r.x), "=f"(r.y) : "l"(v));
    return r;
}
__device__ __forceinline__ ull pack2s(float x) {
    ull r;
    asm("mov.b64 %0, {%1, %1};" : "=l"(r) : "f"(x));
    return r;
}
// bf16x2 word -> f32x2 ull ({even elem, odd elem}); bf16->f32 is a 16-bit shift.
__device__ __forceinline__ ull bf2f(uint32_t p) {
    uint32_t lo = p << 16;
    uint32_t hi = p & 0xFFFF0000u;
    ull r;
    asm("mov.b64 %0, {%1, %2};" : "=l"(r) : "r"(lo), "r"(hi));
    return r;
}

// Split fp32 pair into bf16 hi pair + bf16 residual pair (packed b32 each).
__device__ __forceinline__ void split_pair(float a, float b,
                                           uint32_t& hi, uint32_t& lo) {
    __nv_bfloat16 ah = __float2bfloat16_rn(a);
    __nv_bfloat16 bh = __float2bfloat16_rn(b);
    __nv_bfloat16 al = __float2bfloat16_rn(a - __bfloat162float(ah));
    __nv_bfloat16 bl = __float2bfloat16_rn(b - __bfloat162float(bh));
    __nv_bfloat162 H = __halves2bfloat162(ah, bh);
    __nv_bfloat162 L = __halves2bfloat162(al, bl);
    hi = *reinterpret_cast<uint32_t*>(&H);
    lo = *reinterpret_cast<uint32_t*>(&L);
}
__device__ __forceinline__ uint32_t bf16x2_of(float a, float b) {
    __nv_bfloat162 H = __halves2bfloat162(__float2bfloat16_rn(a),
                                          __float2bfloat16_rn(b));
    return *reinterpret_cast<uint32_t*>(&H);
}

// ---------------------------------------------------------------------------
// Prep kernel: split each 64x64 fp32 weight into bf16 hi/lo planes in the
// final swizzled layout, once for all main-kernel CTAs.
// ---------------------------------------------------------------------------
__global__ void prep_weights(const float* __restrict__ Wq,
                             const float* __restrict__ Wk,
                             const float* __restrict__ Wv,
                             const float* __restrict__ Wf1,
                             const float* __restrict__ Wf2) {
    const float* Ws[5] = {Wq, Wk, Wv, Wf1, Wf2};
    const float* W = Ws[blockIdx.x];
    unsigned char* hi = g_wsplit[blockIdx.x];
    unsigned char* lo = g_wsplit[blockIdx.x] + 8192;
    int tid = threadIdx.x;                 // 512 threads: k(64) x g(8)
    int k = tid >> 3, g = tid & 7;
    const float* src = W + k * 64 + g * 8;
    float4 f0 = *(const float4*)(src);
    float4 f1 = *(const float4*)(src + 4);
    uint32_t h0, l0, h1, l1, h2, l2, h3, l3;
    split_pair(f0.x, f0.y, h0, l0);
    split_pair(f0.z, f0.w, h1, l1);
    split_pair(f1.x, f1.y, h2, l2);
    split_pair(f1.z, f1.w, h3, l3);
    int off = k * 128 + ((g ^ (k & 7)) << 4);
    *(uint4*)(hi + off) = make_uint4(h0, h1, h2, h3);
    *(uint4*)(lo + off) = make_uint4(l0, l1, l2, l3);
}

// ---------------------------------------------------------------------------
// cp.async fetch of one pre-split W (16KB) into an smem slab.
// ---------------------------------------------------------------------------
__device__ __forceinline__ void fetch_W(uint32_t dstU, int widx, int tid) {
#pragma unroll
    for (int i = 0; i < 4; ++i) {
        int idx = tid + i * NTHREADS;      // 1024 x 16B
        asm volatile("cp.async.ca.shared.global [%0], [%1], 16;"
                     :: "r"(dstU + idx * 16),
                        "l"(g_wsplit[widx] + idx * 16));
    }
    asm volatile("cp.async.commit_group;" ::: "memory");
}
__device__ __forceinline__ void wait_cp() {
    asm volatile("cp.async.wait_group 0;" ::: "memory");
}

// ---------------------------------------------------------------------------
// Fused Q+K tensor-core GEMM: shares A fragments across both weights.
// A: bf16 hi/lo [96][64]; Wq/Wk: bf16 hi/lo [k][n] slabs.
// Outputs Q and K as bf16-hi only (128B rows, chunk c at c^(row&7)) + ReLU.
// ---------------------------------------------------------------------------
__device__ __forceinline__ void gemm_qk(
    uint32_t aHi, uint32_t aLo,
    uint32_t wqHi, uint32_t wqLo, uint32_t wkHi, uint32_t wkLo,
    const float* __restrict__ bq, const float* __restrict__ bk,
    char* __restrict__ outQ, char* __restrict__ outK, int tid) {
    const int wid = tid >> 5, lane = tid & 31;
    const int m0 = (wid & 1) * 48;
    const int n0 = (wid >> 1) * 16;
    const int i7 = lane & 7;
    const int h8 = (lane >> 3) & 1;
    const int kh = (lane >> 4) & 1;

    const int rowA = m0 + i7 + h8 * 8;
    const uint32_t aHiB = aHi + rowA * 128;
    const uint32_t aLoB = aLo + rowA * 128;
    const int rowB = i7 + h8 * 8;
    const uint32_t cB = (uint32_t)(((n0 >> 3) + kh) ^ i7) << 4;
    const uint32_t wqHiB = wqHi + rowB * 128 + cB;
    const uint32_t wqLoB = wqLo + rowB * 128 + cB;
    const uint32_t wkHiB = wkHi + rowB * 128 + cB;
    const uint32_t wkLoB = wkLo + rowB * 128 + cB;

    float accq[3][2][4], acck[3][2][4];
#pragma unroll
    for (int mi = 0; mi < 3; ++mi)
#pragma unroll
        for (int nj = 0; nj < 2; ++nj)
#pragma unroll
            for (int x = 0; x < 4; ++x) { accq[mi][nj][x] = 0.0f; acck[mi][nj][x] = 0.0f; }

#pragma unroll
    for (int ks = 0; ks < 4; ++ks) {
        const uint32_t cA = (uint32_t)(((2 * ks) + kh) ^ i7) << 4;
        const uint32_t wk = (uint32_t)(ks * 2048);
        uint32_t ah[3][4], al[3][4], bh[4], bl[4];
#pragma unroll
        for (int mi = 0; mi < 3; ++mi) {
            ldsm4(aHiB + mi * 2048 + cA, ah[mi][0], ah[mi][1], ah[mi][2], ah[mi][3]);
            ldsm4(aLoB + mi * 2048 + cA, al[mi][0], al[mi][1], al[mi][2], al[mi][3]);
        }
        // ---- Wq ----
        ldsm4t(wqHiB + wk, bh[0], bh[1], bh[2], bh[3]);
        ldsm4t(wqLoB + wk, bl[0], bl[1], bl[2], bl[3]);
#pragma unroll
        for (int mi = 0; mi < 3; ++mi) {
            MMA(accq[mi][0], ah[mi][0], ah[mi][1], ah[mi][2], ah[mi][3], bh[0], bh[1]);
            MMA(accq[mi][1], ah[mi][0], ah[mi][1], ah[mi][2], ah[mi][3], bh[2], bh[3]);
        }
#pragma unroll
        for (int mi = 0; mi < 3; ++mi) {
            MMA(accq[mi][0], ah[mi][0], ah[mi][1], ah[mi][2], ah[mi][3], bl[0], bl[1]);
            MMA(accq[mi][1], ah[mi][0], ah[mi][1], ah[mi][2], ah[mi][3], bl[2], bl[3]);
        }
#pragma unroll
        for (int mi = 0; mi < 3; ++mi) {
            MMA(accq[mi][0], al[mi][0], al[mi][1], al[mi][2], al[mi][3], bh[0], bh[1]);
            MMA(accq[mi][1], al[mi][0], al[mi][1], al[mi][2], al[mi][3], bh[2], bh[3]);
        }
        // ---- Wk ----
        ldsm4t(wkHiB + wk, bh[0], bh[1], bh[2], bh[3]);
        ldsm4t(wkLoB + wk, bl[0], bl[1], bl[2], bl[3]);
#pragma unroll
        for (int mi = 0; mi < 3; ++mi) {
            MMA(acck[mi][0], ah[mi][0], ah[mi][1], ah[mi][2], ah[mi][3], bh[0], bh[1]);
            MMA(acck[mi][1], ah[mi][0], ah[mi][1], ah[mi][2], ah[mi][3], bh[2], bh[3]);
        }
#pragma unroll
        for (int mi = 0; mi < 3; ++mi) {
            MMA(acck[mi][0], ah[mi][0], ah[mi][1], ah[mi][2], ah[mi][3], bl[0], bl[1]);
            MMA(acck[mi][1], ah[mi][0], ah[mi][1], ah[mi][2], ah[mi][3], bl[2], bl[3]);
        }
#pragma unroll
        for (int mi = 0; mi < 3; ++mi) {
            MMA(acck[mi][0], al[mi][0], al[mi][1], al[mi][2], al[mi][3], bh[0], bh[1]);
            MMA(acck[mi][1], al[mi][0], al[mi][1], al[mi][2], al[mi][3], bh[2], bh[3]);
        }
    }

    const int g = lane >> 2;
    const int c2 = (lane & 3) * 2;
#pragma unroll
    for (int mi = 0; mi < 3; ++mi) {
#pragma unroll
        for (int nj = 0; nj < 2; ++nj) {
            const int cc = n0 + 8 * nj + c2;
            const int r1 = m0 + mi * 16 + g, r2 = r1 + 8;
            const int coff = (((cc >> 3) ^ g) << 4) + (cc & 7) * 2;
            float2 bvq = *(const float2*)(bq + cc);
            float2 bvk = *(const float2*)(bk + cc);
            // Q
            {
                float v00 = fmaxf(accq[mi][nj][0] + bvq.x, 0.f);
                float v01 = fmaxf(accq[mi][nj][1] + bvq.y, 0.f);
                float v10 = fmaxf(accq[mi][nj][2] + bvq.x, 0.f);
                float v11 = fmaxf(accq[mi][nj][3] + bvq.y, 0.f);
                *(uint32_t*)(outQ + r1 * 128 + coff) = bf16x2_of(v00, v01);
                *(uint32_t*)(outQ + r2 * 128 + coff) = bf16x2_of(v10, v11);
            }
            // K
            {
                float v00 = fmaxf(acck[mi][nj][0] + bvk.x, 0.f);
                float v01 = fmaxf(acck[mi][nj][1] + bvk.y, 0.f);
                float v10 = fmaxf(acck[mi][nj][2] + bvk.x, 0.f);
                float v11 = fmaxf(acck[mi][nj][3] + bvk.y, 0.f);
                *(uint32_t*)(outK + r1 * 128 + coff) = bf16x2_of(v00, v01);
                *(uint32_t*)(outK + r2 * 128 + coff) = bf16x2_of(v10, v11);
            }
        }
    }
}

// ---------------------------------------------------------------------------
// Single tensor-core GEMM (V / FC1 / FC2), 3-term bf16 split.
// MODE 0: fp32 smem out (+bias,+relu)  MODE 1: bf16 hi/lo out (+bias,+relu)
// MODE 2: global fp32 out (+bias)
// ---------------------------------------------------------------------------
template <int MODE>
__device__ __forceinline__ void gemm_mma(
    uint32_t aHi, uint32_t aLo, uint32_t wHi, uint32_t wLo,
    const float* __restrict__ bias,
    char* __restrict__ outF,
    char* __restrict__ outHi, char* __restrict__ outLo,
    float* __restrict__ Y, int b, int n0blk, int tid) {
    const int wid = tid >> 5, lane = tid & 31;
    const int m0 = (wid & 1) * 48;
    const int n0 = (wid >> 1) * 16;
    const int i7 = lane & 7;
    const int h8 = (lane >> 3) & 1;
    const int kh = (lane >> 4) & 1;

    const int rowA = m0 + i7 + h8 * 8;
    const uint32_t aHiB = aHi + rowA * 128;
    const uint32_t aLoB = aLo + rowA * 128;
    const int rowB = i7 + h8 * 8;
    const uint32_t cB = (uint32_t)(((n0 >> 3) + kh) ^ i7) << 4;
    const uint32_t wHiB = wHi + rowB * 128 + cB;
    const uint32_t wLoB = wLo + rowB * 128 + cB;

    float acc[3][2][4];
#pragma unroll
    for (int mi = 0; mi < 3; ++mi)
#pragma unroll
        for (int nj = 0; nj < 2; ++nj)
#pragma unroll
            for (int x = 0; x < 4; ++x) acc[mi][nj][x] = 0.0f;

#pragma unroll
    for (int ks = 0; ks < 4; ++ks) {
        const uint32_t cA = (uint32_t)(((2 * ks) + kh) ^ i7) << 4;
        const uint32_t wk = (uint32_t)(ks * 2048);
        uint32_t ah[3][4], al[3][4], bh[4], bl[4];
        ldsm4t(wHiB + wk, bh[0], bh[1], bh[2], bh[3]);
        ldsm4t(wLoB + wk, bl[0], bl[1], bl[2], bl[3]);
#pragma unroll
        for (int mi = 0; mi < 3; ++mi) {
            ldsm4(aHiB + mi * 2048 + cA, ah[mi][0], ah[mi][1], ah[mi][2], ah[mi][3]);
            ldsm4(aLoB + mi * 2048 + cA, al[mi][0], al[mi][1], al[mi][2], al[mi][3]);
        }
#pragma unroll
        for (int mi = 0; mi < 3; ++mi) {
            MMA(acc[mi][0], ah[mi][0], ah[mi][1], ah[mi][2], ah[mi][3], bh[0], bh[1]);
            MMA(acc[mi][1], ah[mi][0], ah[mi][1], ah[mi][2], ah[mi][3], bh[2], bh[3]);
        }
#pragma unroll
        for (int mi = 0; mi < 3; ++mi) {
            MMA(acc[mi][0], ah[mi][0], ah[mi][1], ah[mi][2], ah[mi][3], bl[0], bl[1]);
            MMA(acc[mi][1], ah[mi][0], ah[mi][1], ah[mi][2], ah[mi][3], bl[2], bl[3]);
        }
#pragma unroll
        for (int mi = 0; mi < 3; ++mi) {
            MMA(acc[mi][0], al[mi][0], al[mi][1], al[mi][2], al[mi][3], bh[0], bh[1]);
            MMA(acc[mi][1], al[mi][0], al[mi][1], al[mi][2], al[mi][3], bh[2], bh[3]);
        }
    }

    const int g = lane >> 2;
    const int c2 = (lane & 3) * 2;
#pragma unroll
    for (int mi = 0; mi < 3; ++mi) {
#pragma unroll
        for (int nj = 0; nj < 2; ++nj) {
            const int cc = n0 + 8 * nj + c2;
            float2 bv = *(const float2*)(bias + cc);
            float v00 = acc[mi][nj][0] + bv.x, v01 = acc[mi][nj][1] + bv.y;
            float v10 = acc[mi][nj][2] + bv.x, v11 = acc[mi][nj][3] + bv.y;
            const int r1 = m0 + mi * 16 + g, r2 = r1 + 8;
            if (MODE == 0) {
                v00 = fmaxf(v00, 0.f); v01 = fmaxf(v01, 0.f);
                v10 = fmaxf(v10, 0.f); v11 = fmaxf(v11, 0.f);
                const int coff = (((cc >> 2) ^ g) << 4) + (cc & 3) * 4;
                *(float2*)(outF + r1 * 256 + coff) = make_float2(v00, v01);
                *(float2*)(outF + r2 * 256 + coff) = make_float2(v10, v11);
            } else if (MODE == 1) {
                v00 = fmaxf(v00, 0.f); v01 = fmaxf(v01, 0.f);
                v10 = fmaxf(v10, 0.f); v11 = fmaxf(v11, 0.f);
                uint32_t hi1, lo1, hi2, lo2;
                split_pair(v00, v01, hi1, lo1);
                split_pair(v10, v11, hi2, lo2);
                const int coff = (((cc >> 3) ^ g) << 4) + (cc & 7) * 2;
                *(uint32_t*)(outHi + r1 * 128 + coff) = hi1;
                *(uint32_t*)(outLo + r1 * 128 + coff) = lo1;
                *(uint32_t*)(outHi + r2 * 128 + coff) = hi2;
                *(uint32_t*)(outLo + r2 * 128 + coff) = lo2;
            } else {
                int node1 = r1 / TT, t1 = r1 - node1 * TT, n1 = n0blk + node1;
                if (n1 < NN)
                    *(float2*)(Y + ((size_t)(b * TT + t1) * NN + n1) * DD + cc) =
                        make_float2(v00, v01);
                int node2 = r2 / TT, t2 = r2 - node2 * TT, n2 = n0blk + node2;
                if (n2 < NN)
                    *(float2*)(Y + ((size_t)(b * TT + t2) * NN + n2) * DD + cc) =
                        make_float2(v10, v11);
            }
        }
    }
}

// ---------------------------------------------------------------------------
// Attention: one thread per (node, head, t-triple): 4*8*8 = 256 tasks.
// Q/K: bf16-hi (128B rows, chunk h at h^(row&7)).  V: fp32 (256B rows).
// Packed f32x2 math for dot + output accumulation; ex2.approx; no max-sub.
// Writes O as bf16 hi/lo (A operand of FC1) over the X region.
// ---------------------------------------------------------------------------
__device__ __forceinline__ void attention(const char* __restrict__ Qb,
                                          const char* __restrict__ Kb,
                                          const char* __restrict__ Vf,
                                          char* __restrict__ Ohi,
                                          char* __restrict__ Olo, int tid) {
    const float scale = 0.5100697176f;   // (1/sqrt(8)) * log2(e)
    const ull scale2 = pack2s(scale);
    const int node = tid >> 6;
    const int h = (tid >> 3) & 7;
    const int tg = tid & 7;
    const int tbase = tg * 3;
    const int rbase = node * TT;         // multiple of 24 -> (rbase & 7) == 0
    const int ch = 2 * h;                // V chunk base

    ull q2[3][4], o2[3][4];
    float sum[3];
#pragma unroll
    for (int i = 0; i < 3; ++i) {
        int r7 = (tbase + i) & 7;
        uint4 qr = *(const uint4*)(Qb + (rbase + tbase + i) * 128 + ((h ^ r7) << 4));
        q2[i][0] = mul2(bf2f(qr.x), scale2);
        q2[i][1] = mul2(bf2f(qr.y), scale2);
        q2[i][2] = mul2(bf2f(qr.z), scale2);
        q2[i][3] = mul2(bf2f(qr.w), scale2);
        sum[i] = 0.0f;
#pragma unroll
        for (int j = 0; j < 4; ++j) o2[i][j] = 0ull;
    }

#pragma unroll
    for (int a8 = 0; a8 < 3; ++a8) {
#pragma unroll
        for (int e = 0; e < 8; ++e) {      // s & 7 == e (compile-time)
            int s = 8 * a8 + e;
            uint4 kr = *(const uint4*)(Kb + (rbase + s) * 128 + ((h ^ e) << 4));
            ull k2[4];
            k2[0] = bf2f(kr.x); k2[1] = bf2f(kr.y);
            k2[2] = bf2f(kr.z); k2[3] = bf2f(kr.w);
            const char* vr = Vf + (rbase + s) * 256;
            ulonglong2 va = *(const ulonglong2*)(vr + ((ch ^ e) << 4));
            ulonglong2 vb = *(const ulonglong2*)(vr + (((ch + 1) ^ e) << 4));
#pragma unroll
            for (int i = 0; i < 3; ++i) {
                ull d2 = mul2(q2[i][0], k2[0]);
                d2 = ffma2(q2[i][1], k2[1], d2);
                d2 = ffma2(q2[i][2], k2[2], d2);
                d2 = ffma2(q2[i][3], k2[3], d2);
                float2 dd = unpack2(d2);
                float dot = dd.x + dd.y;
                float e2 = (s >= tbase + i) ? ex2f(dot) : 0.0f;
                sum[i] += e2;
                ull ep = pack2s(e2);
                o2[i][0] = ffma2(ep, va.x, o2[i][0]);
                o2[i][1] = ffma2(ep, va.y, o2[i][1]);
                o2[i][2] = ffma2(ep, vb.x, o2[i][2]);
                o2[i][3] = ffma2(ep, vb.y, o2[i][3]);
            }
        }
    }

#pragma unroll
    for (int i = 0; i < 3; ++i) {
        float inv = 1.0f / sum[i];
        int row = rbase + tbase + i;
        int r7 = (tbase + i) & 7;
        uint32_t hi[4], lo[4];
#pragma unroll
        for (int j = 0; j < 4; ++j) {
            float2 p = unpack2(o2[i][j]);
            split_pair(p.x * inv, p.y * inv, hi[j], lo[j]);
        }
        int off = row * 128 + ((h ^ r7) << 4);
        *(uint4*)(Ohi + off) = make_uint4(hi[0], hi[1], hi[2], hi[3]);
        *(uint4*)(Olo + off) = make_uint4(lo[0], lo[1], lo[2], lo[3]);
    }
}

// ---------------------------------------------------------------------------
// Fused kernel: one CTA per (batch, 4-node tile); 2 CTAs/SM; 5 barriers.
//   stage X              | cp Wq->S0, Wk->S1
//   QK GEMM -> Q,K bf16  | cp Wv->S2
//   V GEMM  -> V fp32@S0 | cp Wf1->S3
//   attention -> O @ X   |
//   FC1 -> H hi/lo @ Q+K | cp Wf2->S2
//   FC2 -> Y
// ---------------------------------------------------------------------------
__global__ void __launch_bounds__(NTHREADS, 2)
temporal_attention_mma(const float* __restrict__ X,
                       const float* __restrict__ bq, const float* __restrict__ bk,
                       const float* __restrict__ bv, const float* __restrict__ bf1,
                       const float* __restrict__ bf2,
                       float* __restrict__ Y) {
    extern __shared__ char smem[];
    char* Xhi = smem + X_OFF;              // 12K hi + 12K lo
    char* Xlo = smem + X_OFF + 12288;

    const int tid = threadIdx.x;
    const int n0blk = blockIdx.x * NB;
    const int b = blockIdx.y;

    const uint32_t xhiU = smem_u32(Xhi);
    const uint32_t xloU = smem_u32(Xlo);
    const uint32_t s0U = smem_u32(smem + S0_OFF);
    const uint32_t s1U = smem_u32(smem + S1_OFF);
    const uint32_t s2U = smem_u32(smem + S2_OFF);
    const uint32_t s3U = smem_u32(smem + S3_OFF);
    const uint32_t hhiU = smem_u32(smem + Q_OFF);
    const uint32_t hloU = smem_u32(smem + K_OFF);

    // Wq -> S0, Wk -> S1; overlaps X staging.
    fetch_W(s0U, 0, tid);
    fetch_W(s1U, 1, tid);

    // Stage X as bf16 hi/lo (zero-fill out-of-range nodes).
#pragma unroll
    for (int p = 0; p < 3; ++p) {
        int idx = tid + p * NTHREADS;      // 768 tasks: row(96) x group(8)
        int row = idx >> 3, g = idx & 7;
        int node = row / TT, t = row - node * TT;
        int n = n0blk + node;
        float4 f0 = make_float4(0.f, 0.f, 0.f, 0.f);
        float4 f1 = make_float4(0.f, 0.f, 0.f, 0.f);
        if (n < NN) {
            const float* src = X + ((size_t)(b * TT + t) * NN + n) * DD + g * 8;
            f0 = *(const float4*)(src);
            f1 = *(const float4*)(src + 4);
        }
        uint32_t h0, l0, h1, l1, h2, l2, h3, l3;
        split_pair(f0.x, f0.y, h0, l0);
        split_pair(f0.z, f0.w, h1, l1);
        split_pair(f1.x, f1.y, h2, l2);
        split_pair(f1.z, f1.w, h3, l3);
        int off = row * 128 + ((g ^ (row & 7)) << 4);
        *(uint4*)(Xhi + off) = make_uint4(h0, h1, h2, h3);
        *(uint4*)(Xlo + off) = make_uint4(l0, l1, l2, l3);
    }
    wait_cp();
    __syncthreads();

    // Fused QK GEMM -> Q,K bf16; Wv streams into S2.
    fetch_W(s2U, 2, tid);
    gemm_qk(xhiU, xloU, s0U, s0U + 8192, s1U, s1U + 8192,
            bq, bk, smem + Q_OFF, smem + K_OFF, tid);
    wait_cp();
    __syncthreads();

    // V GEMM (Wv@S2) -> V fp32 over S0+S1 (Wq/Wk dead); Wf1 streams into S3.
    fetch_W(s3U, 3, tid);
    gemm_mma<0>(xhiU, xloU, s2U, s2U + 8192, bv, smem + S0_OFF,
                nullptr, nullptr, nullptr, 0, 0, tid);
    wait_cp();
    __syncthreads();

    // Attention (Q,K bf16; V fp32@S0) -> O hi/lo over X region.
    attention(smem + Q_OFF, smem + K_OFF, smem + S0_OFF, Xhi, Xlo, tid);
    __syncthreads();

    // FC1 GEMM (O@X x Wf1@S3) -> H hi/lo over Q+K; Wf2 streams into S2.
    fetch_W(s2U, 4, tid);
    gemm_mma<1>(xhiU, xloU, s3U, s3U + 8192, bf1, nullptr,
                smem + Q_OFF, smem + K_OFF, nullptr, 0, 0, tid);
    wait_cp();
    __syncthreads();

    // FC2 GEMM (H x Wf2@S2) -> Y.
    gemm_mma<2>(hhiU, hloU, s2U, s2U + 8192, bf2, nullptr,
                nullptr, nullptr, Y, b, n0blk, tid);
}

// ---------------------------------------------------------------------------
// kernel_launch: inputs per metadata order:
// 0=X 1=STE(unused) 2=Wq 3=bq 4=Wk 5=bk 6=Wv 7=bv 8=Wf1 9=bf1 10=Wf2 11=bf2
// ---------------------------------------------------------------------------
extern "C" void kernel_launch(void* const* d_in, const int* in_sizes, int n_in,
                              void* d_out, int out_size) {
    const float* X   = (const float*)d_in[0];
    const float* Wq  = (const float*)d_in[2];
    const float* bq  = (const float*)d_in[3];
    const float* Wk  = (const float*)d_in[4];
    const float* bk  = (const float*)d_in[5];
    const float* Wv  = (const float*)d_in[6];
    const float* bv  = (const float*)d_in[7];
    const float* Wf1 = (const float*)d_in[8];
    const float* bf1 = (const float*)d_in[9];
    const float* Wf2 = (const float*)d_in[10];
    const float* bf2 = (const float*)d_in[11];
    float* Y = (float*)d_out;

    prep_weights<<<5, 512>>>(Wq, Wk, Wv, Wf1, Wf2);

    cudaFuncSetAttribute(temporal_attention_mma,
                         cudaFuncAttributeMaxDynamicSharedMemorySize, SMEM_BYTES);
    dim3 grid(NTILES, BB);
    temporal_attention_mma<<<grid, NTHREADS, SMEM_BYTES>>>(
        X, bq, bk, bv, bf1, bf2, Y);
}

// round 15
// speedup vs baseline: 2.1218x; 1.0026x over previous
#include <cuda_runtime.h>
#include <cuda_bf16.h>
#include <cstdint>

// Problem constants
#define BB 32
#define TT 24
#define NN 325
#define DD 64

#define NB 4                  // nodes per CTA
#define MROWS 96              // NB * TT
#define NTILES 82
#define NTHREADS 256          // 8 warps: 2 m-groups (48 rows) x 4 n-groups (16)

// smem regions (total 110592 -> 2 CTAs/SM)
//   X_OFF : X hi/lo bf16 (12K+12K); later O hi/lo (attention out)
//   Q_OFF : Q bf16-hi (12K); later H hi (FC1 out)
//   KF_OFF: K fp32 (24K); first 12K later H lo
//   S0..S2: three 16K W slabs; V fp32 (24K) lands over S0 + S1 head.
#define X_OFF 0
#define Q_OFF 24576
#define KF_OFF 36864
#define S0_OFF 61440
#define S1_OFF 77824
#define S2_OFF 94208
#define SMEM_BYTES 110592

// Pre-split weights: [w][0..8192) hi plane, [8192..16384) lo plane,
// in the swizzled smem layout (row k: 128B; chunk g at g^(k&7)).
__device__ __align__(16) unsigned char g_wsplit[5][16384];

typedef unsigned long long ull;

// ---------------------------------------------------------------------------
// PTX helpers
// ---------------------------------------------------------------------------
__device__ __forceinline__ uint32_t smem_u32(const void* p) {
    return (uint32_t)__cvta_generic_to_shared(p);
}
__device__ __forceinline__ void ldsm4(uint32_t addr, uint32_t& r0, uint32_t& r1,
                                      uint32_t& r2, uint32_t& r3) {
    asm volatile("ldmatrix.sync.aligned.m8n8.x4.shared.b16 {%0,%1,%2,%3}, [%4];"
                 : "=r"(r0), "=r"(r1), "=r"(r2), "=r"(r3) : "r"(addr));
}
__device__ __forceinline__ void ldsm4t(uint32_t addr, uint32_t& r0, uint32_t& r1,
                                       uint32_t& r2, uint32_t& r3) {
    asm volatile("ldmatrix.sync.aligned.m8n8.x4.trans.shared.b16 {%0,%1,%2,%3}, [%4];"
                 : "=r"(r0), "=r"(r1), "=r"(r2), "=r"(r3) : "r"(addr));
}
#define MMA(ac, A0, A1, A2, A3, B0, B1)                                        \
    asm volatile(                                                              \
        "mma.sync.aligned.m16n8k16.row.col.f32.bf16.bf16.f32 "                 \
        "{%0,%1,%2,%3}, {%4,%5,%6,%7}, {%8,%9}, {%0,%1,%2,%3};"                \
        : "+f"((ac)[0]), "+f"((ac)[1]), "+f"((ac)[2]), "+f"((ac)[3])           \
        : "r"(A0), "r"(A1), "r"(A2), "r"(A3), "r"(B0), "r"(B1))

__device__ __forceinline__ float ex2f(float x) {
    float y;
    asm("ex2.approx.f32 %0, %1;" : "=f"(y) : "f"(x));
    return y;
}
__device__ __forceinline__ ull ffma2(ull a, ull b, ull c) {
    ull d;
    asm("fma.rn.f32x2 %0, %1, %2, %3;" : "=l"(d) : "l"(a), "l"(b), "l"(c));
    return d;
}
__device__ __forceinline__ ull mul2(ull a, ull b) {
    ull d;
    asm("mul.rn.f32x2 %0, %1, %2;" : "=l"(d) : "l"(a), "l"(b));
    return d;
}
__device__ __forceinline__ float2 unpack2(ull v) {
    float2 r;
    asm("mov.b64 {%0, %1}, %2;" : "=f"(r.x), "=f"(r.y) : "l"(v));
    return r;
}
__device__ __forceinline__ ull pack2s(float x) {
    ull r;
    asm("mov.b64 %0, {%1, %1};" : "=l"(r) : "f"(x));
    return r;
}
// bf16x2 word -> f32x2 ull ({even elem, odd elem}).
__device__ __forceinline__ ull bf2f(uint32_t p) {
    uint32_t lo = p << 16;
    uint32_t hi = p & 0xFFFF0000u;
    ull r;
    asm("mov.b64 %0, {%1, %2};" : "=l"(r) : "r"(lo), "r"(hi));
    return r;
}

// Split fp32 pair into bf16 hi pair + bf16 residual pair (packed b32 each).
__device__ __forceinline__ void split_pair(float a, float b,
                                           uint32_t& hi, uint32_t& lo) {
    __nv_bfloat16 ah = __float2bfloat16_rn(a);
    __nv_bfloat16 bh = __float2bfloat16_rn(b);
    __nv_bfloat16 al = __float2bfloat16_rn(a - __bfloat162float(ah));
    __nv_bfloat16 bl = __float2bfloat16_rn(b - __bfloat162float(bh));
    __nv_bfloat162 H = __halves2bfloat162(ah, bh);
    __nv_bfloat162 L = __halves2bfloat162(al, bl);
    hi = *reinterpret_cast<uint32_t*>(&H);
    lo = *reinterpret_cast<uint32_t*>(&L);
}
__device__ __forceinline__ uint32_t bf16x2_of(float a, float b) {
    __nv_bfloat162 H = __halves2bfloat162(__float2bfloat16_rn(a),
                                          __float2bfloat16_rn(b));
    return *reinterpret_cast<uint32_t*>(&H);
}

// ---------------------------------------------------------------------------
// Prep kernel: split each 64x64 fp32 weight into bf16 hi/lo planes in the
// final swizzled layout, once for all main-kernel CTAs.
// ---------------------------------------------------------------------------
__global__ void prep_weights(const float* __restrict__ Wq,
                             const float* __restrict__ Wk,
                             const float* __restrict__ Wv,
                             const float* __restrict__ Wf1,
                             const float* __restrict__ Wf2) {
    const float* Ws[5] = {Wq, Wk, Wv, Wf1, Wf2};
    const float* W = Ws[blockIdx.x];
    unsigned char* hi = g_wsplit[blockIdx.x];
    unsigned char* lo = g_wsplit[blockIdx.x] + 8192;
    int tid = threadIdx.x;                 // 512 threads: k(64) x g(8)
    int k = tid >> 3, g = tid & 7;
    const float* src = W + k * 64 + g * 8;
    float4 f0 = *(const float4*)(src);
    float4 f1 = *(const float4*)(src + 4);
    uint32_t h0, l0, h1, l1, h2, l2, h3, l3;
    split_pair(f0.x, f0.y, h0, l0);
    split_pair(f0.z, f0.w, h1, l1);
    split_pair(f1.x, f1.y, h2, l2);
    split_pair(f1.z, f1.w, h3, l3);
    int off = k * 128 + ((g ^ (k & 7)) << 4);
    *(uint4*)(hi + off) = make_uint4(h0, h1, h2, h3);
    *(uint4*)(lo + off) = make_uint4(l0, l1, l2, l3);
}

// ---------------------------------------------------------------------------
// cp.async fetch of one pre-split W (16KB) into an smem slab.
// ---------------------------------------------------------------------------
__device__ __forceinline__ void fetch_W(uint32_t dstU, int widx, int tid) {
#pragma unroll
    for (int i = 0; i < 4; ++i) {
        int idx = tid + i * NTHREADS;      // 1024 x 16B
        asm volatile("cp.async.ca.shared.global [%0], [%1], 16;"
                     :: "r"(dstU + idx * 16),
                        "l"(g_wsplit[widx] + idx * 16));
    }
    asm volatile("cp.async.commit_group;" ::: "memory");
}
__device__ __forceinline__ void wait_cp() {
    asm volatile("cp.async.wait_group 0;" ::: "memory");
}

// ---------------------------------------------------------------------------
// Fused Q+K tensor-core GEMM: shares A fragments across both weights.
// Q out: bf16-hi (128B rows, chunk c at c^(row&7)) + ReLU.
// K out: fp32 (256B rows, 16B chunk c at c^(row&7)) + ReLU.
// ---------------------------------------------------------------------------
__device__ __forceinline__ void gemm_qk(
    uint32_t aHi, uint32_t aLo,
    uint32_t wqHi, uint32_t wqLo, uint32_t wkHi, uint32_t wkLo,
    const float* __restrict__ bq, const float* __restrict__ bk,
    char* __restrict__ outQ, char* __restrict__ outK, int tid) {
    const int wid = tid >> 5, lane = tid & 31;
    const int m0 = (wid & 1) * 48;
    const int n0 = (wid >> 1) * 16;
    const int i7 = lane & 7;
    const int h8 = (lane >> 3) & 1;
    const int kh = (lane >> 4) & 1;

    const int rowA = m0 + i7 + h8 * 8;
    const uint32_t aHiB = aHi + rowA * 128;
    const uint32_t aLoB = aLo + rowA * 128;
    const int rowB = i7 + h8 * 8;
    const uint32_t cB = (uint32_t)(((n0 >> 3) + kh) ^ i7) << 4;
    const uint32_t wqHiB = wqHi + rowB * 128 + cB;
    const uint32_t wqLoB = wqLo + rowB * 128 + cB;
    const uint32_t wkHiB = wkHi + rowB * 128 + cB;
    const uint32_t wkLoB = wkLo + rowB * 128 + cB;

    float accq[3][2][4], acck[3][2][4];
#pragma unroll
    for (int mi = 0; mi < 3; ++mi)
#pragma unroll
        for (int nj = 0; nj < 2; ++nj)
#pragma unroll
            for (int x = 0; x < 4; ++x) { accq[mi][nj][x] = 0.0f; acck[mi][nj][x] = 0.0f; }

#pragma unroll
    for (int ks = 0; ks < 4; ++ks) {
        const uint32_t cA = (uint32_t)(((2 * ks) + kh) ^ i7) << 4;
        const uint32_t wk = (uint32_t)(ks * 2048);
        uint32_t ah[3][4], al[3][4], bh[4], bl[4];
#pragma unroll
        for (int mi = 0; mi < 3; ++mi) {
            ldsm4(aHiB + mi * 2048 + cA, ah[mi][0], ah[mi][1], ah[mi][2], ah[mi][3]);
            ldsm4(aLoB + mi * 2048 + cA, al[mi][0], al[mi][1], al[mi][2], al[mi][3]);
        }
        // ---- Wq ----
        ldsm4t(wqHiB + wk, bh[0], bh[1], bh[2], bh[3]);
        ldsm4t(wqLoB + wk, bl[0], bl[1], bl[2], bl[3]);
#pragma unroll
        for (int mi = 0; mi < 3; ++mi) {
            MMA(accq[mi][0], ah[mi][0], ah[mi][1], ah[mi][2], ah[mi][3], bh[0], bh[1]);
            MMA(accq[mi][1], ah[mi][0], ah[mi][1], ah[mi][2], ah[mi][3], bh[2], bh[3]);
        }
#pragma unroll
        for (int mi = 0; mi < 3; ++mi) {
            MMA(accq[mi][0], ah[mi][0], ah[mi][1], ah[mi][2], ah[mi][3], bl[0], bl[1]);
            MMA(accq[mi][1], ah[mi][0], ah[mi][1], ah[mi][2], ah[mi][3], bl[2], bl[3]);
        }
#pragma unroll
        for (int mi = 0; mi < 3; ++mi) {
            MMA(accq[mi][0], al[mi][0], al[mi][1], al[mi][2], al[mi][3], bh[0], bh[1]);
            MMA(accq[mi][1], al[mi][0], al[mi][1], al[mi][2], al[mi][3], bh[2], bh[3]);
        }
        // ---- Wk ----
        ldsm4t(wkHiB + wk, bh[0], bh[1], bh[2], bh[3]);
        ldsm4t(wkLoB + wk, bl[0], bl[1], bl[2], bl[3]);
#pragma unroll
        for (int mi = 0; mi < 3; ++mi) {
            MMA(acck[mi][0], ah[mi][0], ah[mi][1], ah[mi][2], ah[mi][3], bh[0], bh[1]);
            MMA(acck[mi][1], ah[mi][0], ah[mi][1], ah[mi][2], ah[mi][3], bh[2], bh[3]);
        }
#pragma unroll
        for (int mi = 0; mi < 3; ++mi) {
            MMA(acck[mi][0], ah[mi][0], ah[mi][1], ah[mi][2], ah[mi][3], bl[0], bl[1]);
            MMA(acck[mi][1], ah[mi][0], ah[mi][1], ah[mi][2], ah[mi][3], bl[2], bl[3]);
        }
#pragma unroll
        for (int mi = 0; mi < 3; ++mi) {
            MMA(acck[mi][0], al[mi][0], al[mi][1], al[mi][2], al[mi][3], bh[0], bh[1]);
            MMA(acck[mi][1], al[mi][0], al[mi][1], al[mi][2], al[mi][3], bh[2], bh[3]);
        }
    }

    const int g = lane >> 2;
    const int c2 = (lane & 3) * 2;
#pragma unroll
    for (int mi = 0; mi < 3; ++mi) {
#pragma unroll
        for (int nj = 0; nj < 2; ++nj) {
            const int cc = n0 + 8 * nj + c2;
            const int r1 = m0 + mi * 16 + g, r2 = r1 + 8;
            float2 bvq = *(const float2*)(bq + cc);
            float2 bvk = *(const float2*)(bk + cc);
            // Q -> bf16-hi
            {
                const int coff = (((cc >> 3) ^ g) << 4) + (cc & 7) * 2;
                float v00 = fmaxf(accq[mi][nj][0] + bvq.x, 0.f);
                float v01 = fmaxf(accq[mi][nj][1] + bvq.y, 0.f);
                float v10 = fmaxf(accq[mi][nj][2] + bvq.x, 0.f);
                float v11 = fmaxf(accq[mi][nj][3] + bvq.y, 0.f);
                *(uint32_t*)(outQ + r1 * 128 + coff) = bf16x2_of(v00, v01);
                *(uint32_t*)(outQ + r2 * 128 + coff) = bf16x2_of(v10, v11);
            }
            // K -> fp32
            {
                const int coff = (((cc >> 2) ^ g) << 4) + (cc & 3) * 4;
                float v00 = fmaxf(acck[mi][nj][0] + bvk.x, 0.f);
                float v01 = fmaxf(acck[mi][nj][1] + bvk.y, 0.f);
                float v10 = fmaxf(acck[mi][nj][2] + bvk.x, 0.f);
                float v11 = fmaxf(acck[mi][nj][3] + bvk.y, 0.f);
                *(float2*)(outK + r1 * 256 + coff) = make_float2(v00, v01);
                *(float2*)(outK + r2 * 256 + coff) = make_float2(v10, v11);
            }
        }
    }
}

// ---------------------------------------------------------------------------
// Single tensor-core GEMM (V / FC1 / FC2), 3-term bf16 split.
// MODE 0: fp32 smem out (+bias,+relu)  MODE 1: bf16 hi/lo out (+bias,+relu)
// MODE 2: global fp32 out (+bias)
// ---------------------------------------------------------------------------
template <int MODE>
__device__ __forceinline__ void gemm_mma(
    uint32_t aHi, uint32_t aLo, uint32_t wHi, uint32_t wLo,
    const float* __restrict__ bias,
    char* __restrict__ outF,
    char* __restrict__ outHi, char* __restrict__ outLo,
    float* __restrict__ Y, int b, int n0blk, int tid) {
    const int wid = tid >> 5, lane = tid & 31;
    const int m0 = (wid & 1) * 48;
    const int n0 = (wid >> 1) * 16;
    const int i7 = lane & 7;
    const int h8 = (lane >> 3) & 1;
    const int kh = (lane >> 4) & 1;

    const int rowA = m0 + i7 + h8 * 8;
    const uint32_t aHiB = aHi + rowA * 128;
    const uint32_t aLoB = aLo + rowA * 128;
    const int rowB = i7 + h8 * 8;
    const uint32_t cB = (uint32_t)(((n0 >> 3) + kh) ^ i7) << 4;
    const uint32_t wHiB = wHi + rowB * 128 + cB;
    const uint32_t wLoB = wLo + rowB * 128 + cB;

    float acc[3][2][4];
#pragma unroll
    for (int mi = 0; mi < 3; ++mi)
#pragma unroll
        for (int nj = 0; nj < 2; ++nj)
#pragma unroll
            for (int x = 0; x < 4; ++x) acc[mi][nj][x] = 0.0f;

#pragma unroll
    for (int ks = 0; ks < 4; ++ks) {
        const uint32_t cA = (uint32_t)(((2 * ks) + kh) ^ i7) << 4;
        const uint32_t wk = (uint32_t)(ks * 2048);
        uint32_t ah[3][4], al[3][4], bh[4], bl[4];
        ldsm4t(wHiB + wk, bh[0], bh[1], bh[2], bh[3]);
        ldsm4t(wLoB + wk, bl[0], bl[1], bl[2], bl[3]);
#pragma unroll
        for (int mi = 0; mi < 3; ++mi) {
            ldsm4(aHiB + mi * 2048 + cA, ah[mi][0], ah[mi][1], ah[mi][2], ah[mi][3]);
            ldsm4(aLoB + mi * 2048 + cA, al[mi][0], al[mi][1], al[mi][2], al[mi][3]);
        }
#pragma unroll
        for (int mi = 0; mi < 3; ++mi) {
            MMA(acc[mi][0], ah[mi][0], ah[mi][1], ah[mi][2], ah[mi][3], bh[0], bh[1]);
            MMA(acc[mi][1], ah[mi][0], ah[mi][1], ah[mi][2], ah[mi][3], bh[2], bh[3]);
        }
#pragma unroll
        for (int mi = 0; mi < 3; ++mi) {
            MMA(acc[mi][0], ah[mi][0], ah[mi][1], ah[mi][2], ah[mi][3], bl[0], bl[1]);
            MMA(acc[mi][1], ah[mi][0], ah[mi][1], ah[mi][2], ah[mi][3], bl[2], bl[3]);
        }
#pragma unroll
        for (int mi = 0; mi < 3; ++mi) {
            MMA(acc[mi][0], al[mi][0], al[mi][1], al[mi][2], al[mi][3], bh[0], bh[1]);
            MMA(acc[mi][1], al[mi][0], al[mi][1], al[mi][2], al[mi][3], bh[2], bh[3]);
        }
    }

    const int g = lane >> 2;
    const int c2 = (lane & 3) * 2;
#pragma unroll
    for (int mi = 0; mi < 3; ++mi) {
#pragma unroll
        for (int nj = 0; nj < 2; ++nj) {
            const int cc = n0 + 8 * nj + c2;
            float2 bv = *(const float2*)(bias + cc);
            float v00 = acc[mi][nj][0] + bv.x, v01 = acc[mi][nj][1] + bv.y;
            float v10 = acc[mi][nj][2] + bv.x, v11 = acc[mi][nj][3] + bv.y;
            const int r1 = m0 + mi * 16 + g, r2 = r1 + 8;
            if (MODE == 0) {
                v00 = fmaxf(v00, 0.f); v01 = fmaxf(v01, 0.f);
                v10 = fmaxf(v10, 0.f); v11 = fmaxf(v11, 0.f);
                const int coff = (((cc >> 2) ^ g) << 4) + (cc & 3) * 4;
                *(float2*)(outF + r1 * 256 + coff) = make_float2(v00, v01);
                *(float2*)(outF + r2 * 256 + coff) = make_float2(v10, v11);
            } else if (MODE == 1) {
                v00 = fmaxf(v00, 0.f); v01 = fmaxf(v01, 0.f);
                v10 = fmaxf(v10, 0.f); v11 = fmaxf(v11, 0.f);
                uint32_t hi1, lo1, hi2, lo2;
                split_pair(v00, v01, hi1, lo1);
                split_pair(v10, v11, hi2, lo2);
                const int coff = (((cc >> 3) ^ g) << 4) + (cc & 7) * 2;
                *(uint32_t*)(outHi + r1 * 128 + coff) = hi1;
                *(uint32_t*)(outLo + r1 * 128 + coff) = lo1;
                *(uint32_t*)(outHi + r2 * 128 + coff) = hi2;
                *(uint32_t*)(outLo + r2 * 128 + coff) = lo2;
            } else {
                int node1 = r1 / TT, t1 = r1 - node1 * TT, n1 = n0blk + node1;
                if (n1 < NN)
                    *(float2*)(Y + ((size_t)(b * TT + t1) * NN + n1) * DD + cc) =
                        make_float2(v00, v01);
                int node2 = r2 / TT, t2 = r2 - node2 * TT, n2 = n0blk + node2;
                if (n2 < NN)
                    *(float2*)(Y + ((size_t)(b * TT + t2) * NN + n2) * DD + cc) =
                        make_float2(v10, v11);
            }
        }
    }
}

// ---------------------------------------------------------------------------
// Attention: one thread per (node, head, t-triple): 4*8*8 = 256 tasks.
// Q: bf16-hi (128B rows).  K,V: fp32 (256B rows, chunk c at c^(row&7)).
// Packed f32x2 math; ex2.approx; no max-subtraction.
// Writes O as bf16 hi/lo (A operand of FC1) over the X region.
// ---------------------------------------------------------------------------
__device__ __forceinline__ void attention(const char* __restrict__ Qb,
                                          const char* __restrict__ Kf,
                                          const char* __restrict__ Vf,
                                          char* __restrict__ Ohi,
                                          char* __restrict__ Olo, int tid) {
    const float scale = 0.5100697176f;   // (1/sqrt(8)) * log2(e)
    const ull scale2 = pack2s(scale);
    const int node = tid >> 6;
    const int h = (tid >> 3) & 7;
    const int tg = tid & 7;
    const int tbase = tg * 3;
    const int rbase = node * TT;         // multiple of 24 -> (rbase & 7) == 0
    const int ch = 2 * h;                // fp32 chunk base for this head

    ull q2[3][4], o2[3][4];
    float sum[3];
#pragma unroll
    for (int i = 0; i < 3; ++i) {
        int r7 = (tbase + i) & 7;
        uint4 qr = *(const uint4*)(Qb + (rbase + tbase + i) * 128 + ((h ^ r7) << 4));
        q2[i][0] = mul2(bf2f(qr.x), scale2);
        q2[i][1] = mul2(bf2f(qr.y), scale2);
        q2[i][2] = mul2(bf2f(qr.z), scale2);
        q2[i][3] = mul2(bf2f(qr.w), scale2);
        sum[i] = 0.0f;
#pragma unroll
        for (int j = 0; j < 4; ++j) o2[i][j] = 0ull;
    }

#pragma unroll
    for (int a8 = 0; a8 < 3; ++a8) {
#pragma unroll
        for (int e = 0; e < 8; ++e) {      // s & 7 == e (compile-time)
            int s = 8 * a8 + e;
            const int c1 = ((ch ^ e) << 4), c2v = (((ch + 1) ^ e) << 4);
            const char* kr = Kf + (rbase + s) * 256;
            const char* vr = Vf + (rbase + s) * 256;
            ulonglong2 ka = *(const ulonglong2*)(kr + c1);
            ulonglong2 kb = *(const ulonglong2*)(kr + c2v);
            ulonglong2 va = *(const ulonglong2*)(vr + c1);
            ulonglong2 vb = *(const ulonglong2*)(vr + c2v);
#pragma unroll
            for (int i = 0; i < 3; ++i) {
                ull d2 = mul2(q2[i][0], ka.x);
                d2 = ffma2(q2[i][1], ka.y, d2);
                d2 = ffma2(q2[i][2], kb.x, d2);
                d2 = ffma2(q2[i][3], kb.y, d2);
                float2 dd = unpack2(d2);
                float dot = dd.x + dd.y;
                float e2 = (s >= tbase + i) ? ex2f(dot) : 0.0f;
                sum[i] += e2;
                ull ep = pack2s(e2);
                o2[i][0] = ffma2(ep, va.x, o2[i][0]);
                o2[i][1] = ffma2(ep, va.y, o2[i][1]);
                o2[i][2] = ffma2(ep, vb.x, o2[i][2]);
                o2[i][3] = ffma2(ep, vb.y, o2[i][3]);
            }
        }
    }

#pragma unroll
    for (int i = 0; i < 3; ++i) {
        float inv = 1.0f / sum[i];
        int row = rbase + tbase + i;
        int r7 = (tbase + i) & 7;
        uint32_t hi[4], lo[4];
#pragma unroll
        for (int j = 0; j < 4; ++j) {
            float2 p = unpack2(o2[i][j]);
            split_pair(p.x * inv, p.y * inv, hi[j], lo[j]);
        }
        int off = row * 128 + ((h ^ r7) << 4);
        *(uint4*)(Ohi + off) = make_uint4(hi[0], hi[1], hi[2], hi[3]);
        *(uint4*)(Olo + off) = make_uint4(lo[0], lo[1], lo[2], lo[3]);
    }
}

// ---------------------------------------------------------------------------
// Fused kernel: one CTA per (batch, 4-node tile); 2 CTAs/SM; 5 barriers.
//   stage X                 | cp Wq->S0, Wk->S1
//   QK GEMM -> Q bf16, K f32| cp Wv->S2
//   V GEMM  -> V f32 @S0+S1 |
//   attention -> O @ X      | cp Wf1->S2 (Wv dead)
//   FC1 -> H hi@Q, lo@K     | cp Wf2->S0 (V dead)
//   FC2 -> Y
// ---------------------------------------------------------------------------
__global__ void __launch_bounds__(NTHREADS, 2)
temporal_attention_mma(const float* __restrict__ X,
                       const float* __restrict__ bq, const float* __restrict__ bk,
                       const float* __restrict__ bv, const float* __restrict__ bf1,
                       const float* __restrict__ bf2,
                       float* __restrict__ Y) {
    extern __shared__ char smem[];
    char* Xhi = smem + X_OFF;              // 12K hi + 12K lo
    char* Xlo = smem + X_OFF + 12288;

    const int tid = threadIdx.x;
    const int n0blk = blockIdx.x * NB;
    const int b = blockIdx.y;

    const uint32_t xhiU = smem_u32(Xhi);
    const uint32_t xloU = smem_u32(Xlo);
    const uint32_t s0U = smem_u32(smem + S0_OFF);
    const uint32_t s1U = smem_u32(smem + S1_OFF);
    const uint32_t s2U = smem_u32(smem + S2_OFF);
    const uint32_t hhiU = smem_u32(smem + Q_OFF);
    const uint32_t hloU = smem_u32(smem + KF_OFF);

    // Wq -> S0, Wk -> S1; overlaps X staging.
    fetch_W(s0U, 0, tid);
    fetch_W(s1U, 1, tid);

    // Stage X as bf16 hi/lo (zero-fill out-of-range nodes).
#pragma unroll
    for (int p = 0; p < 3; ++p) {
        int idx = tid + p * NTHREADS;      // 768 tasks: row(96) x group(8)
        int row = idx >> 3, g = idx & 7;
        int node = row / TT, t = row - node * TT;
        int n = n0blk + node;
        float4 f0 = make_float4(0.f, 0.f, 0.f, 0.f);
        float4 f1 = make_float4(0.f, 0.f, 0.f, 0.f);
        if (n < NN) {
            const float* src = X + ((size_t)(b * TT + t) * NN + n) * DD + g * 8;
            f0 = *(const float4*)(src);
            f1 = *(const float4*)(src + 4);
        }
        uint32_t h0, l0, h1, l1, h2, l2, h3, l3;
        split_pair(f0.x, f0.y, h0, l0);
        split_pair(f0.z, f0.w, h1, l1);
        split_pair(f1.x, f1.y, h2, l2);
        split_pair(f1.z, f1.w, h3, l3);
        int off = row * 128 + ((g ^ (row & 7)) << 4);
        *(uint4*)(Xhi + off) = make_uint4(h0, h1, h2, h3);
        *(uint4*)(Xlo + off) = make_uint4(l0, l1, l2, l3);
    }
    wait_cp();
    __syncthreads();

    // Fused QK GEMM -> Q bf16, K fp32; Wv streams into S2.
    fetch_W(s2U, 2, tid);
    gemm_qk(xhiU, xloU, s0U, s0U + 8192, s1U, s1U + 8192,
            bq, bk, smem + Q_OFF, smem + KF_OFF, tid);
    wait_cp();
    __syncthreads();

    // V GEMM (Wv@S2) -> V fp32 over S0 + S1 head (Wq/Wk dead).
    gemm_mma<0>(xhiU, xloU, s2U, s2U + 8192, bv, smem + S0_OFF,
                nullptr, nullptr, nullptr, 0, 0, tid);
    __syncthreads();

    // Attention (Q bf16, K/V fp32) -> O hi/lo over X; Wf1 streams into S2.
    fetch_W(s2U, 3, tid);
    attention(smem + Q_OFF, smem + KF_OFF, smem + S0_OFF, Xhi, Xlo, tid);
    wait_cp();
    __syncthreads();

    // FC1 GEMM (O@X x Wf1@S2) -> H hi@Q, lo@K head; Wf2 streams into S0.
    fetch_W(s0U, 4, tid);
    gemm_mma<1>(xhiU, xloU, s2U, s2U + 8192, bf1, nullptr,
                smem + Q_OFF, smem + KF_OFF, nullptr, 0, 0, tid);
    wait_cp();
    __syncthreads();

    // FC2 GEMM (H x Wf2@S0) -> Y.
    gemm_mma<2>(hhiU, hloU, s0U, s0U + 8192, bf2, nullptr,
                nullptr, nullptr, Y, b, n0blk, tid);
}

// ---------------------------------------------------------------------------
// kernel_launch: inputs per metadata order:
// 0=X 1=STE(unused) 2=Wq 3=bq 4=Wk 5=bk 6=Wv 7=bv 8=Wf1 9=bf1 10=Wf2 11=bf2
// ---------------------------------------------------------------------------
extern "C" void kernel_launch(void* const* d_in, const int* in_sizes, int n_in,
                              void* d_out, int out_size) {
    const float* X   = (const float*)d_in[0];
    const float* Wq  = (const float*)d_in[2];
    const float* bq  = (const float*)d_in[3];
    const float* Wk  = (const float*)d_in[4];
    const float* bk  = (const float*)d_in[5];
    const float* Wv  = (const float*)d_in[6];
    const float* bv  = (const float*)d_in[7];
    const float* Wf1 = (const float*)d_in[8];
    const float* bf1 = (const float*)d_in[9];
    const float* Wf2 = (const float*)d_in[10];
    const float* bf2 = (const float*)d_in[11];
    float* Y = (float*)d_out;

    prep_weights<<<5, 512>>>(Wq, Wk, Wv, Wf1, Wf2);

    cudaFuncSetAttribute(temporal_attention_mma,
                         cudaFuncAttributeMaxDynamicSharedMemorySize, SMEM_BYTES);
    dim3 grid(NTILES, BB);
    temporal_attention_mma<<<grid, NTHREADS, SMEM_BYTES>>>(
        X, bq, bk, bv, bf1, bf2, Y);
}

// round 16
// speedup vs baseline: 2.1890x; 1.0317x over previous
#include <cuda_runtime.h>
#include <cuda_bf16.h>
#include <cstdint>

// Problem constants
#define BB 32
#define TT 24
#define NN 325
#define DD 64

#define NB 4                  // nodes per CTA
#define MROWS 96              // NB * TT
#define NTILES 82
#define NTHREADS 256          // 8 warps: 2 m-groups (48 rows) x 4 n-groups (16)

// smem regions (total 106496 -> 2 CTAs/SM)
//   X_OFF : X hi/lo bf16 (12K+12K); later O hi/lo (attention out)
//   Q_OFF : Q bf16-hi (12K); later H hi (FC1 out)
//   K_OFF : K bf16-hi (12K); later H lo
//   V_OFF : V fp32 (24K)
//   SA/SB : 8K Wq-hi / 8K Wk-hi; later 16K contiguous Wf2 slab
//   SC    : 16K Wv hi/lo; later Wf1 slab
#define X_OFF 0
#define Q_OFF 24576
#define K_OFF 36864
#define V_OFF 49152
#define SA_OFF 73728
#define SB_OFF 81920
#define SC_OFF 90112
#define SMEM_BYTES 106496

// Pre-split weights: [w][0..8192) hi plane, [8192..16384) lo plane,
// in the swizzled smem layout (row k: 128B; chunk g at g^(k&7)).
__device__ __align__(16) unsigned char g_wsplit[5][16384];

typedef unsigned long long ull;

// ---------------------------------------------------------------------------
// PTX helpers
// ---------------------------------------------------------------------------
__device__ __forceinline__ uint32_t smem_u32(const void* p) {
    return (uint32_t)__cvta_generic_to_shared(p);
}
__device__ __forceinline__ void ldsm4(uint32_t addr, uint32_t& r0, uint32_t& r1,
                                      uint32_t& r2, uint32_t& r3) {
    asm volatile("ldmatrix.sync.aligned.m8n8.x4.shared.b16 {%0,%1,%2,%3}, [%4];"
                 : "=r"(r0), "=r"(r1), "=r"(r2), "=r"(r3) : "r"(addr));
}
__device__ __forceinline__ void ldsm4t(uint32_t addr, uint32_t& r0, uint32_t& r1,
                                       uint32_t& r2, uint32_t& r3) {
    asm volatile("ldmatrix.sync.aligned.m8n8.x4.trans.shared.b16 {%0,%1,%2,%3}, [%4];"
                 : "=r"(r0), "=r"(r1), "=r"(r2), "=r"(r3) : "r"(addr));
}
#define MMA(ac, A0, A1, A2, A3, B0, B1)                                        \
    asm volatile(                                                              \
        "mma.sync.aligned.m16n8k16.row.col.f32.bf16.bf16.f32 "                 \
        "{%0,%1,%2,%3}, {%4,%5,%6,%7}, {%8,%9}, {%0,%1,%2,%3};"                \
        : "+f"((ac)[0]), "+f"((ac)[1]), "+f"((ac)[2]), "+f"((ac)[3])           \
        : "r"(A0), "r"(A1), "r"(A2), "r"(A3), "r"(B0), "r"(B1))

__device__ __forceinline__ float ex2f(float x) {
    float y;
    asm("ex2.approx.f32 %0, %1;" : "=f"(y) : "f"(x));
    return y;
}
__device__ __forceinline__ ull ffma2(ull a, ull b, ull c) {
    ull d;
    asm("fma.rn.f32x2 %0, %1, %2, %3;" : "=l"(d) : "l"(a), "l"(b), "l"(c));
    return d;
}
__device__ __forceinline__ ull mul2(ull a, ull b) {
    ull d;
    asm("mul.rn.f32x2 %0, %1, %2;" : "=l"(d) : "l"(a), "l"(b));
    return d;
}
__device__ __forceinline__ float2 unpack2(ull v) {
    float2 r;
    asm("mov.b64 {%0, %1}, %2;" : "=f"(r.x), "=f"(r.y) : "l"(v));
    return r;
}
__device__ __forceinline__ ull pack2s(float x) {
    ull r;
    asm("mov.b64 %0, {%1, %1};" : "=l"(r) : "f"(x));
    return r;
}
// bf16x2 word -> f32x2 ull ({even elem, odd elem}).
__device__ __forceinline__ ull bf2f(uint32_t p) {
    uint32_t lo = p << 16;
    uint32_t hi = p & 0xFFFF0000u;
    ull r;
    asm("mov.b64 %0, {%1, %2};" : "=l"(r) : "r"(lo), "r"(hi));
    return r;
}

// Split fp32 pair into bf16 hi pair + bf16 residual pair (packed b32 each).
__device__ __forceinline__ void split_pair(float a, float b,
                                           uint32_t& hi, uint32_t& lo) {
    __nv_bfloat16 ah = __float2bfloat16_rn(a);
    __nv_bfloat16 bh = __float2bfloat16_rn(b);
    __nv_bfloat16 al = __float2bfloat16_rn(a - __bfloat162float(ah));
    __nv_bfloat16 bl = __float2bfloat16_rn(b - __bfloat162float(bh));
    __nv_bfloat162 H = __halves2bfloat162(ah, bh);
    __nv_bfloat162 L = __halves2bfloat162(al, bl);
    hi = *reinterpret_cast<uint32_t*>(&H);
    lo = *reinterpret_cast<uint32_t*>(&L);
}
__device__ __forceinline__ uint32_t bf16x2_of(float a, float b) {
    __nv_bfloat162 H = __halves2bfloat162(__float2bfloat16_rn(a),
                                          __float2bfloat16_rn(b));
    return *reinterpret_cast<uint32_t*>(&H);
}

// ---------------------------------------------------------------------------
// Prep kernel: split each 64x64 fp32 weight into bf16 hi/lo planes in the
// final swizzled layout, once for all main-kernel CTAs.
// ---------------------------------------------------------------------------
__global__ void prep_weights(const float* __restrict__ Wq,
                             const float* __restrict__ Wk,
                             const float* __restrict__ Wv,
                             const float* __restrict__ Wf1,
                             const float* __restrict__ Wf2) {
    const float* Ws[5] = {Wq, Wk, Wv, Wf1, Wf2};
    const float* W = Ws[blockIdx.x];
    unsigned char* hi = g_wsplit[blockIdx.x];
    unsigned char* lo = g_wsplit[blockIdx.x] + 8192;
    int tid = threadIdx.x;                 // 512 threads: k(64) x g(8)
    int k = tid >> 3, g = tid & 7;
    const float* src = W + k * 64 + g * 8;
    float4 f0 = *(const float4*)(src);
    float4 f1 = *(const float4*)(src + 4);
    uint32_t h0, l0, h1, l1, h2, l2, h3, l3;
    split_pair(f0.x, f0.y, h0, l0);
    split_pair(f0.z, f0.w, h1, l1);
    split_pair(f1.x, f1.y, h2, l2);
    split_pair(f1.z, f1.w, h3, l3);
    int off = k * 128 + ((g ^ (k & 7)) << 4);
    *(uint4*)(hi + off) = make_uint4(h0, h1, h2, h3);
    *(uint4*)(lo + off) = make_uint4(l0, l1, l2, l3);
}

// ---------------------------------------------------------------------------
// cp.async fetches: full 16KB (hi+lo) or hi-plane-only 8KB.
// ---------------------------------------------------------------------------
__device__ __forceinline__ void fetch_W(uint32_t dstU, int widx, int tid) {
#pragma unroll
    for (int i = 0; i < 4; ++i) {
        int idx = tid + i * NTHREADS;      // 1024 x 16B
        asm volatile("cp.async.ca.shared.global [%0], [%1], 16;"
                     :: "r"(dstU + idx * 16),
                        "l"(g_wsplit[widx] + idx * 16));
    }
    asm volatile("cp.async.commit_group;" ::: "memory");
}
__device__ __forceinline__ void fetch_W8(uint32_t dstU, int widx, int tid) {
#pragma unroll
    for (int i = 0; i < 2; ++i) {
        int idx = tid + i * NTHREADS;      // 512 x 16B (hi plane only)
        asm volatile("cp.async.ca.shared.global [%0], [%1], 16;"
                     :: "r"(dstU + idx * 16),
                        "l"(g_wsplit[widx] + idx * 16));
    }
    asm volatile("cp.async.commit_group;" ::: "memory");
}
__device__ __forceinline__ void wait_cp() {
    asm volatile("cp.async.wait_group 0;" ::: "memory");
}

// ---------------------------------------------------------------------------
// Fused Q+K+V tensor-core GEMM. A fragments loaded ONCE per k-step.
// Q,K: 2-term (Ah+Al)@Wh (W hi plane only), out bf16-hi + ReLU.
// V:   3-term, out fp32 (256B rows) + ReLU.
// 8 warps: warp w -> m-group (w&1)*48, n-group (w>>1)*16.
// ---------------------------------------------------------------------------
__device__ __forceinline__ void gemm_qkv(
    uint32_t aHi, uint32_t aLo,
    uint32_t wq, uint32_t wk, uint32_t wvHi, uint32_t wvLo,
    const float* __restrict__ bq, const float* __restrict__ bk,
    const float* __restrict__ bv,
    char* __restrict__ outQ, char* __restrict__ outK,
    char* __restrict__ outV, int tid) {
    const int wid = tid >> 5, lane = tid & 31;
    const int m0 = (wid & 1) * 48;
    const int n0 = (wid >> 1) * 16;
    const int i7 = lane & 7;
    const int h8 = (lane >> 3) & 1;
    const int kh = (lane >> 4) & 1;

    const int rowA = m0 + i7 + h8 * 8;
    const uint32_t aHiB = aHi + rowA * 128;
    const uint32_t aLoB = aLo + rowA * 128;
    const int rowB = i7 + h8 * 8;
    const uint32_t cB = (uint32_t)(((n0 >> 3) + kh) ^ i7) << 4;
    const uint32_t wqB = wq + rowB * 128 + cB;
    const uint32_t wkB = wk + rowB * 128 + cB;
    const uint32_t wvHiB = wvHi + rowB * 128 + cB;
    const uint32_t wvLoB = wvLo + rowB * 128 + cB;

    float accq[3][2][4], acck[3][2][4], accv[3][2][4];
#pragma unroll
    for (int mi = 0; mi < 3; ++mi)
#pragma unroll
        for (int nj = 0; nj < 2; ++nj)
#pragma unroll
            for (int x = 0; x < 4; ++x) {
                accq[mi][nj][x] = 0.0f;
                acck[mi][nj][x] = 0.0f;
                accv[mi][nj][x] = 0.0f;
            }

#pragma unroll
    for (int ks = 0; ks < 4; ++ks) {
        const uint32_t cA = (uint32_t)(((2 * ks) + kh) ^ i7) << 4;
        const uint32_t wkofs = (uint32_t)(ks * 2048);
        uint32_t ah[3][4], al[3][4], b0[4], b1[4];
#pragma unroll
        for (int mi = 0; mi < 3; ++mi) {
            ldsm4(aHiB + mi * 2048 + cA, ah[mi][0], ah[mi][1], ah[mi][2], ah[mi][3]);
            ldsm4(aLoB + mi * 2048 + cA, al[mi][0], al[mi][1], al[mi][2], al[mi][3]);
        }
        // ---- Q: (Ah + Al) @ Wq-hi ----
        ldsm4t(wqB + wkofs, b0[0], b0[1], b0[2], b0[3]);
#pragma unroll
        for (int mi = 0; mi < 3; ++mi) {
            MMA(accq[mi][0], ah[mi][0], ah[mi][1], ah[mi][2], ah[mi][3], b0[0], b0[1]);
            MMA(accq[mi][1], ah[mi][0], ah[mi][1], ah[mi][2], ah[mi][3], b0[2], b0[3]);
        }
#pragma unroll
        for (int mi = 0; mi < 3; ++mi) {
            MMA(accq[mi][0], al[mi][0], al[mi][1], al[mi][2], al[mi][3], b0[0], b0[1]);
            MMA(accq[mi][1], al[mi][0], al[mi][1], al[mi][2], al[mi][3], b0[2], b0[3]);
        }
        // ---- K: (Ah + Al) @ Wk-hi ----
        ldsm4t(wkB + wkofs, b0[0], b0[1], b0[2], b0[3]);
#pragma unroll
        for (int mi = 0; mi < 3; ++mi) {
            MMA(acck[mi][0], ah[mi][0], ah[mi][1], ah[mi][2], ah[mi][3], b0[0], b0[1]);
            MMA(acck[mi][1], ah[mi][0], ah[mi][1], ah[mi][2], ah[mi][3], b0[2], b0[3]);
        }
#pragma unroll
        for (int mi = 0; mi < 3; ++mi) {
            MMA(acck[mi][0], al[mi][0], al[mi][1], al[mi][2], al[mi][3], b0[0], b0[1]);
            MMA(acck[mi][1], al[mi][0], al[mi][1], al[mi][2], al[mi][3], b0[2], b0[3]);
        }
        // ---- V: 3-term ----
        ldsm4t(wvHiB + wkofs, b0[0], b0[1], b0[2], b0[3]);
        ldsm4t(wvLoB + wkofs, b1[0], b1[1], b1[2], b1[3]);
#pragma unroll
        for (int mi = 0; mi < 3; ++mi) {
            MMA(accv[mi][0], ah[mi][0], ah[mi][1], ah[mi][2], ah[mi][3], b0[0], b0[1]);
            MMA(accv[mi][1], ah[mi][0], ah[mi][1], ah[mi][2], ah[mi][3], b0[2], b0[3]);
        }
#pragma unroll
        for (int mi = 0; mi < 3; ++mi) {
            MMA(accv[mi][0], ah[mi][0], ah[mi][1], ah[mi][2], ah[mi][3], b1[0], b1[1]);
            MMA(accv[mi][1], ah[mi][0], ah[mi][1], ah[mi][2], ah[mi][3], b1[2], b1[3]);
        }
#pragma unroll
        for (int mi = 0; mi < 3; ++mi) {
            MMA(accv[mi][0], al[mi][0], al[mi][1], al[mi][2], al[mi][3], b0[0], b0[1]);
            MMA(accv[mi][1], al[mi][0], al[mi][1], al[mi][2], al[mi][3], b0[2], b0[3]);
        }
    }

    const int g = lane >> 2;
    const int c2 = (lane & 3) * 2;
#pragma unroll
    for (int mi = 0; mi < 3; ++mi) {
#pragma unroll
        for (int nj = 0; nj < 2; ++nj) {
            const int cc = n0 + 8 * nj + c2;
            const int r1 = m0 + mi * 16 + g, r2 = r1 + 8;
            const int coff8 = (((cc >> 3) ^ g) << 4) + (cc & 7) * 2;
            // Q -> bf16-hi
            {
                float2 bv2 = *(const float2*)(bq + cc);
                float v00 = fmaxf(accq[mi][nj][0] + bv2.x, 0.f);
                float v01 = fmaxf(accq[mi][nj][1] + bv2.y, 0.f);
                float v10 = fmaxf(accq[mi][nj][2] + bv2.x, 0.f);
                float v11 = fmaxf(accq[mi][nj][3] + bv2.y, 0.f);
                *(uint32_t*)(outQ + r1 * 128 + coff8) = bf16x2_of(v00, v01);
                *(uint32_t*)(outQ + r2 * 128 + coff8) = bf16x2_of(v10, v11);
            }
            // K -> bf16-hi
            {
                float2 bv2 = *(const float2*)(bk + cc);
                float v00 = fmaxf(acck[mi][nj][0] + bv2.x, 0.f);
                float v01 = fmaxf(acck[mi][nj][1] + bv2.y, 0.f);
                float v10 = fmaxf(acck[mi][nj][2] + bv2.x, 0.f);
                float v11 = fmaxf(acck[mi][nj][3] + bv2.y, 0.f);
                *(uint32_t*)(outK + r1 * 128 + coff8) = bf16x2_of(v00, v01);
                *(uint32_t*)(outK + r2 * 128 + coff8) = bf16x2_of(v10, v11);
            }
            // V -> fp32 (256B rows)
            {
                const int coff4 = (((cc >> 2) ^ g) << 4) + (cc & 3) * 4;
                float2 bv2 = *(const float2*)(bv + cc);
                float v00 = fmaxf(accv[mi][nj][0] + bv2.x, 0.f);
                float v01 = fmaxf(accv[mi][nj][1] + bv2.y, 0.f);
                float v10 = fmaxf(accv[mi][nj][2] + bv2.x, 0.f);
                float v11 = fmaxf(accv[mi][nj][3] + bv2.y, 0.f);
                *(float2*)(outV + r1 * 256 + coff4) = make_float2(v00, v01);
                *(float2*)(outV + r2 * 256 + coff4) = make_float2(v10, v11);
            }
        }
    }
}

// ---------------------------------------------------------------------------
// Single tensor-core GEMM (FC1 / FC2), 3-term bf16 split.
// MODE 1: bf16 hi/lo out (+bias,+relu)  MODE 2: global fp32 out (+bias)
// ---------------------------------------------------------------------------
template <int MODE>
__device__ __forceinline__ void gemm_mma(
    uint32_t aHi, uint32_t aLo, uint32_t wHi, uint32_t wLo,
    const float* __restrict__ bias,
    char* __restrict__ outHi, char* __restrict__ outLo,
    float* __restrict__ Y, int b, int n0blk, int tid) {
    const int wid = tid >> 5, lane = tid & 31;
    const int m0 = (wid & 1) * 48;
    const int n0 = (wid >> 1) * 16;
    const int i7 = lane & 7;
    const int h8 = (lane >> 3) & 1;
    const int kh = (lane >> 4) & 1;

    const int rowA = m0 + i7 + h8 * 8;
    const uint32_t aHiB = aHi + rowA * 128;
    const uint32_t aLoB = aLo + rowA * 128;
    const int rowB = i7 + h8 * 8;
    const uint32_t cB = (uint32_t)(((n0 >> 3) + kh) ^ i7) << 4;
    const uint32_t wHiB = wHi + rowB * 128 + cB;
    const uint32_t wLoB = wLo + rowB * 128 + cB;

    float acc[3][2][4];
#pragma unroll
    for (int mi = 0; mi < 3; ++mi)
#pragma unroll
        for (int nj = 0; nj < 2; ++nj)
#pragma unroll
            for (int x = 0; x < 4; ++x) acc[mi][nj][x] = 0.0f;

#pragma unroll
    for (int ks = 0; ks < 4; ++ks) {
        const uint32_t cA = (uint32_t)(((2 * ks) + kh) ^ i7) << 4;
        const uint32_t wk = (uint32_t)(ks * 2048);
        uint32_t ah[3][4], al[3][4], bh[4], bl[4];
        ldsm4t(wHiB + wk, bh[0], bh[1], bh[2], bh[3]);
        ldsm4t(wLoB + wk, bl[0], bl[1], bl[2], bl[3]);
#pragma unroll
        for (int mi = 0; mi < 3; ++mi) {
            ldsm4(aHiB + mi * 2048 + cA, ah[mi][0], ah[mi][1], ah[mi][2], ah[mi][3]);
            ldsm4(aLoB + mi * 2048 + cA, al[mi][0], al[mi][1], al[mi][2], al[mi][3]);
        }
#pragma unroll
        for (int mi = 0; mi < 3; ++mi) {
            MMA(acc[mi][0], ah[mi][0], ah[mi][1], ah[mi][2], ah[mi][3], bh[0], bh[1]);
            MMA(acc[mi][1], ah[mi][0], ah[mi][1], ah[mi][2], ah[mi][3], bh[2], bh[3]);
        }
#pragma unroll
        for (int mi = 0; mi < 3; ++mi) {
            MMA(acc[mi][0], ah[mi][0], ah[mi][1], ah[mi][2], ah[mi][3], bl[0], bl[1]);
            MMA(acc[mi][1], ah[mi][0], ah[mi][1], ah[mi][2], ah[mi][3], bl[2], bl[3]);
        }
#pragma unroll
        for (int mi = 0; mi < 3; ++mi) {
            MMA(acc[mi][0], al[mi][0], al[mi][1], al[mi][2], al[mi][3], bh[0], bh[1]);
            MMA(acc[mi][1], al[mi][0], al[mi][1], al[mi][2], al[mi][3], bh[2], bh[3]);
        }
    }

    const int g = lane >> 2;
    const int c2 = (lane & 3) * 2;
#pragma unroll
    for (int mi = 0; mi < 3; ++mi) {
#pragma unroll
        for (int nj = 0; nj < 2; ++nj) {
            const int cc = n0 + 8 * nj + c2;
            float2 bv = *(const float2*)(bias + cc);
            float v00 = acc[mi][nj][0] + bv.x, v01 = acc[mi][nj][1] + bv.y;
            float v10 = acc[mi][nj][2] + bv.x, v11 = acc[mi][nj][3] + bv.y;
            const int r1 = m0 + mi * 16 + g, r2 = r1 + 8;
            if (MODE == 1) {
                v00 = fmaxf(v00, 0.f); v01 = fmaxf(v01, 0.f);
                v10 = fmaxf(v10, 0.f); v11 = fmaxf(v11, 0.f);
                uint32_t hi1, lo1, hi2, lo2;
                split_pair(v00, v01, hi1, lo1);
                split_pair(v10, v11, hi2, lo2);
                const int coff = (((cc >> 3) ^ g) << 4) + (cc & 7) * 2;
                *(uint32_t*)(outHi + r1 * 128 + coff) = hi1;
                *(uint32_t*)(outLo + r1 * 128 + coff) = lo1;
                *(uint32_t*)(outHi + r2 * 128 + coff) = hi2;
                *(uint32_t*)(outLo + r2 * 128 + coff) = lo2;
            } else {
                int node1 = r1 / TT, t1 = r1 - node1 * TT, n1 = n0blk + node1;
                if (n1 < NN)
                    *(float2*)(Y + ((size_t)(b * TT + t1) * NN + n1) * DD + cc) =
                        make_float2(v00, v01);
                int node2 = r2 / TT, t2 = r2 - node2 * TT, n2 = n0blk + node2;
                if (n2 < NN)
                    *(float2*)(Y + ((size_t)(b * TT + t2) * NN + n2) * DD + cc) =
                        make_float2(v10, v11);
            }
        }
    }
}

// ---------------------------------------------------------------------------
// Attention: one thread per (node, head, t-triple): 4*8*8 = 256 tasks.
// Q/K: bf16-hi (128B rows, chunk h at h^(row&7)).  V: fp32 (256B rows).
// Packed f32x2 math; ex2.approx; no max-subtraction.
// Writes O as bf16 hi/lo (A operand of FC1) over the X region.
// ---------------------------------------------------------------------------
__device__ __forceinline__ void attention(const char* __restrict__ Qb,
                                          const char* __restrict__ Kb,
                                          const char* __restrict__ Vf,
                                          char* __restrict__ Ohi,
                                          char* __restrict__ Olo, int tid) {
    const float scale = 0.5100697176f;   // (1/sqrt(8)) * log2(e)
    const ull scale2 = pack2s(scale);
    const int node = tid >> 6;
    const int h = (tid >> 3) & 7;
    const int tg = tid & 7;
    const int tbase = tg * 3;
    const int rbase = node * TT;         // multiple of 24 -> (rbase & 7) == 0
    const int ch = 2 * h;                // V chunk base

    ull q2[3][4], o2[3][4];
    float sum[3];
#pragma unroll
    for (int i = 0; i < 3; ++i) {
        int r7 = (tbase + i) & 7;
        uint4 qr = *(const uint4*)(Qb + (rbase + tbase + i) * 128 + ((h ^ r7) << 4));
        q2[i][0] = mul2(bf2f(qr.x), scale2);
        q2[i][1] = mul2(bf2f(qr.y), scale2);
        q2[i][2] = mul2(bf2f(qr.z), scale2);
        q2[i][3] = mul2(bf2f(qr.w), scale2);
        sum[i] = 0.0f;
#pragma unroll
        for (int j = 0; j < 4; ++j) o2[i][j] = 0ull;
    }

#pragma unroll
    for (int a8 = 0; a8 < 3; ++a8) {
#pragma unroll
        for (int e = 0; e < 8; ++e) {      // s & 7 == e (compile-time)
            int s = 8 * a8 + e;
            uint4 kr = *(const uint4*)(Kb + (rbase + s) * 128 + ((h ^ e) << 4));
            ull k2[4];
            k2[0] = bf2f(kr.x); k2[1] = bf2f(kr.y);
            k2[2] = bf2f(kr.z); k2[3] = bf2f(kr.w);
            const char* vr = Vf + (rbase + s) * 256;
            ulonglong2 va = *(const ulonglong2*)(vr + ((ch ^ e) << 4));
            ulonglong2 vb = *(const ulonglong2*)(vr + (((ch + 1) ^ e) << 4));
#pragma unroll
            for (int i = 0; i < 3; ++i) {
                ull d2 = mul2(q2[i][0], k2[0]);
                d2 = ffma2(q2[i][1], k2[1], d2);
                d2 = ffma2(q2[i][2], k2[2], d2);
                d2 = ffma2(q2[i][3], k2[3], d2);
                float2 dd = unpack2(d2);
                float dot = dd.x + dd.y;
                float e2 = (s >= tbase + i) ? ex2f(dot) : 0.0f;
                sum[i] += e2;
                ull ep = pack2s(e2);
                o2[i][0] = ffma2(ep, va.x, o2[i][0]);
                o2[i][1] = ffma2(ep, va.y, o2[i][1]);
                o2[i][2] = ffma2(ep, vb.x, o2[i][2]);
                o2[i][3] = ffma2(ep, vb.y, o2[i][3]);
            }
        }
    }

#pragma unroll
    for (int i = 0; i < 3; ++i) {
        float inv = 1.0f / sum[i];
        int row = rbase + tbase + i;
        int r7 = (tbase + i) & 7;
        uint32_t hi[4], lo[4];
#pragma unroll
        for (int j = 0; j < 4; ++j) {
            float2 p = unpack2(o2[i][j]);
            split_pair(p.x * inv, p.y * inv, hi[j], lo[j]);
        }
        int off = row * 128 + ((h ^ r7) << 4);
        *(uint4*)(Ohi + off) = make_uint4(hi[0], hi[1], hi[2], hi[3]);
        *(uint4*)(Olo + off) = make_uint4(lo[0], lo[1], lo[2], lo[3]);
    }
}

// ---------------------------------------------------------------------------
// Fused kernel: one CTA per (batch, 4-node tile); 2 CTAs/SM; 4 barriers.
//   stage X                      | cp Wq-hi->SA, Wk-hi->SB, Wv->SC
//   QKV GEMM -> Q,K bf16; V f32 |
//   attention -> O @ X           | cp Wf1->SC
//   FC1 -> H hi@Q, lo@K          | cp Wf2->SA(+SB)
//   FC2 -> Y
// ---------------------------------------------------------------------------
__global__ void __launch_bounds__(NTHREADS, 2)
temporal_attention_mma(const float* __restrict__ X,
                       const float* __restrict__ bq, const float* __restrict__ bk,
                       const float* __restrict__ bv, const float* __restrict__ bf1,
                       const float* __restrict__ bf2,
                       float* __restrict__ Y) {
    extern __shared__ char smem[];
    char* Xhi = smem + X_OFF;              // 12K hi + 12K lo
    char* Xlo = smem + X_OFF + 12288;

    const int tid = threadIdx.x;
    const int n0blk = blockIdx.x * NB;
    const int b = blockIdx.y;

    const uint32_t xhiU = smem_u32(Xhi);
    const uint32_t xloU = smem_u32(Xlo);
    const uint32_t saU = smem_u32(smem + SA_OFF);
    const uint32_t sbU = smem_u32(smem + SB_OFF);
    const uint32_t scU = smem_u32(smem + SC_OFF);
    const uint32_t hhiU = smem_u32(smem + Q_OFF);
    const uint32_t hloU = smem_u32(smem + K_OFF);

    // Wq-hi -> SA, Wk-hi -> SB, Wv (hi+lo) -> SC; overlaps X staging.
    fetch_W8(saU, 0, tid);
    fetch_W8(sbU, 1, tid);
    fetch_W(scU, 2, tid);

    // Stage X as bf16 hi/lo (zero-fill out-of-range nodes).
#pragma unroll
    for (int p = 0; p < 3; ++p) {
        int idx = tid + p * NTHREADS;      // 768 tasks: row(96) x group(8)
        int row = idx >> 3, g = idx & 7;
        int node = row / TT, t = row - node * TT;
        int n = n0blk + node;
        float4 f0 = make_float4(0.f, 0.f, 0.f, 0.f);
        float4 f1 = make_float4(0.f, 0.f, 0.f, 0.f);
        if (n < NN) {
            const float* src = X + ((size_t)(b * TT + t) * NN + n) * DD + g * 8;
            f0 = *(const float4*)(src);
            f1 = *(const float4*)(src + 4);
        }
        uint32_t h0, l0, h1, l1, h2, l2, h3, l3;
        split_pair(f0.x, f0.y, h0, l0);
        split_pair(f0.z, f0.w, h1, l1);
        split_pair(f1.x, f1.y, h2, l2);
        split_pair(f1.z, f1.w, h3, l3);
        int off = row * 128 + ((g ^ (row & 7)) << 4);
        *(uint4*)(Xhi + off) = make_uint4(h0, h1, h2, h3);
        *(uint4*)(Xlo + off) = make_uint4(l0, l1, l2, l3);
    }
    wait_cp();
    __syncthreads();

    // Fused QKV GEMM.
    gemm_qkv(xhiU, xloU, saU, sbU, scU, scU + 8192,
             bq, bk, bv, smem + Q_OFF, smem + K_OFF, smem + V_OFF, tid);
    __syncthreads();

    // Attention -> O hi/lo over X; Wf1 streams into SC (Wv dead).
    fetch_W(scU, 3, tid);
    attention(smem + Q_OFF, smem + K_OFF, smem + V_OFF, Xhi, Xlo, tid);
    wait_cp();
    __syncthreads();

    // FC1 (O @ Wf1) -> H hi@Q, lo@K; Wf2 streams into SA+SB (16K contiguous).
    fetch_W(saU, 4, tid);
    gemm_mma<1>(xhiU, xloU, scU, scU + 8192, bf1,
                smem + Q_OFF, smem + K_OFF, nullptr, 0, 0, tid);
    wait_cp();
    __syncthreads();

    // FC2 (H @ Wf2) -> Y.
    gemm_mma<2>(hhiU, hloU, saU, saU + 8192, bf2,
                nullptr, nullptr, Y, b, n0blk, tid);
}

// ---------------------------------------------------------------------------
// kernel_launch: inputs per metadata order:
// 0=X 1=STE(unused) 2=Wq 3=bq 4=Wk 5=bk 6=Wv 7=bv 8=Wf1 9=bf1 10=Wf2 11=bf2
// ---------------------------------------------------------------------------
extern "C" void kernel_launch(void* const* d_in, const int* in_sizes, int n_in,
                              void* d_out, int out_size) {
    const float* X   = (const float*)d_in[0];
    const float* Wq  = (const float*)d_in[2];
    const float* bq  = (const float*)d_in[3];
    const float* Wk  = (const float*)d_in[4];
    const float* bk  = (const float*)d_in[5];
    const float* Wv  = (const float*)d_in[6];
    const float* bv  = (const float*)d_in[7];
    const float* Wf1 = (const float*)d_in[8];
    const float* bf1 = (const float*)d_in[9];
    const float* Wf2 = (const float*)d_in[10];
    const float* bf2 = (const float*)d_in[11];
    float* Y = (float*)d_out;

    prep_weights<<<5, 512>>>(Wq, Wk, Wv, Wf1, Wf2);

    cudaFuncSetAttribute(temporal_attention_mma,
                         cudaFuncAttributeMaxDynamicSharedMemorySize, SMEM_BYTES);
    dim3 grid(NTILES, BB);
    temporal_attention_mma<<<grid, NTHREADS, SMEM_BYTES>>>(
        X, bq, bk, bv, bf1, bf2, Y);
}

// round 17
// speedup vs baseline: 2.2517x; 1.0286x over previous
#include <cuda_runtime.h>
#include <cuda_bf16.h>
#include <cstdint>

// Problem constants
#define BB 32
#define TT 24
#define NN 325
#define DD 64

#define NB 4                  // nodes per CTA
#define MROWS 96              // NB * TT
#define NTILES 82
#define NTHREADS 256          // 8 warps: 2 m-groups (48 rows) x 4 n-groups (16)

// smem regions (total 106496 -> 2 CTAs/SM)
#define X_OFF 0
#define Q_OFF 24576
#define K_OFF 36864
#define V_OFF 49152
#define SA_OFF 73728
#define SB_OFF 81920
#define SC_OFF 90112
#define SMEM_BYTES 106496

// Pre-split weights: [w][0..8192) hi plane, [8192..16384) lo plane,
// in the swizzled smem layout (row k: 128B; chunk g at g^(k&7)).
__device__ __align__(16) unsigned char g_wsplit[5][16384];

typedef unsigned long long ull;

// ---------------------------------------------------------------------------
// PTX helpers
// ---------------------------------------------------------------------------
__device__ __forceinline__ uint32_t smem_u32(const void* p) {
    return (uint32_t)__cvta_generic_to_shared(p);
}
__device__ __forceinline__ void ldsm4(uint32_t addr, uint32_t& r0, uint32_t& r1,
                                      uint32_t& r2, uint32_t& r3) {
    asm volatile("ldmatrix.sync.aligned.m8n8.x4.shared.b16 {%0,%1,%2,%3}, [%4];"
                 : "=r"(r0), "=r"(r1), "=r"(r2), "=r"(r3) : "r"(addr));
}
__device__ __forceinline__ void ldsm4t(uint32_t addr, uint32_t& r0, uint32_t& r1,
                                       uint32_t& r2, uint32_t& r3) {
    asm volatile("ldmatrix.sync.aligned.m8n8.x4.trans.shared.b16 {%0,%1,%2,%3}, [%4];"
                 : "=r"(r0), "=r"(r1), "=r"(r2), "=r"(r3) : "r"(addr));
}
#define MMA(ac, A0, A1, A2, A3, B0, B1)                                        \
    asm volatile(                                                              \
        "mma.sync.aligned.m16n8k16.row.col.f32.bf16.bf16.f32 "                 \
        "{%0,%1,%2,%3}, {%4,%5,%6,%7}, {%8,%9}, {%0,%1,%2,%3};"                \
        : "+f"((ac)[0]), "+f"((ac)[1]), "+f"((ac)[2]), "+f"((ac)[3])           \
        : "r"(A0), "r"(A1), "r"(A2), "r"(A3), "r"(B0), "r"(B1))

__device__ __forceinline__ float ex2f(float x) {
    float y;
    asm("ex2.approx.f32 %0, %1;" : "=f"(y) : "f"(x));
    return y;
}
__device__ __forceinline__ ull ffma2(ull a, ull b, ull c) {
    ull d;
    asm("fma.rn.f32x2 %0, %1, %2, %3;" : "=l"(d) : "l"(a), "l"(b), "l"(c));
    return d;
}
__device__ __forceinline__ ull mul2(ull a, ull b) {
    ull d;
    asm("mul.rn.f32x2 %0, %1, %2;" : "=l"(d) : "l"(a), "l"(b));
    return d;
}
__device__ __forceinline__ float2 unpack2(ull v) {
    float2 r;
    asm("mov.b64 {%0, %1}, %2;" : "=f"(r.x), "=f"(r.y) : "l"(v));
    return r;
}
__device__ __forceinline__ ull pack2s(float x) {
    ull r;
    asm("mov.b64 %0, {%1, %1};" : "=l"(r) : "f"(x));
    return r;
}
// bf16x2 word -> f32x2 ull ({even elem, odd elem}).
__device__ __forceinline__ ull bf2f(uint32_t p) {
    uint32_t lo = p << 16;
    uint32_t hi = p & 0xFFFF0000u;
    ull r;
    asm("mov.b64 %0, {%1, %2};" : "=l"(r) : "r"(lo), "r"(hi));
    return r;
}

// Split fp32 pair into bf16 hi pair + bf16 residual pair (packed b32 each).
__device__ __forceinline__ void split_pair(float a, float b,
                                           uint32_t& hi, uint32_t& lo) {
    __nv_bfloat16 ah = __float2bfloat16_rn(a);
    __nv_bfloat16 bh = __float2bfloat16_rn(b);
    __nv_bfloat16 al = __float2bfloat16_rn(a - __bfloat162float(ah));
    __nv_bfloat16 bl = __float2bfloat16_rn(b - __bfloat162float(bh));
    __nv_bfloat162 H = __halves2bfloat162(ah, bh);
    __nv_bfloat162 L = __halves2bfloat162(al, bl);
    hi = *reinterpret_cast<uint32_t*>(&H);
    lo = *reinterpret_cast<uint32_t*>(&L);
}
__device__ __forceinline__ uint32_t bf16x2_of(float a, float b) {
    __nv_bfloat162 H = __halves2bfloat162(__float2bfloat16_rn(a),
                                          __float2bfloat16_rn(b));
    return *reinterpret_cast<uint32_t*>(&H);
}

// ---------------------------------------------------------------------------
// Prep kernel: split each 64x64 fp32 weight into bf16 hi/lo planes in the
// final swizzled layout, once for all main-kernel CTAs.
// ---------------------------------------------------------------------------
__global__ void prep_weights(const float* __restrict__ Wq,
                             const float* __restrict__ Wk,
                             const float* __restrict__ Wv,
                             const float* __restrict__ Wf1,
                             const float* __restrict__ Wf2) {
    const float* Ws[5] = {Wq, Wk, Wv, Wf1, Wf2};
    const float* W = Ws[blockIdx.x];
    unsigned char* hi = g_wsplit[blockIdx.x];
    unsigned char* lo = g_wsplit[blockIdx.x] + 8192;
    int tid = threadIdx.x;                 // 512 threads: k(64) x g(8)
    int k = tid >> 3, g = tid & 7;
    const float* src = W + k * 64 + g * 8;
    float4 f0 = *(const float4*)(src);
    float4 f1 = *(const float4*)(src + 4);
    uint32_t h0, l0, h1, l1, h2, l2, h3, l3;
    split_pair(f0.x, f0.y, h0, l0);
    split_pair(f0.z, f0.w, h1, l1);
    split_pair(f1.x, f1.y, h2, l2);
    split_pair(f1.z, f1.w, h3, l3);
    int off = k * 128 + ((g ^ (k & 7)) << 4);
    *(uint4*)(hi + off) = make_uint4(h0, h1, h2, h3);
    *(uint4*)(lo + off) = make_uint4(l0, l1, l2, l3);
}

// ---------------------------------------------------------------------------
// cp.async fetches: full 16KB (hi+lo) or hi-plane-only 8KB.
// ---------------------------------------------------------------------------
__device__ __forceinline__ void fetch_W(uint32_t dstU, int widx, int tid) {
#pragma unroll
    for (int i = 0; i < 4; ++i) {
        int idx = tid + i * NTHREADS;      // 1024 x 16B
        asm volatile("cp.async.ca.shared.global [%0], [%1], 16;"
                     :: "r"(dstU + idx * 16),
                        "l"(g_wsplit[widx] + idx * 16));
    }
    asm volatile("cp.async.commit_group;" ::: "memory");
}
__device__ __forceinline__ void fetch_W8(uint32_t dstU, int widx, int tid) {
#pragma unroll
    for (int i = 0; i < 2; ++i) {
        int idx = tid + i * NTHREADS;      // 512 x 16B (hi plane only)
        asm volatile("cp.async.ca.shared.global [%0], [%1], 16;"
                     :: "r"(dstU + idx * 16),
                        "l"(g_wsplit[widx] + idx * 16));
    }
    asm volatile("cp.async.commit_group;" ::: "memory");
}
__device__ __forceinline__ void wait_cp() {
    asm volatile("cp.async.wait_group 0;" ::: "memory");
}

// ---------------------------------------------------------------------------
// Fused Q+K+V tensor-core GEMM. A fragments loaded ONCE per k-step.
// Q,K: 1-term Ah@Wh (value err ~3e-3, attenuated ~100x by softmax),
//      out bf16-hi + ReLU.
// V:   3-term, out fp32 (256B rows) + ReLU.
// 8 warps: warp w -> m-group (w&1)*48, n-group (w>>1)*16.
// ---------------------------------------------------------------------------
__device__ __forceinline__ void gemm_qkv(
    uint32_t aHi, uint32_t aLo,
    uint32_t wq, uint32_t wk, uint32_t wvHi, uint32_t wvLo,
    const float* __restrict__ bq, const float* __restrict__ bk,
    const float* __restrict__ bv,
    char* __restrict__ outQ, char* __restrict__ outK,
    char* __restrict__ outV, int tid) {
    const int wid = tid >> 5, lane = tid & 31;
    const int m0 = (wid & 1) * 48;
    const int n0 = (wid >> 1) * 16;
    const int i7 = lane & 7;
    const int h8 = (lane >> 3) & 1;
    const int kh = (lane >> 4) & 1;

    const int rowA = m0 + i7 + h8 * 8;
    const uint32_t aHiB = aHi + rowA * 128;
    const uint32_t aLoB = aLo + rowA * 128;
    const int rowB = i7 + h8 * 8;
    const uint32_t cB = (uint32_t)(((n0 >> 3) + kh) ^ i7) << 4;
    const uint32_t wqB = wq + rowB * 128 + cB;
    const uint32_t wkB = wk + rowB * 128 + cB;
    const uint32_t wvHiB = wvHi + rowB * 128 + cB;
    const uint32_t wvLoB = wvLo + rowB * 128 + cB;

    float accq[3][2][4], acck[3][2][4], accv[3][2][4];
#pragma unroll
    for (int mi = 0; mi < 3; ++mi)
#pragma unroll
        for (int nj = 0; nj < 2; ++nj)
#pragma unroll
            for (int x = 0; x < 4; ++x) {
                accq[mi][nj][x] = 0.0f;
                acck[mi][nj][x] = 0.0f;
                accv[mi][nj][x] = 0.0f;
            }

#pragma unroll
    for (int ks = 0; ks < 4; ++ks) {
        const uint32_t cA = (uint32_t)(((2 * ks) + kh) ^ i7) << 4;
        const uint32_t wkofs = (uint32_t)(ks * 2048);
        uint32_t ah[3][4], al[3][4], b0[4], b1[4];
#pragma unroll
        for (int mi = 0; mi < 3; ++mi) {
            ldsm4(aHiB + mi * 2048 + cA, ah[mi][0], ah[mi][1], ah[mi][2], ah[mi][3]);
            ldsm4(aLoB + mi * 2048 + cA, al[mi][0], al[mi][1], al[mi][2], al[mi][3]);
        }
        // ---- Q: Ah @ Wq-hi (1-term) ----
        ldsm4t(wqB + wkofs, b0[0], b0[1], b0[2], b0[3]);
#pragma unroll
        for (int mi = 0; mi < 3; ++mi) {
            MMA(accq[mi][0], ah[mi][0], ah[mi][1], ah[mi][2], ah[mi][3], b0[0], b0[1]);
            MMA(accq[mi][1], ah[mi][0], ah[mi][1], ah[mi][2], ah[mi][3], b0[2], b0[3]);
        }
        // ---- K: Ah @ Wk-hi (1-term) ----
        ldsm4t(wkB + wkofs, b0[0], b0[1], b0[2], b0[3]);
#pragma unroll
        for (int mi = 0; mi < 3; ++mi) {
            MMA(acck[mi][0], ah[mi][0], ah[mi][1], ah[mi][2], ah[mi][3], b0[0], b0[1]);
            MMA(acck[mi][1], ah[mi][0], ah[mi][1], ah[mi][2], ah[mi][3], b0[2], b0[3]);
        }
        // ---- V: 3-term ----
        ldsm4t(wvHiB + wkofs, b0[0], b0[1], b0[2], b0[3]);
        ldsm4t(wvLoB + wkofs, b1[0], b1[1], b1[2], b1[3]);
#pragma unroll
        for (int mi = 0; mi < 3; ++mi) {
            MMA(accv[mi][0], ah[mi][0], ah[mi][1], ah[mi][2], ah[mi][3], b0[0], b0[1]);
            MMA(accv[mi][1], ah[mi][0], ah[mi][1], ah[mi][2], ah[mi][3], b0[2], b0[3]);
        }
#pragma unroll
        for (int mi = 0; mi < 3; ++mi) {
            MMA(accv[mi][0], ah[mi][0], ah[mi][1], ah[mi][2], ah[mi][3], b1[0], b1[1]);
            MMA(accv[mi][1], ah[mi][0], ah[mi][1], ah[mi][2], ah[mi][3], b1[2], b1[3]);
        }
#pragma unroll
        for (int mi = 0; mi < 3; ++mi) {
            MMA(accv[mi][0], al[mi][0], al[mi][1], al[mi][2], al[mi][3], b0[0], b0[1]);
            MMA(accv[mi][1], al[mi][0], al[mi][1], al[mi][2], al[mi][3], b0[2], b0[3]);
        }
    }

    const int g = lane >> 2;
    const int c2 = (lane & 3) * 2;
#pragma unroll
    for (int mi = 0; mi < 3; ++mi) {
#pragma unroll
        for (int nj = 0; nj < 2; ++nj) {
            const int cc = n0 + 8 * nj + c2;
            const int r1 = m0 + mi * 16 + g, r2 = r1 + 8;
            const int coff8 = (((cc >> 3) ^ g) << 4) + (cc & 7) * 2;
            // Q -> bf16-hi
            {
                float2 bv2 = *(const float2*)(bq + cc);
                float v00 = fmaxf(accq[mi][nj][0] + bv2.x, 0.f);
                float v01 = fmaxf(accq[mi][nj][1] + bv2.y, 0.f);
                float v10 = fmaxf(accq[mi][nj][2] + bv2.x, 0.f);
                float v11 = fmaxf(accq[mi][nj][3] + bv2.y, 0.f);
                *(uint32_t*)(outQ + r1 * 128 + coff8) = bf16x2_of(v00, v01);
                *(uint32_t*)(outQ + r2 * 128 + coff8) = bf16x2_of(v10, v11);
            }
            // K -> bf16-hi
            {
                float2 bv2 = *(const float2*)(bk + cc);
                float v00 = fmaxf(acck[mi][nj][0] + bv2.x, 0.f);
                float v01 = fmaxf(acck[mi][nj][1] + bv2.y, 0.f);
                float v10 = fmaxf(acck[mi][nj][2] + bv2.x, 0.f);
                float v11 = fmaxf(acck[mi][nj][3] + bv2.y, 0.f);
                *(uint32_t*)(outK + r1 * 128 + coff8) = bf16x2_of(v00, v01);
                *(uint32_t*)(outK + r2 * 128 + coff8) = bf16x2_of(v10, v11);
            }
            // V -> fp32 (256B rows)
            {
                const int coff4 = (((cc >> 2) ^ g) << 4) + (cc & 3) * 4;
                float2 bv2 = *(const float2*)(bv + cc);
                float v00 = fmaxf(accv[mi][nj][0] + bv2.x, 0.f);
                float v01 = fmaxf(accv[mi][nj][1] + bv2.y, 0.f);
                float v10 = fmaxf(accv[mi][nj][2] + bv2.x, 0.f);
                float v11 = fmaxf(accv[mi][nj][3] + bv2.y, 0.f);
                *(float2*)(outV + r1 * 256 + coff4) = make_float2(v00, v01);
                *(float2*)(outV + r2 * 256 + coff4) = make_float2(v10, v11);
            }
        }
    }
}

// ---------------------------------------------------------------------------
// Single tensor-core GEMM (FC1 / FC2), 3-term bf16 split.
// MODE 1: bf16 hi/lo out (+bias,+relu)  MODE 2: global fp32 out (+bias)
// ---------------------------------------------------------------------------
template <int MODE>
__device__ __forceinline__ void gemm_mma(
    uint32_t aHi, uint32_t aLo, uint32_t wHi, uint32_t wLo,
    const float* __restrict__ bias,
    char* __restrict__ outHi, char* __restrict__ outLo,
    float* __restrict__ Y, int b, int n0blk, int tid) {
    const int wid = tid >> 5, lane = tid & 31;
    const int m0 = (wid & 1) * 48;
    const int n0 = (wid >> 1) * 16;
    const int i7 = lane & 7;
    const int h8 = (lane >> 3) & 1;
    const int kh = (lane >> 4) & 1;

    const int rowA = m0 + i7 + h8 * 8;
    const uint32_t aHiB = aHi + rowA * 128;
    const uint32_t aLoB = aLo + rowA * 128;
    const int rowB = i7 + h8 * 8;
    const uint32_t cB = (uint32_t)(((n0 >> 3) + kh) ^ i7) << 4;
    const uint32_t wHiB = wHi + rowB * 128 + cB;
    const uint32_t wLoB = wLo + rowB * 128 + cB;

    float acc[3][2][4];
#pragma unroll
    for (int mi = 0; mi < 3; ++mi)
#pragma unroll
        for (int nj = 0; nj < 2; ++nj)
#pragma unroll
            for (int x = 0; x < 4; ++x) acc[mi][nj][x] = 0.0f;

#pragma unroll
    for (int ks = 0; ks < 4; ++ks) {
        const uint32_t cA = (uint32_t)(((2 * ks) + kh) ^ i7) << 4;
        const uint32_t wk = (uint32_t)(ks * 2048);
        uint32_t ah[3][4], al[3][4], bh[4], bl[4];
        ldsm4t(wHiB + wk, bh[0], bh[1], bh[2], bh[3]);
        ldsm4t(wLoB + wk, bl[0], bl[1], bl[2], bl[3]);
#pragma unroll
        for (int mi = 0; mi < 3; ++mi) {
            ldsm4(aHiB + mi * 2048 + cA, ah[mi][0], ah[mi][1], ah[mi][2], ah[mi][3]);
            ldsm4(aLoB + mi * 2048 + cA, al[mi][0], al[mi][1], al[mi][2], al[mi][3]);
        }
#pragma unroll
        for (int mi = 0; mi < 3; ++mi) {
            MMA(acc[mi][0], ah[mi][0], ah[mi][1], ah[mi][2], ah[mi][3], bh[0], bh[1]);
            MMA(acc[mi][1], ah[mi][0], ah[mi][1], ah[mi][2], ah[mi][3], bh[2], bh[3]);
        }
#pragma unroll
        for (int mi = 0; mi < 3; ++mi) {
            MMA(acc[mi][0], ah[mi][0], ah[mi][1], ah[mi][2], ah[mi][3], bl[0], bl[1]);
            MMA(acc[mi][1], ah[mi][0], ah[mi][1], ah[mi][2], ah[mi][3], bl[2], bl[3]);
        }
#pragma unroll
        for (int mi = 0; mi < 3; ++mi) {
            MMA(acc[mi][0], al[mi][0], al[mi][1], al[mi][2], al[mi][3], bh[0], bh[1]);
            MMA(acc[mi][1], al[mi][0], al[mi][1], al[mi][2], al[mi][3], bh[2], bh[3]);
        }
    }

    const int g = lane >> 2;
    const int c2 = (lane & 3) * 2;
#pragma unroll
    for (int mi = 0; mi < 3; ++mi) {
#pragma unroll
        for (int nj = 0; nj < 2; ++nj) {
            const int cc = n0 + 8 * nj + c2;
            float2 bv = *(const float2*)(bias + cc);
            float v00 = acc[mi][nj][0] + bv.x, v01 = acc[mi][nj][1] + bv.y;
            float v10 = acc[mi][nj][2] + bv.x, v11 = acc[mi][nj][3] + bv.y;
            const int r1 = m0 + mi * 16 + g, r2 = r1 + 8;
            if (MODE == 1) {
                v00 = fmaxf(v00, 0.f); v01 = fmaxf(v01, 0.f);
                v10 = fmaxf(v10, 0.f); v11 = fmaxf(v11, 0.f);
                uint32_t hi1, lo1, hi2, lo2;
                split_pair(v00, v01, hi1, lo1);
                split_pair(v10, v11, hi2, lo2);
                const int coff = (((cc >> 3) ^ g) << 4) + (cc & 7) * 2;
                *(uint32_t*)(outHi + r1 * 128 + coff) = hi1;
                *(uint32_t*)(outLo + r1 * 128 + coff) = lo1;
                *(uint32_t*)(outHi + r2 * 128 + coff) = hi2;
                *(uint32_t*)(outLo + r2 * 128 + coff) = lo2;
            } else {
                int node1 = r1 / TT, t1 = r1 - node1 * TT, n1 = n0blk + node1;
                if (n1 < NN)
                    *(float2*)(Y + ((size_t)(b * TT + t1) * NN + n1) * DD + cc) =
                        make_float2(v00, v01);
                int node2 = r2 / TT, t2 = r2 - node2 * TT, n2 = n0blk + node2;
                if (n2 < NN)
                    *(float2*)(Y + ((size_t)(b * TT + t2) * NN + n2) * DD + cc) =
                        make_float2(v10, v11);
            }
        }
    }
}

// ---------------------------------------------------------------------------
// Attention: one thread per (node, head, t-triple): 4*8*8 = 256 tasks.
// Q/K: bf16-hi (128B rows, chunk h at h^(row&7)).  V: fp32 (256B rows).
// Packed f32x2 math; ex2.approx; no max-subtraction.
// Writes O as bf16 hi/lo (A operand of FC1) over the X region.
// ---------------------------------------------------------------------------
__device__ __forceinline__ void attention(const char* __restrict__ Qb,
                                          const char* __restrict__ Kb,
                                          const char* __restrict__ Vf,
                                          char* __restrict__ Ohi,
                                          char* __restrict__ Olo, int tid) {
    const float scale = 0.5100697176f;   // (1/sqrt(8)) * log2(e)
    const ull scale2 = pack2s(scale);
    const int node = tid >> 6;
    const int h = (tid >> 3) & 7;
    const int tg = tid & 7;
    const int tbase = tg * 3;
    const int rbase = node * TT;         // multiple of 24 -> (rbase & 7) == 0
    const int ch = 2 * h;                // V chunk base

    ull q2[3][4], o2[3][4];
    float sum[3];
#pragma unroll
    for (int i = 0; i < 3; ++i) {
        int r7 = (tbase + i) & 7;
        uint4 qr = *(const uint4*)(Qb + (rbase + tbase + i) * 128 + ((h ^ r7) << 4));
        q2[i][0] = mul2(bf2f(qr.x), scale2);
        q2[i][1] = mul2(bf2f(qr.y), scale2);
        q2[i][2] = mul2(bf2f(qr.z), scale2);
        q2[i][3] = mul2(bf2f(qr.w), scale2);
        sum[i] = 0.0f;
#pragma unroll
        for (int j = 0; j < 4; ++j) o2[i][j] = 0ull;
    }

#pragma unroll
    for (int a8 = 0; a8 < 3; ++a8) {
#pragma unroll
        for (int e = 0; e < 8; ++e) {      // s & 7 == e (compile-time)
            int s = 8 * a8 + e;
            uint4 kr = *(const uint4*)(Kb + (rbase + s) * 128 + ((h ^ e) << 4));
            ull k2[4];
            k2[0] = bf2f(kr.x); k2[1] = bf2f(kr.y);
            k2[2] = bf2f(kr.z); k2[3] = bf2f(kr.w);
            const char* vr = Vf + (rbase + s) * 256;
            ulonglong2 va = *(const ulonglong2*)(vr + ((ch ^ e) << 4));
            ulonglong2 vb = *(const ulonglong2*)(vr + (((ch + 1) ^ e) << 4));
#pragma unroll
            for (int i = 0; i < 3; ++i) {
                ull d2 = mul2(q2[i][0], k2[0]);
                d2 = ffma2(q2[i][1], k2[1], d2);
                d2 = ffma2(q2[i][2], k2[2], d2);
                d2 = ffma2(q2[i][3], k2[3], d2);
                float2 dd = unpack2(d2);
                float dot = dd.x + dd.y;
                float e2 = (s >= tbase + i) ? ex2f(dot) : 0.0f;
                sum[i] += e2;
                ull ep = pack2s(e2);
                o2[i][0] = ffma2(ep, va.x, o2[i][0]);
                o2[i][1] = ffma2(ep, va.y, o2[i][1]);
                o2[i][2] = ffma2(ep, vb.x, o2[i][2]);
                o2[i][3] = ffma2(ep, vb.y, o2[i][3]);
            }
        }
    }

#pragma unroll
    for (int i = 0; i < 3; ++i) {
        float inv = 1.0f / sum[i];
        int row = rbase + tbase + i;
        int r7 = (tbase + i) & 7;
        uint32_t hi[4], lo[4];
#pragma unroll
        for (int j = 0; j < 4; ++j) {
            float2 p = unpack2(o2[i][j]);
            split_pair(p.x * inv, p.y * inv, hi[j], lo[j]);
        }
        int off = row * 128 + ((h ^ r7) << 4);
        *(uint4*)(Ohi + off) = make_uint4(hi[0], hi[1], hi[2], hi[3]);
        *(uint4*)(Olo + off) = make_uint4(lo[0], lo[1], lo[2], lo[3]);
    }
}

// ---------------------------------------------------------------------------
// Fused kernel: one CTA per (batch, 4-node tile); 2 CTAs/SM; 4 barriers.
//   stage X                      | cp Wq-hi->SA, Wk-hi->SB, Wv->SC
//   QKV GEMM -> Q,K bf16; V f32 |
//   attention -> O @ X           | cp Wf1->SC
//   FC1 -> H hi@Q, lo@K          | cp Wf2->SA(+SB)
//   FC2 -> Y
// ---------------------------------------------------------------------------
__global__ void __launch_bounds__(NTHREADS, 2)
temporal_attention_mma(const float* __restrict__ X,
                       const float* __restrict__ bq, const float* __restrict__ bk,
                       const float* __restrict__ bv, const float* __restrict__ bf1,
                       const float* __restrict__ bf2,
                       float* __restrict__ Y) {
    extern __shared__ char smem[];
    char* Xhi = smem + X_OFF;              // 12K hi + 12K lo
    char* Xlo = smem + X_OFF + 12288;

    const int tid = threadIdx.x;
    const int n0blk = blockIdx.x * NB;
    const int b = blockIdx.y;

    const uint32_t xhiU = smem_u32(Xhi);
    const uint32_t xloU = smem_u32(Xlo);
    const uint32_t saU = smem_u32(smem + SA_OFF);
    const uint32_t sbU = smem_u32(smem + SB_OFF);
    const uint32_t scU = smem_u32(smem + SC_OFF);
    const uint32_t hhiU = smem_u32(smem + Q_OFF);
    const uint32_t hloU = smem_u32(smem + K_OFF);

    // Wq-hi -> SA, Wk-hi -> SB, Wv (hi+lo) -> SC; overlaps X staging.
    fetch_W8(saU, 0, tid);
    fetch_W8(sbU, 1, tid);
    fetch_W(scU, 2, tid);

    // Stage X as bf16 hi/lo (zero-fill out-of-range nodes).
#pragma unroll
    for (int p = 0; p < 3; ++p) {
        int idx = tid + p * NTHREADS;      // 768 tasks: row(96) x group(8)
        int row = idx >> 3, g = idx & 7;
        int node = row / TT, t = row - node * TT;
        int n = n0blk + node;
        float4 f0 = make_float4(0.f, 0.f, 0.f, 0.f);
        float4 f1 = make_float4(0.f, 0.f, 0.f, 0.f);
        if (n < NN) {
            const float* src = X + ((size_t)(b * TT + t) * NN + n) * DD + g * 8;
            f0 = *(const float4*)(src);
            f1 = *(const float4*)(src + 4);
        }
        uint32_t h0, l0, h1, l1, h2, l2, h3, l3;
        split_pair(f0.x, f0.y, h0, l0);
        split_pair(f0.z, f0.w, h1, l1);
        split_pair(f1.x, f1.y, h2, l2);
        split_pair(f1.z, f1.w, h3, l3);
        int off = row * 128 + ((g ^ (row & 7)) << 4);
        *(uint4*)(Xhi + off) = make_uint4(h0, h1, h2, h3);
        *(uint4*)(Xlo + off) = make_uint4(l0, l1, l2, l3);
    }
    wait_cp();
    __syncthreads();

    // Fused QKV GEMM.
    gemm_qkv(xhiU, xloU, saU, sbU, scU, scU + 8192,
             bq, bk, bv, smem + Q_OFF, smem + K_OFF, smem + V_OFF, tid);
    __syncthreads();

    // Attention -> O hi/lo over X; Wf1 streams into SC (Wv dead).
    fetch_W(scU, 3, tid);
    attention(smem + Q_OFF, smem + K_OFF, smem + V_OFF, Xhi, Xlo, tid);
    wait_cp();
    __syncthreads();

    // FC1 (O @ Wf1) -> H hi@Q, lo@K; Wf2 streams into SA+SB (16K contiguous).
    fetch_W(saU, 4, tid);
    gemm_mma<1>(xhiU, xloU, scU, scU + 8192, bf1,
                smem + Q_OFF, smem + K_OFF, nullptr, 0, 0, tid);
    wait_cp();
    __syncthreads();

    // FC2 (H @ Wf2) -> Y.
    gemm_mma<2>(hhiU, hloU, saU, saU + 8192, bf2,
                nullptr, nullptr, Y, b, n0blk, tid);
}

// ---------------------------------------------------------------------------
// kernel_launch: inputs per metadata order:
// 0=X 1=STE(unused) 2=Wq 3=bq 4=Wk 5=bk 6=Wv 7=bv 8=Wf1 9=bf1 10=Wf2 11=bf2
// ---------------------------------------------------------------------------
extern "C" void kernel_launch(void* const* d_in, const int* in_sizes, int n_in,
                              void* d_out, int out_size) {
    const float* X   = (const float*)d_in[0];
    const float* Wq  = (const float*)d_in[2];
    const float* bq  = (const float*)d_in[3];
    const float* Wk  = (const float*)d_in[4];
    const float* bk  = (const float*)d_in[5];
    const float* Wv  = (const float*)d_in[6];
    const float* bv  = (const float*)d_in[7];
    const float* Wf1 = (const float*)d_in[8];
    const float* bf1 = (const float*)d_in[9];
    const float* Wf2 = (const float*)d_in[10];
    const float* bf2 = (const float*)d_in[11];
    float* Y = (float*)d_out;

    prep_weights<<<5, 512>>>(Wq, Wk, Wv, Wf1, Wf2);

    cudaFuncSetAttribute(temporal_attention_mma,
                         cudaFuncAttributeMaxDynamicSharedMemorySize, SMEM_BYTES);
    dim3 grid(NTILES, BB);
    temporal_attention_mma<<<grid, NTHREADS, SMEM_BYTES>>>(
        X, bq, bk, bv, bf1, bf2, Y);
}